// round 7
// baseline (speedup 1.0000x reference)
#include <cuda_runtime.h>
#include <cuda_fp16.h>
#include <cstdint>

// Problem constants
#define BATCH 4
#define TSEQ  2048
#define CDIM  1024
#define NHEAD 16
#define HDIM  64
#define C3    (3*CDIM)
#define MTOT  (BATCH*TSEQ)   // 8192

// fold attention scale * log2(e) into Q so S is directly in exp2 domain
#define QSCALE 0.18033688011112042f   // 0.125 * 1.4426950408889634

// ---------------------------------------------------------------------------
// Device-global scratch (no allocation allowed)
// ---------------------------------------------------------------------------
__device__ __align__(256) __half g_qkvh[(size_t)3 * BATCH * NHEAD * TSEQ * HDIM];
__device__ __align__(256) __half g_qkvl[(size_t)3 * BATCH * NHEAD * TSEQ * HDIM];
__device__ __align__(256) __half g_yh[(size_t)MTOT * CDIM];
__device__ __align__(256) __half g_yl[(size_t)MTOT * CDIM];
__device__ __align__(256) __half g_xh[(size_t)MTOT * CDIM];
__device__ __align__(256) __half g_xl[(size_t)MTOT * CDIM];
__device__ __align__(256) __half g_wq[(size_t)C3 * CDIM];    // transposed N x K
__device__ __align__(256) __half g_wp[(size_t)CDIM * CDIM];  // transposed N x K

// ---------------------------------------------------------------------------
// Helpers (baseline PTX only)
// ---------------------------------------------------------------------------
__device__ __forceinline__ uint32_t smem_u32(const void* p) {
    uint32_t a;
    asm("{ .reg .u64 t; cvta.to.shared.u64 t, %1; cvt.u32.u64 %0, t; }" : "=r"(a) : "l"(p));
    return a;
}
__device__ __forceinline__ void cpa16(uint32_t dst, const void* src) {
    asm volatile("cp.async.cg.shared.global [%0], [%1], 16;\n" :: "r"(dst), "l"(src));
}
#define CP_COMMIT() asm volatile("cp.async.commit_group;\n" ::: "memory")
#define CP_WAIT(n)  asm volatile("cp.async.wait_group %0;\n" :: "n"(n) : "memory")
#define SWZ128(o) ((o) ^ (((o) >> 3) & 0x70))

__device__ __forceinline__ void ldsm4(uint32_t addr, uint32_t* r) {
    asm volatile("ldmatrix.sync.aligned.m8n8.x4.shared.b16 {%0,%1,%2,%3}, [%4];"
                 : "=r"(r[0]), "=r"(r[1]), "=r"(r[2]), "=r"(r[3]) : "r"(addr));
}
__device__ __forceinline__ void ldsm4t(uint32_t addr, uint32_t* r) {
    asm volatile("ldmatrix.sync.aligned.m8n8.x4.trans.shared.b16 {%0,%1,%2,%3}, [%4];"
                 : "=r"(r[0]), "=r"(r[1]), "=r"(r[2]), "=r"(r[3]) : "r"(addr));
}
__device__ __forceinline__ void mma16816(float* d, const uint32_t* a, uint32_t b0, uint32_t b1) {
    asm volatile("mma.sync.aligned.m16n8k16.row.col.f32.f16.f16.f32 "
                 "{%0,%1,%2,%3},{%4,%5,%6,%7},{%8,%9},{%0,%1,%2,%3};"
                 : "+f"(d[0]), "+f"(d[1]), "+f"(d[2]), "+f"(d[3])
                 : "r"(a[0]), "r"(a[1]), "r"(a[2]), "r"(a[3]), "r"(b0), "r"(b1));
}
__device__ __forceinline__ uint32_t packh2(__half a, __half b) {
    __half2 t; t.x = a; t.y = b;
    return *reinterpret_cast<uint32_t*>(&t);
}

// ---------------------------------------------------------------------------
// Split fp32 -> fp16 hi/lo
// ---------------------------------------------------------------------------
__global__ void __launch_bounds__(256) split_kernel(
    const float* __restrict__ in, __half* __restrict__ hi,
    __half* __restrict__ lo, int n4)
{
    int i = blockIdx.x * 256 + threadIdx.x;
    if (i >= n4) return;
    float4 v = ((const float4*)in)[i];
    float vv[4] = {v.x, v.y, v.z, v.w};
    __half h[4], l[4];
    #pragma unroll
    for (int j = 0; j < 4; j++) {
        h[j] = __float2half(vv[j]);
        l[j] = __float2half(vv[j] - __half2float(h[j]));
    }
    ((uint32_t*)hi)[2*i]   = packh2(h[0], h[1]);
    ((uint32_t*)hi)[2*i+1] = packh2(h[2], h[3]);
    ((uint32_t*)lo)[2*i]   = packh2(l[0], l[1]);
    ((uint32_t*)lo)[2*i+1] = packh2(l[2], l[3]);
}

// ---------------------------------------------------------------------------
// Transpose weights: W (KxN fp32, row-major) -> Wt (NxK fp16)
// ---------------------------------------------------------------------------
__global__ void __launch_bounds__(256) tsplit_kernel(
    const float* __restrict__ W, __half* __restrict__ Th, int K, int N)
{
    __shared__ float t[32][33];
    int n0 = blockIdx.x * 32, k0 = blockIdx.y * 32;
    int tx = threadIdx.x, ty = threadIdx.y;
    #pragma unroll
    for (int i = 0; i < 32; i += 8)
        t[ty + i][tx] = W[(size_t)(k0 + ty + i) * N + n0 + tx];
    __syncthreads();
    #pragma unroll
    for (int i = 0; i < 32; i += 8)
        Th[(size_t)(n0 + ty + i) * K + k0 + tx] = __float2half(t[tx][ty + i]);
}

// ---------------------------------------------------------------------------
// mma.sync fp16 2-term GEMM: C(MxN) = (Ah+Al)(MxK) * B(NxK)^T
// Tile 128x128, BK=64 (SW128), 2 stages x 3 tiles x 16KB = 96KB.
// MMA scheduling: full hi-pass (16 indep MMAs) then lo-pass -> RAW dist 16.
// ---------------------------------------------------------------------------
#define TILE_B     (128 * 128)           // 16384 B per tile
#define STAGE_B    (3 * TILE_B)          // 49152 B
#define MM_SMEM    (2 * STAGE_B)         // 98304 B

template<int MODE>
__global__ void __launch_bounds__(256, 2) mmasync_kernel(
    const __half* __restrict__ Ah, const __half* __restrict__ Al,
    const __half* __restrict__ Bh,
    float* __restrict__ C, int N, int K)
{
    extern __shared__ char smraw[];
    const uint32_t smb = smem_u32(smraw);

    const int tid  = threadIdx.x;
    const int wid  = tid >> 5, lane = tid & 31;
    const int wm   = wid & 1;
    const int wn   = wid >> 1;
    const int bm   = blockIdx.y * 128, bn = blockIdx.x * 128;
    const int l16  = lane & 15, lh = lane >> 4;

    float acc[4][4][4];
    #pragma unroll
    for (int i = 0; i < 4; i++)
        #pragma unroll
        for (int j = 0; j < 4; j++)
            #pragma unroll
            for (int k = 0; k < 4; k++) acc[i][j][k] = 0.f;

    const __half* srcs[3] = {Ah, Al, Bh};

    auto fill = [&](int s, int k0) {
        uint32_t sb = smb + (uint32_t)s * STAGE_B;
        #pragma unroll
        for (int t = 0; t < 3; t++) {
            const __half* src = srcs[t];
            const int rbase = (t < 2) ? bm : bn;
            uint32_t tb = sb + (uint32_t)t * TILE_B;
            #pragma unroll
            for (int i = 0; i < 4; i++) {
                int chunk = tid + i * 256;
                int row = chunk >> 3, c = chunk & 7;
                cpa16(tb + SWZ128((uint32_t)(row * 128 + c * 16)),
                      src + (size_t)(rbase + row) * K + k0 + c * 8);
            }
        }
    };

    const int nch = K >> 6;   // BK = 64
    fill(0, 0); CP_COMMIT();

    for (int i = 0; i < nch; i++) {
        if (i + 1 < nch) { fill((i + 1) & 1, (i + 1) << 6); CP_COMMIT(); CP_WAIT(1); }
        else             { CP_WAIT(0); }
        __syncthreads();

        uint32_t sb = smb + (uint32_t)(i & 1) * STAGE_B;
        uint32_t Abh = sb, Abl = sb + TILE_B, Bbh = sb + 2 * TILE_B;

        #pragma unroll
        for (int kh = 0; kh < 4; kh++) {
            const uint32_t koff = (uint32_t)(kh * 32 + lh * 16);
            uint32_t ah[4][4], al[4][4];
            #pragma unroll
            for (int mt = 0; mt < 4; mt++) {
                uint32_t ro = SWZ128((uint32_t)((wm * 64 + mt * 16 + l16) * 128) + koff);
                ldsm4(Abh + ro, ah[mt]);
                ldsm4(Abl + ro, al[mt]);
            }
            uint32_t bh[2][4];
            #pragma unroll
            for (int np = 0; np < 2; np++) {
                uint32_t ro = SWZ128((uint32_t)((wn * 32 + np * 16 + l16) * 128) + koff);
                ldsm4(Bbh + ro, bh[np]);
            }
            // hi pass: 16 independent MMAs
            #pragma unroll
            for (int mt = 0; mt < 4; mt++)
                #pragma unroll
                for (int nt = 0; nt < 4; nt++) {
                    const int np = nt >> 1, o = nt & 1;
                    mma16816(acc[mt][nt], ah[mt], bh[np][o], bh[np][o + 2]);
                }
            // lo pass: 16 independent MMAs (RAW distance 16 vs hi pass)
            #pragma unroll
            for (int mt = 0; mt < 4; mt++)
                #pragma unroll
                for (int nt = 0; nt < 4; nt++) {
                    const int np = nt >> 1, o = nt & 1;
                    mma16816(acc[mt][nt], al[mt], bh[np][o], bh[np][o + 2]);
                }
        }
        __syncthreads();
    }

    const int er = lane >> 2, ec = (lane & 3) * 2;
    #pragma unroll
    for (int mt = 0; mt < 4; mt++)
        #pragma unroll
        for (int nt = 0; nt < 4; nt++) {
            int r0 = bm + wm * 64 + mt * 16 + er;
            int c0 = bn + wn * 32 + nt * 8 + ec;
            if (MODE == 0) {
                *(float2*)&C[(size_t)r0 * N + c0] =
                    make_float2(acc[mt][nt][0], acc[mt][nt][1]);
                *(float2*)&C[(size_t)(r0 + 8) * N + c0] =
                    make_float2(acc[mt][nt][2], acc[mt][nt][3]);
            } else {
                int bb = r0 >> 11, t = r0 & 2047;
                int part = c0 >> 10, rem = c0 & 1023;
                int hh = rem >> 6, d = rem & 63;
                size_t o = ((((size_t)part * BATCH + bb) * NHEAD + hh) * TSEQ + t) * HDIM + d;
                #pragma unroll
                for (int rr = 0; rr < 2; rr++) {
                    float v0 = acc[mt][nt][2 * rr + 0];
                    float v1 = acc[mt][nt][2 * rr + 1];
                    size_t oo = o + (size_t)rr * 8 * HDIM;
                    if (part == 0) {
                        v0 *= QSCALE; v1 *= QSCALE;
                        __half h0 = __float2half(v0), h1 = __float2half(v1);
                        *(uint32_t*)&g_qkvh[oo] = packh2(h0, h1);
                        *(uint32_t*)&g_qkvl[oo] = packh2(
                            __float2half(v0 - __half2float(h0)),
                            __float2half(v1 - __half2float(h1)));
                    } else {
                        *(uint32_t*)&g_qkvh[oo] = packh2(__float2half(v0), __float2half(v1));
                    }
                }
            }
        }
}

// ---------------------------------------------------------------------------
// Tensor-core flash attention (causal), fp16 2-term, Bq=128, Bk=64, D=64.
// MMA scheduling: process K/V groups in pairs; all hi MMAs before lo MMAs.
// ---------------------------------------------------------------------------
#define FL_SMEM (64 * 1024)

__global__ void __launch_bounds__(256, 2) flash_tc_kernel()
{
    extern __shared__ char smraw[];
    const uint32_t S = smem_u32(smraw);
    const int tid = threadIdx.x, w = tid >> 5, lane = tid & 31;
    const int l16 = lane & 15, lh = lane >> 4;
    const int b = blockIdx.z, h = blockIdx.y;
    const int qt = (int)(gridDim.x - 1 - blockIdx.x);   // heaviest first
    const int n_kt = 2 * qt + 2;

    const uint32_t Qh_s = S, Ql_s = S + 16384;
    const uint32_t stg0 = S + 32768;

    const size_t head = (((size_t)b) * NHEAD + h) * TSEQ * HDIM;
    const size_t HSZ  = (size_t)BATCH * NHEAD * TSEQ * HDIM;
    const __half* qh = g_qkvh + head;
    const __half* ql = g_qkvl + head;
    const __half* kh = g_qkvh + HSZ + head;
    const __half* vh = g_qkvh + 2 * HSZ + head;

    {
        #pragma unroll
        for (int i = 0; i < 8; i++) {
            int idx = tid + i * 256;
            int mtx = idx >> 10, row = (idx >> 3) & 127, c = idx & 7;
            const __half* src = (mtx ? ql : qh) + (size_t)(qt * 128 + row) * HDIM + c * 8;
            cpa16((mtx ? Ql_s : Qh_s) + SWZ128((uint32_t)(row * 128 + c * 16)), src);
        }
    }
    auto fillkv = [&](int s, int kt) {
        uint32_t sb = stg0 + (uint32_t)s * 16384u;
        const __half* bases[2] = {kh, vh};
        #pragma unroll
        for (int i = 0; i < 4; i++) {
            int idx = tid + i * 256;
            int mtx = idx >> 9, row = (idx >> 3) & 63, c = idx & 7;
            cpa16(sb + (uint32_t)mtx * 8192u + SWZ128((uint32_t)(row * 128 + c * 16)),
                  bases[mtx] + (size_t)(kt * 64 + row) * HDIM + c * 8);
        }
    };

    fillkv(0, 0); CP_COMMIT();
    if (n_kt > 1) { fillkv(1, 1); CP_COMMIT(); }

    float m0 = -1e30f, m1 = -1e30f, l0 = 0.f, l1 = 0.f;
    float o[8][4];
    #pragma unroll
    for (int j = 0; j < 8; j++)
        #pragma unroll
        for (int e = 0; e < 4; e++) o[j][e] = 0.f;

    for (int kt = 0; kt < n_kt; kt++) {
        if (kt + 1 < n_kt) { CP_WAIT(1); } else { CP_WAIT(0); }
        __syncthreads();

        const uint32_t sb   = stg0 + (uint32_t)(kt & 1) * 16384u;
        const uint32_t Kh_s = sb, Vh_s = sb + 8192;

        // ---- S = Q K^T (2-term), paired groups, hi-before-lo ----
        float s[8][4];
        #pragma unroll
        for (int j = 0; j < 8; j++)
            #pragma unroll
            for (int e = 0; e < 4; e++) s[j][e] = 0.f;

        #pragma unroll
        for (int kk = 0; kk < 4; kk++) {
            const uint32_t koff = (uint32_t)(kk * 32 + lh * 16);
            uint32_t qf[4], qlf[4];
            ldsm4(Qh_s + SWZ128((uint32_t)((w * 16 + l16) * 128) + koff), qf);
            ldsm4(Ql_s + SWZ128((uint32_t)((w * 16 + l16) * 128) + koff), qlf);
            #pragma unroll
            for (int gp = 0; gp < 2; gp++) {
                const int g0 = 2 * gp, g1 = 2 * gp + 1;
                uint32_t kf0[4], kf1[4];
                ldsm4(Kh_s + SWZ128((uint32_t)((g0 * 16 + l16) * 128) + koff), kf0);
                ldsm4(Kh_s + SWZ128((uint32_t)((g1 * 16 + l16) * 128) + koff), kf1);
                // hi pass (4 independent accs)
                mma16816(s[2 * g0],     qf, kf0[0], kf0[2]);
                mma16816(s[2 * g0 + 1], qf, kf0[1], kf0[3]);
                mma16816(s[2 * g1],     qf, kf1[0], kf1[2]);
                mma16816(s[2 * g1 + 1], qf, kf1[1], kf1[3]);
                // lo pass (RAW distance 4)
                mma16816(s[2 * g0],     qlf, kf0[0], kf0[2]);
                mma16816(s[2 * g0 + 1], qlf, kf0[1], kf0[3]);
                mma16816(s[2 * g1],     qlf, kf1[0], kf1[2]);
                mma16816(s[2 * g1 + 1], qlf, kf1[1], kf1[3]);
            }
        }

        // ---- causal mask ----
        const int row0 = qt * 128 + w * 16 + (lane >> 2);
        if (kt * 64 + 63 > qt * 128 + w * 16) {
            #pragma unroll
            for (int j = 0; j < 8; j++) {
                int colb = kt * 64 + j * 8 + (lane & 3) * 2;
                if (colb + 0 > row0)     s[j][0] = -1e30f;
                if (colb + 1 > row0)     s[j][1] = -1e30f;
                if (colb + 0 > row0 + 8) s[j][2] = -1e30f;
                if (colb + 1 > row0 + 8) s[j][3] = -1e30f;
            }
        }

        // ---- online softmax (exp2 domain) ----
        float mx0 = -1e30f, mx1 = -1e30f;
        #pragma unroll
        for (int j = 0; j < 8; j++) {
            mx0 = fmaxf(mx0, fmaxf(s[j][0], s[j][1]));
            mx1 = fmaxf(mx1, fmaxf(s[j][2], s[j][3]));
        }
        mx0 = fmaxf(mx0, __shfl_xor_sync(0xffffffffu, mx0, 1));
        mx0 = fmaxf(mx0, __shfl_xor_sync(0xffffffffu, mx0, 2));
        mx1 = fmaxf(mx1, __shfl_xor_sync(0xffffffffu, mx1, 1));
        mx1 = fmaxf(mx1, __shfl_xor_sync(0xffffffffu, mx1, 2));
        float nm0 = fmaxf(m0, mx0), nm1 = fmaxf(m1, mx1);
        float c0 = exp2f(m0 - nm0), c1 = exp2f(m1 - nm1);
        m0 = nm0; m1 = nm1;
        float sum0 = 0.f, sum1 = 0.f;
        #pragma unroll
        for (int j = 0; j < 8; j++) {
            s[j][0] = exp2f(s[j][0] - m0);
            s[j][1] = exp2f(s[j][1] - m0);
            s[j][2] = exp2f(s[j][2] - m1);
            s[j][3] = exp2f(s[j][3] - m1);
            sum0 += s[j][0] + s[j][1];
            sum1 += s[j][2] + s[j][3];
        }
        sum0 += __shfl_xor_sync(0xffffffffu, sum0, 1);
        sum0 += __shfl_xor_sync(0xffffffffu, sum0, 2);
        sum1 += __shfl_xor_sync(0xffffffffu, sum1, 1);
        sum1 += __shfl_xor_sync(0xffffffffu, sum1, 2);
        l0 = l0 * c0 + sum0;
        l1 = l1 * c1 + sum1;
        #pragma unroll
        for (int j = 0; j < 8; j++) {
            o[j][0] *= c0; o[j][1] *= c0; o[j][2] *= c1; o[j][3] *= c1;
        }

        // ---- O += P V (2-term), paired groups, hi-before-lo ----
        #pragma unroll
        for (int kk = 0; kk < 4; kk++) {
            uint32_t pa[4], pb[4];
            #pragma unroll
            for (int half = 0; half < 2; half++) {
                const int f = 2 * kk + half;
                __half h0 = __float2half(s[f][0]);
                __half h1 = __float2half(s[f][1]);
                __half h2 = __float2half(s[f][2]);
                __half h3 = __float2half(s[f][3]);
                pa[2 * half + 0] = packh2(h0, h1);
                pa[2 * half + 1] = packh2(h2, h3);
                pb[2 * half + 0] = packh2(
                    __float2half(s[f][0] - __half2float(h0)),
                    __float2half(s[f][1] - __half2float(h1)));
                pb[2 * half + 1] = packh2(
                    __float2half(s[f][2] - __half2float(h2)),
                    __float2half(s[f][3] - __half2float(h3)));
            }
            #pragma unroll
            for (int gp = 0; gp < 2; gp++) {
                const int g0 = 2 * gp, g1 = 2 * gp + 1;
                uint32_t vf0[4], vf1[4];
                uint32_t ro0 = SWZ128((uint32_t)((kk * 16 + l16) * 128 + g0 * 32) + (uint32_t)(lh * 16));
                uint32_t ro1 = SWZ128((uint32_t)((kk * 16 + l16) * 128 + g1 * 32) + (uint32_t)(lh * 16));
                ldsm4t(Vh_s + ro0, vf0);
                ldsm4t(Vh_s + ro1, vf1);
                // hi pass
                mma16816(o[2 * g0],     pa, vf0[0], vf0[1]);
                mma16816(o[2 * g0 + 1], pa, vf0[2], vf0[3]);
                mma16816(o[2 * g1],     pa, vf1[0], vf1[1]);
                mma16816(o[2 * g1 + 1], pa, vf1[2], vf1[3]);
                // lo pass (RAW distance 4)
                mma16816(o[2 * g0],     pb, vf0[0], vf0[1]);
                mma16816(o[2 * g0 + 1], pb, vf0[2], vf0[3]);
                mma16816(o[2 * g1],     pb, vf1[0], vf1[1]);
                mma16816(o[2 * g1 + 1], pb, vf1[2], vf1[3]);
            }
        }

        __syncthreads();
        if (kt + 2 < n_kt) { fillkv(kt & 1, kt + 2); CP_COMMIT(); }
    }

    // ---- epilogue ----
    const float inv0 = 1.f / l0, inv1 = 1.f / l1;
    const int r0 = qt * 128 + w * 16 + (lane >> 2);
    const int t0 = r0, t1 = r0 + 8;
    #pragma unroll
    for (int j = 0; j < 8; j++) {
        int d = j * 8 + (lane & 3) * 2;
        size_t o0 = ((size_t)b * TSEQ + t0) * CDIM + h * HDIM + d;
        size_t o1 = ((size_t)b * TSEQ + t1) * CDIM + h * HDIM + d;
        float y0 = o[j][0] * inv0, y1 = o[j][1] * inv0;
        float y2 = o[j][2] * inv1, y3 = o[j][3] * inv1;
        __half h0 = __float2half(y0), h1 = __float2half(y1);
        __half h2 = __float2half(y2), h3 = __float2half(y3);
        *(uint32_t*)&g_yh[o0] = packh2(h0, h1);
        *(uint32_t*)&g_yh[o1] = packh2(h2, h3);
        *(uint32_t*)&g_yl[o0] = packh2(
            __float2half(y0 - __half2float(h0)),
            __float2half(y1 - __half2float(h1)));
        *(uint32_t*)&g_yl[o1] = packh2(
            __float2half(y2 - __half2float(h2)),
            __float2half(y3 - __half2float(h3)));
    }
}

// ---------------------------------------------------------------------------
extern "C" void kernel_launch(void* const* d_in, const int* in_sizes, int n_in,
                              void* d_out, int out_size)
{
    const float* x      = (const float*)d_in[0];
    const float* w_qkv  = (const float*)d_in[1];
    const float* w_proj = (const float*)d_in[2];
    float* out = (float*)d_out;

    __half *xh, *xl, *yh, *yl, *wq, *wp;
    cudaGetSymbolAddress((void**)&xh, g_xh);
    cudaGetSymbolAddress((void**)&xl, g_xl);
    cudaGetSymbolAddress((void**)&yh, g_yh);
    cudaGetSymbolAddress((void**)&yl, g_yl);
    cudaGetSymbolAddress((void**)&wq, g_wq);
    cudaGetSymbolAddress((void**)&wp, g_wp);

    cudaFuncSetAttribute(mmasync_kernel<0>, cudaFuncAttributeMaxDynamicSharedMemorySize, MM_SMEM);
    cudaFuncSetAttribute(mmasync_kernel<1>, cudaFuncAttributeMaxDynamicSharedMemorySize, MM_SMEM);
    cudaFuncSetAttribute(flash_tc_kernel,   cudaFuncAttributeMaxDynamicSharedMemorySize, FL_SMEM);
    cudaFuncSetAttribute(mmasync_kernel<0>, cudaFuncAttributePreferredSharedMemoryCarveout, 100);
    cudaFuncSetAttribute(mmasync_kernel<1>, cudaFuncAttributePreferredSharedMemoryCarveout, 100);
    cudaFuncSetAttribute(flash_tc_kernel,   cudaFuncAttributePreferredSharedMemoryCarveout, 100);

    const int n4 = MTOT * CDIM / 4;

    split_kernel<<<(n4 + 255) / 256, 256>>>(x, xh, xl, n4);

    {
        dim3 g1(C3 / 32, CDIM / 32), blk(32, 8);
        tsplit_kernel<<<g1, blk>>>(w_qkv, wq, CDIM, C3);
        dim3 g2(CDIM / 32, CDIM / 32);
        tsplit_kernel<<<g2, blk>>>(w_proj, wp, CDIM, CDIM);
    }

    {
        dim3 grid(C3 / 128, MTOT / 128);
        mmasync_kernel<1><<<grid, 256, MM_SMEM>>>(xh, xl, wq, nullptr, C3, CDIM);
    }

    {
        dim3 grid(TSEQ / 128, NHEAD, BATCH);
        flash_tc_kernel<<<grid, 256, FL_SMEM>>>();
    }

    {
        dim3 grid(CDIM / 128, MTOT / 128);
        mmasync_kernel<0><<<grid, 256, MM_SMEM>>>(yh, yl, wp, out, CDIM, CDIM);
    }
    (void)in_sizes; (void)n_in; (void)out_size;
}

// round 8
// speedup vs baseline: 1.0188x; 1.0188x over previous
#include <cuda_runtime.h>
#include <cuda_fp16.h>
#include <cstdint>

// Problem constants
#define BATCH 4
#define TSEQ  2048
#define CDIM  1024
#define NHEAD 16
#define HDIM  64
#define C3    (3*CDIM)
#define MTOT  (BATCH*TSEQ)   // 8192

// fold attention scale * log2(e) into Q so S is directly in exp2 domain
#define QSCALE 0.18033688011112042f   // 0.125 * 1.4426950408889634

// ---------------------------------------------------------------------------
// Device-global scratch (no allocation allowed)
// ---------------------------------------------------------------------------
__device__ __align__(256) __half g_qkvh[(size_t)3 * BATCH * NHEAD * TSEQ * HDIM];
__device__ __align__(256) __half g_qkvl[(size_t)3 * BATCH * NHEAD * TSEQ * HDIM];
__device__ __align__(256) __half g_yh[(size_t)MTOT * CDIM];
__device__ __align__(256) __half g_yl[(size_t)MTOT * CDIM];
__device__ __align__(256) __half g_xh[(size_t)MTOT * CDIM];
__device__ __align__(256) __half g_xl[(size_t)MTOT * CDIM];
__device__ __align__(256) __half g_wq[(size_t)C3 * CDIM];    // transposed N x K
__device__ __align__(256) __half g_wp[(size_t)CDIM * CDIM];  // transposed N x K

// ---------------------------------------------------------------------------
// Helpers (baseline PTX only)
// ---------------------------------------------------------------------------
__device__ __forceinline__ uint32_t smem_u32(const void* p) {
    uint32_t a;
    asm("{ .reg .u64 t; cvta.to.shared.u64 t, %1; cvt.u32.u64 %0, t; }" : "=r"(a) : "l"(p));
    return a;
}
__device__ __forceinline__ void cpa16(uint32_t dst, const void* src) {
    asm volatile("cp.async.cg.shared.global [%0], [%1], 16;\n" :: "r"(dst), "l"(src));
}
#define CP_COMMIT() asm volatile("cp.async.commit_group;\n" ::: "memory")
#define CP_WAIT(n)  asm volatile("cp.async.wait_group %0;\n" :: "n"(n) : "memory")
#define SWZ128(o) ((o) ^ (((o) >> 3) & 0x70))

__device__ __forceinline__ void ldsm4(uint32_t addr, uint32_t* r) {
    asm volatile("ldmatrix.sync.aligned.m8n8.x4.shared.b16 {%0,%1,%2,%3}, [%4];"
                 : "=r"(r[0]), "=r"(r[1]), "=r"(r[2]), "=r"(r[3]) : "r"(addr));
}
__device__ __forceinline__ void ldsm4t(uint32_t addr, uint32_t* r) {
    asm volatile("ldmatrix.sync.aligned.m8n8.x4.trans.shared.b16 {%0,%1,%2,%3}, [%4];"
                 : "=r"(r[0]), "=r"(r[1]), "=r"(r[2]), "=r"(r[3]) : "r"(addr));
}
__device__ __forceinline__ void mma16816(float* d, const uint32_t* a, uint32_t b0, uint32_t b1) {
    asm volatile("mma.sync.aligned.m16n8k16.row.col.f32.f16.f16.f32 "
                 "{%0,%1,%2,%3},{%4,%5,%6,%7},{%8,%9},{%0,%1,%2,%3};"
                 : "+f"(d[0]), "+f"(d[1]), "+f"(d[2]), "+f"(d[3])
                 : "r"(a[0]), "r"(a[1]), "r"(a[2]), "r"(a[3]), "r"(b0), "r"(b1));
}
__device__ __forceinline__ uint32_t packh2(__half a, __half b) {
    __half2 t; t.x = a; t.y = b;
    return *reinterpret_cast<uint32_t*>(&t);
}

// ---------------------------------------------------------------------------
// Split fp32 -> fp16 hi/lo
// ---------------------------------------------------------------------------
__global__ void __launch_bounds__(256) split_kernel(
    const float* __restrict__ in, __half* __restrict__ hi,
    __half* __restrict__ lo, int n4)
{
    int i = blockIdx.x * 256 + threadIdx.x;
    if (i >= n4) return;
    float4 v = ((const float4*)in)[i];
    float vv[4] = {v.x, v.y, v.z, v.w};
    __half h[4], l[4];
    #pragma unroll
    for (int j = 0; j < 4; j++) {
        h[j] = __float2half(vv[j]);
        l[j] = __float2half(vv[j] - __half2float(h[j]));
    }
    ((uint32_t*)hi)[2*i]   = packh2(h[0], h[1]);
    ((uint32_t*)hi)[2*i+1] = packh2(h[2], h[3]);
    ((uint32_t*)lo)[2*i]   = packh2(l[0], l[1]);
    ((uint32_t*)lo)[2*i+1] = packh2(l[2], l[3]);
}

// ---------------------------------------------------------------------------
// Transpose weights: W (KxN fp32, row-major) -> Wt (NxK fp16)
// ---------------------------------------------------------------------------
__global__ void __launch_bounds__(256) tsplit_kernel(
    const float* __restrict__ W, __half* __restrict__ Th, int K, int N)
{
    __shared__ float t[32][33];
    int n0 = blockIdx.x * 32, k0 = blockIdx.y * 32;
    int tx = threadIdx.x, ty = threadIdx.y;
    #pragma unroll
    for (int i = 0; i < 32; i += 8)
        t[ty + i][tx] = W[(size_t)(k0 + ty + i) * N + n0 + tx];
    __syncthreads();
    #pragma unroll
    for (int i = 0; i < 32; i += 8)
        Th[(size_t)(n0 + ty + i) * K + k0 + tx] = __float2half(t[tx][ty + i]);
}

// ---------------------------------------------------------------------------
// mma.sync fp16 2-term GEMM: C(MxN) = (Ah+Al)(MxK) * B(NxK)^T
// CTA tile 256x128, 8 warps as 4(M) x 2(N), warp tile 64x64, BK=64 (SW128).
// 1 CTA/SM; smem = 2 stages x (A 64KB + B 16KB) = 160KB.
// Arithmetic intensity: A tiles read by 2 warps, B by 4 (was 4 / 2 at 128x128
// with 64x32 warp tiles and half the accumulators).
// ---------------------------------------------------------------------------
#define A_TILE_B   (256 * 128)           // 32768 B (one of hi/lo)
#define B_TILE_B   (128 * 128)           // 16384 B
#define STAGE_B    (2 * A_TILE_B + B_TILE_B)   // 81920 B
#define MM_SMEM    (2 * STAGE_B)               // 163840 B

template<int MODE>
__global__ void __launch_bounds__(256, 1) mmasync_kernel(
    const __half* __restrict__ Ah, const __half* __restrict__ Al,
    const __half* __restrict__ Bh,
    float* __restrict__ C, int N, int K)
{
    extern __shared__ char smraw[];
    const uint32_t smb = smem_u32(smraw);

    const int tid  = threadIdx.x;
    const int wid  = tid >> 5, lane = tid & 31;
    const int wm   = wid & 3;          // 4 M-positions (64 rows each)
    const int wn   = wid >> 2;         // 2 N-positions (64 cols each)
    const int bm   = blockIdx.y * 256, bn = blockIdx.x * 128;
    const int l16  = lane & 15, lh = lane >> 4;

    float acc[4][8][4];
    #pragma unroll
    for (int i = 0; i < 4; i++)
        #pragma unroll
        for (int j = 0; j < 8; j++)
            #pragma unroll
            for (int k = 0; k < 4; k++) acc[i][j][k] = 0.f;

    auto fill = [&](int s, int k0) {
        uint32_t sb = smb + (uint32_t)s * STAGE_B;
        // A hi: 256 rows x 8 chunks = 2048
        #pragma unroll
        for (int i = 0; i < 8; i++) {
            int chunk = tid + i * 256;
            int row = chunk >> 3, c = chunk & 7;
            cpa16(sb + SWZ128((uint32_t)(row * 128 + c * 16)),
                  Ah + (size_t)(bm + row) * K + k0 + c * 8);
        }
        // A lo
        #pragma unroll
        for (int i = 0; i < 8; i++) {
            int chunk = tid + i * 256;
            int row = chunk >> 3, c = chunk & 7;
            cpa16(sb + A_TILE_B + SWZ128((uint32_t)(row * 128 + c * 16)),
                  Al + (size_t)(bm + row) * K + k0 + c * 8);
        }
        // B: 128 rows x 8 chunks = 1024
        #pragma unroll
        for (int i = 0; i < 4; i++) {
            int chunk = tid + i * 256;
            int row = chunk >> 3, c = chunk & 7;
            cpa16(sb + 2 * A_TILE_B + SWZ128((uint32_t)(row * 128 + c * 16)),
                  Bh + (size_t)(bn + row) * K + k0 + c * 8);
        }
    };

    const int nch = K >> 6;   // BK = 64
    fill(0, 0); CP_COMMIT();

    for (int i = 0; i < nch; i++) {
        if (i + 1 < nch) { fill((i + 1) & 1, (i + 1) << 6); CP_COMMIT(); CP_WAIT(1); }
        else             { CP_WAIT(0); }
        __syncthreads();

        uint32_t sb  = smb + (uint32_t)(i & 1) * STAGE_B;
        uint32_t Abh = sb, Abl = sb + A_TILE_B, Bbh = sb + 2 * A_TILE_B;

        #pragma unroll
        for (int kh = 0; kh < 4; kh++) {
            const uint32_t koff = (uint32_t)(kh * 32 + lh * 16);
            uint32_t ah[4][4], al[4][4];
            #pragma unroll
            for (int mt = 0; mt < 4; mt++) {
                uint32_t ro = SWZ128((uint32_t)((wm * 64 + mt * 16 + l16) * 128) + koff);
                ldsm4(Abh + ro, ah[mt]);
                ldsm4(Abl + ro, al[mt]);
            }
            uint32_t bh[4][4];
            #pragma unroll
            for (int np = 0; np < 4; np++) {
                uint32_t ro = SWZ128((uint32_t)((wn * 64 + np * 16 + l16) * 128) + koff);
                ldsm4(Bbh + ro, bh[np]);
            }
            // hi pass: 32 independent MMAs
            #pragma unroll
            for (int mt = 0; mt < 4; mt++)
                #pragma unroll
                for (int nt = 0; nt < 8; nt++) {
                    const int np = nt >> 1, o = nt & 1;
                    mma16816(acc[mt][nt], ah[mt], bh[np][o], bh[np][o + 2]);
                }
            // lo pass
            #pragma unroll
            for (int mt = 0; mt < 4; mt++)
                #pragma unroll
                for (int nt = 0; nt < 8; nt++) {
                    const int np = nt >> 1, o = nt & 1;
                    mma16816(acc[mt][nt], al[mt], bh[np][o], bh[np][o + 2]);
                }
        }
        __syncthreads();
    }

    const int er = lane >> 2, ec = (lane & 3) * 2;
    #pragma unroll
    for (int mt = 0; mt < 4; mt++)
        #pragma unroll
        for (int nt = 0; nt < 8; nt++) {
            int r0 = bm + wm * 64 + mt * 16 + er;
            int c0 = bn + wn * 64 + nt * 8 + ec;
            if (MODE == 0) {
                *(float2*)&C[(size_t)r0 * N + c0] =
                    make_float2(acc[mt][nt][0], acc[mt][nt][1]);
                *(float2*)&C[(size_t)(r0 + 8) * N + c0] =
                    make_float2(acc[mt][nt][2], acc[mt][nt][3]);
            } else {
                int bb = r0 >> 11, t = r0 & 2047;
                int part = c0 >> 10, rem = c0 & 1023;
                int hh = rem >> 6, d = rem & 63;
                size_t o = ((((size_t)part * BATCH + bb) * NHEAD + hh) * TSEQ + t) * HDIM + d;
                #pragma unroll
                for (int rr = 0; rr < 2; rr++) {
                    float v0 = acc[mt][nt][2 * rr + 0];
                    float v1 = acc[mt][nt][2 * rr + 1];
                    size_t oo = o + (size_t)rr * 8 * HDIM;
                    if (part == 0) {
                        v0 *= QSCALE; v1 *= QSCALE;
                        __half h0 = __float2half(v0), h1 = __float2half(v1);
                        *(uint32_t*)&g_qkvh[oo] = packh2(h0, h1);
                        *(uint32_t*)&g_qkvl[oo] = packh2(
                            __float2half(v0 - __half2float(h0)),
                            __float2half(v1 - __half2float(h1)));
                    } else {
                        *(uint32_t*)&g_qkvh[oo] = packh2(__float2half(v0), __float2half(v1));
                    }
                }
            }
        }
}

// ---------------------------------------------------------------------------
// Tensor-core flash attention (causal), fp16 2-term, Bq=128, Bk=64, D=64.
// ---------------------------------------------------------------------------
#define FL_SMEM (64 * 1024)

__global__ void __launch_bounds__(256, 2) flash_tc_kernel()
{
    extern __shared__ char smraw[];
    const uint32_t S = smem_u32(smraw);
    const int tid = threadIdx.x, w = tid >> 5, lane = tid & 31;
    const int l16 = lane & 15, lh = lane >> 4;
    const int b = blockIdx.z, h = blockIdx.y;
    const int qt = (int)(gridDim.x - 1 - blockIdx.x);   // heaviest first
    const int n_kt = 2 * qt + 2;

    const uint32_t Qh_s = S, Ql_s = S + 16384;
    const uint32_t stg0 = S + 32768;

    const size_t head = (((size_t)b) * NHEAD + h) * TSEQ * HDIM;
    const size_t HSZ  = (size_t)BATCH * NHEAD * TSEQ * HDIM;
    const __half* qh = g_qkvh + head;
    const __half* ql = g_qkvl + head;
    const __half* kh = g_qkvh + HSZ + head;
    const __half* vh = g_qkvh + 2 * HSZ + head;

    {
        #pragma unroll
        for (int i = 0; i < 8; i++) {
            int idx = tid + i * 256;
            int mtx = idx >> 10, row = (idx >> 3) & 127, c = idx & 7;
            const __half* src = (mtx ? ql : qh) + (size_t)(qt * 128 + row) * HDIM + c * 8;
            cpa16((mtx ? Ql_s : Qh_s) + SWZ128((uint32_t)(row * 128 + c * 16)), src);
        }
    }
    auto fillkv = [&](int s, int kt) {
        uint32_t sb = stg0 + (uint32_t)s * 16384u;
        const __half* bases[2] = {kh, vh};
        #pragma unroll
        for (int i = 0; i < 4; i++) {
            int idx = tid + i * 256;
            int mtx = idx >> 9, row = (idx >> 3) & 63, c = idx & 7;
            cpa16(sb + (uint32_t)mtx * 8192u + SWZ128((uint32_t)(row * 128 + c * 16)),
                  bases[mtx] + (size_t)(kt * 64 + row) * HDIM + c * 8);
        }
    };

    fillkv(0, 0); CP_COMMIT();
    if (n_kt > 1) { fillkv(1, 1); CP_COMMIT(); }

    float m0 = -1e30f, m1 = -1e30f, l0 = 0.f, l1 = 0.f;
    float o[8][4];
    #pragma unroll
    for (int j = 0; j < 8; j++)
        #pragma unroll
        for (int e = 0; e < 4; e++) o[j][e] = 0.f;

    for (int kt = 0; kt < n_kt; kt++) {
        if (kt + 1 < n_kt) { CP_WAIT(1); } else { CP_WAIT(0); }
        __syncthreads();

        const uint32_t sb   = stg0 + (uint32_t)(kt & 1) * 16384u;
        const uint32_t Kh_s = sb, Vh_s = sb + 8192;

        float s[8][4];
        #pragma unroll
        for (int j = 0; j < 8; j++)
            #pragma unroll
            for (int e = 0; e < 4; e++) s[j][e] = 0.f;

        #pragma unroll
        for (int kk = 0; kk < 4; kk++) {
            const uint32_t koff = (uint32_t)(kk * 32 + lh * 16);
            uint32_t qf[4], qlf[4];
            ldsm4(Qh_s + SWZ128((uint32_t)((w * 16 + l16) * 128) + koff), qf);
            ldsm4(Ql_s + SWZ128((uint32_t)((w * 16 + l16) * 128) + koff), qlf);
            #pragma unroll
            for (int gp = 0; gp < 2; gp++) {
                const int g0 = 2 * gp, g1 = 2 * gp + 1;
                uint32_t kf0[4], kf1[4];
                ldsm4(Kh_s + SWZ128((uint32_t)((g0 * 16 + l16) * 128) + koff), kf0);
                ldsm4(Kh_s + SWZ128((uint32_t)((g1 * 16 + l16) * 128) + koff), kf1);
                mma16816(s[2 * g0],     qf, kf0[0], kf0[2]);
                mma16816(s[2 * g0 + 1], qf, kf0[1], kf0[3]);
                mma16816(s[2 * g1],     qf, kf1[0], kf1[2]);
                mma16816(s[2 * g1 + 1], qf, kf1[1], kf1[3]);
                mma16816(s[2 * g0],     qlf, kf0[0], kf0[2]);
                mma16816(s[2 * g0 + 1], qlf, kf0[1], kf0[3]);
                mma16816(s[2 * g1],     qlf, kf1[0], kf1[2]);
                mma16816(s[2 * g1 + 1], qlf, kf1[1], kf1[3]);
            }
        }

        const int row0 = qt * 128 + w * 16 + (lane >> 2);
        if (kt * 64 + 63 > qt * 128 + w * 16) {
            #pragma unroll
            for (int j = 0; j < 8; j++) {
                int colb = kt * 64 + j * 8 + (lane & 3) * 2;
                if (colb + 0 > row0)     s[j][0] = -1e30f;
                if (colb + 1 > row0)     s[j][1] = -1e30f;
                if (colb + 0 > row0 + 8) s[j][2] = -1e30f;
                if (colb + 1 > row0 + 8) s[j][3] = -1e30f;
            }
        }

        float mx0 = -1e30f, mx1 = -1e30f;
        #pragma unroll
        for (int j = 0; j < 8; j++) {
            mx0 = fmaxf(mx0, fmaxf(s[j][0], s[j][1]));
            mx1 = fmaxf(mx1, fmaxf(s[j][2], s[j][3]));
        }
        mx0 = fmaxf(mx0, __shfl_xor_sync(0xffffffffu, mx0, 1));
        mx0 = fmaxf(mx0, __shfl_xor_sync(0xffffffffu, mx0, 2));
        mx1 = fmaxf(mx1, __shfl_xor_sync(0xffffffffu, mx1, 1));
        mx1 = fmaxf(mx1, __shfl_xor_sync(0xffffffffu, mx1, 2));
        float nm0 = fmaxf(m0, mx0), nm1 = fmaxf(m1, mx1);
        float c0 = exp2f(m0 - nm0), c1 = exp2f(m1 - nm1);
        m0 = nm0; m1 = nm1;
        float sum0 = 0.f, sum1 = 0.f;
        #pragma unroll
        for (int j = 0; j < 8; j++) {
            s[j][0] = exp2f(s[j][0] - m0);
            s[j][1] = exp2f(s[j][1] - m0);
            s[j][2] = exp2f(s[j][2] - m1);
            s[j][3] = exp2f(s[j][3] - m1);
            sum0 += s[j][0] + s[j][1];
            sum1 += s[j][2] + s[j][3];
        }
        sum0 += __shfl_xor_sync(0xffffffffu, sum0, 1);
        sum0 += __shfl_xor_sync(0xffffffffu, sum0, 2);
        sum1 += __shfl_xor_sync(0xffffffffu, sum1, 1);
        sum1 += __shfl_xor_sync(0xffffffffu, sum1, 2);
        l0 = l0 * c0 + sum0;
        l1 = l1 * c1 + sum1;
        #pragma unroll
        for (int j = 0; j < 8; j++) {
            o[j][0] *= c0; o[j][1] *= c0; o[j][2] *= c1; o[j][3] *= c1;
        }

        #pragma unroll
        for (int kk = 0; kk < 4; kk++) {
            uint32_t pa[4], pb[4];
            #pragma unroll
            for (int half = 0; half < 2; half++) {
                const int f = 2 * kk + half;
                __half h0 = __float2half(s[f][0]);
                __half h1 = __float2half(s[f][1]);
                __half h2 = __float2half(s[f][2]);
                __half h3 = __float2half(s[f][3]);
                pa[2 * half + 0] = packh2(h0, h1);
                pa[2 * half + 1] = packh2(h2, h3);
                pb[2 * half + 0] = packh2(
                    __float2half(s[f][0] - __half2float(h0)),
                    __float2half(s[f][1] - __half2float(h1)));
                pb[2 * half + 1] = packh2(
                    __float2half(s[f][2] - __half2float(h2)),
                    __float2half(s[f][3] - __half2float(h3)));
            }
            #pragma unroll
            for (int gp = 0; gp < 2; gp++) {
                const int g0 = 2 * gp, g1 = 2 * gp + 1;
                uint32_t vf0[4], vf1[4];
                uint32_t ro0 = SWZ128((uint32_t)((kk * 16 + l16) * 128 + g0 * 32) + (uint32_t)(lh * 16));
                uint32_t ro1 = SWZ128((uint32_t)((kk * 16 + l16) * 128 + g1 * 32) + (uint32_t)(lh * 16));
                ldsm4t(Vh_s + ro0, vf0);
                ldsm4t(Vh_s + ro1, vf1);
                mma16816(o[2 * g0],     pa, vf0[0], vf0[1]);
                mma16816(o[2 * g0 + 1], pa, vf0[2], vf0[3]);
                mma16816(o[2 * g1],     pa, vf1[0], vf1[1]);
                mma16816(o[2 * g1 + 1], pa, vf1[2], vf1[3]);
                mma16816(o[2 * g0],     pb, vf0[0], vf0[1]);
                mma16816(o[2 * g0 + 1], pb, vf0[2], vf0[3]);
                mma16816(o[2 * g1],     pb, vf1[0], vf1[1]);
                mma16816(o[2 * g1 + 1], pb, vf1[2], vf1[3]);
            }
        }

        __syncthreads();
        if (kt + 2 < n_kt) { fillkv(kt & 1, kt + 2); CP_COMMIT(); }
    }

    const float inv0 = 1.f / l0, inv1 = 1.f / l1;
    const int r0 = qt * 128 + w * 16 + (lane >> 2);
    const int t0 = r0, t1 = r0 + 8;
    #pragma unroll
    for (int j = 0; j < 8; j++) {
        int d = j * 8 + (lane & 3) * 2;
        size_t o0 = ((size_t)b * TSEQ + t0) * CDIM + h * HDIM + d;
        size_t o1 = ((size_t)b * TSEQ + t1) * CDIM + h * HDIM + d;
        float y0 = o[j][0] * inv0, y1 = o[j][1] * inv0;
        float y2 = o[j][2] * inv1, y3 = o[j][3] * inv1;
        __half h0 = __float2half(y0), h1 = __float2half(y1);
        __half h2 = __float2half(y2), h3 = __float2half(y3);
        *(uint32_t*)&g_yh[o0] = packh2(h0, h1);
        *(uint32_t*)&g_yh[o1] = packh2(h2, h3);
        *(uint32_t*)&g_yl[o0] = packh2(
            __float2half(y0 - __half2float(h0)),
            __float2half(y1 - __half2float(h1)));
        *(uint32_t*)&g_yl[o1] = packh2(
            __float2half(y2 - __half2float(h2)),
            __float2half(y3 - __half2float(h3)));
    }
}

// ---------------------------------------------------------------------------
extern "C" void kernel_launch(void* const* d_in, const int* in_sizes, int n_in,
                              void* d_out, int out_size)
{
    const float* x      = (const float*)d_in[0];
    const float* w_qkv  = (const float*)d_in[1];
    const float* w_proj = (const float*)d_in[2];
    float* out = (float*)d_out;

    __half *xh, *xl, *yh, *yl, *wq, *wp;
    cudaGetSymbolAddress((void**)&xh, g_xh);
    cudaGetSymbolAddress((void**)&xl, g_xl);
    cudaGetSymbolAddress((void**)&yh, g_yh);
    cudaGetSymbolAddress((void**)&yl, g_yl);
    cudaGetSymbolAddress((void**)&wq, g_wq);
    cudaGetSymbolAddress((void**)&wp, g_wp);

    cudaFuncSetAttribute(mmasync_kernel<0>, cudaFuncAttributeMaxDynamicSharedMemorySize, MM_SMEM);
    cudaFuncSetAttribute(mmasync_kernel<1>, cudaFuncAttributeMaxDynamicSharedMemorySize, MM_SMEM);
    cudaFuncSetAttribute(flash_tc_kernel,   cudaFuncAttributeMaxDynamicSharedMemorySize, FL_SMEM);
    cudaFuncSetAttribute(mmasync_kernel<0>, cudaFuncAttributePreferredSharedMemoryCarveout, 100);
    cudaFuncSetAttribute(mmasync_kernel<1>, cudaFuncAttributePreferredSharedMemoryCarveout, 100);
    cudaFuncSetAttribute(flash_tc_kernel,   cudaFuncAttributePreferredSharedMemoryCarveout, 100);

    const int n4 = MTOT * CDIM / 4;

    split_kernel<<<(n4 + 255) / 256, 256>>>(x, xh, xl, n4);

    {
        dim3 g1(C3 / 32, CDIM / 32), blk(32, 8);
        tsplit_kernel<<<g1, blk>>>(w_qkv, wq, CDIM, C3);
        dim3 g2(CDIM / 32, CDIM / 32);
        tsplit_kernel<<<g2, blk>>>(w_proj, wp, CDIM, CDIM);
    }

    {
        dim3 grid(C3 / 128, MTOT / 256);
        mmasync_kernel<1><<<grid, 256, MM_SMEM>>>(xh, xl, wq, nullptr, C3, CDIM);
    }

    {
        dim3 grid(TSEQ / 128, NHEAD, BATCH);
        flash_tc_kernel<<<grid, 256, FL_SMEM>>>();
    }

    {
        dim3 grid(CDIM / 128, MTOT / 256);
        mmasync_kernel<0><<<grid, 256, MM_SMEM>>>(yh, yl, wp, out, CDIM, CDIM);
    }
    (void)in_sizes; (void)n_in; (void)out_size;
}

// round 9
// speedup vs baseline: 1.0191x; 1.0003x over previous
#include <cuda_runtime.h>
#include <cuda_fp16.h>
#include <cstdint>

// Problem constants
#define BATCH 4
#define TSEQ  2048
#define CDIM  1024
#define NHEAD 16
#define HDIM  64
#define C3    (3*CDIM)
#define MTOT  (BATCH*TSEQ)   // 8192

#define QSCALE 0.18033688011112042f   // 0.125 * log2(e)
#define LOSCALE 1024.0f               // lo-plane pre-scale (exact exponent shift)
#define INVLOSCALE 0.0009765625f      // 2^-10

// ---------------------------------------------------------------------------
// Device-global scratch (no allocation allowed)
// ---------------------------------------------------------------------------
__device__ __align__(256) __half g_qkvh[(size_t)3 * BATCH * NHEAD * TSEQ * HDIM];
__device__ __align__(256) __half g_qkvl[(size_t)3 * BATCH * NHEAD * TSEQ * HDIM]; // Q-lo, UNSCALED
__device__ __align__(256) __half g_yh[(size_t)MTOT * CDIM];
__device__ __align__(256) __half g_yl[(size_t)MTOT * CDIM];   // scaled x1024
__device__ __align__(256) __half g_xh[(size_t)MTOT * CDIM];
__device__ __align__(256) __half g_xl[(size_t)MTOT * CDIM];   // scaled x1024
__device__ __align__(256) __half g_wq[(size_t)C3 * CDIM];     // transposed N x K
__device__ __align__(256) __half g_wp[(size_t)CDIM * CDIM];   // transposed N x K

// ---------------------------------------------------------------------------
// Helpers (baseline PTX only)
// ---------------------------------------------------------------------------
__device__ __forceinline__ uint32_t smem_u32(const void* p) {
    uint32_t a;
    asm("{ .reg .u64 t; cvta.to.shared.u64 t, %1; cvt.u32.u64 %0, t; }" : "=r"(a) : "l"(p));
    return a;
}
__device__ __forceinline__ void cpa16(uint32_t dst, const void* src) {
    asm volatile("cp.async.cg.shared.global [%0], [%1], 16;\n" :: "r"(dst), "l"(src));
}
#define CP_COMMIT() asm volatile("cp.async.commit_group;\n" ::: "memory")
#define CP_WAIT(n)  asm volatile("cp.async.wait_group %0;\n" :: "n"(n) : "memory")
#define SWZ128(o) ((o) ^ (((o) >> 3) & 0x70))

__device__ __forceinline__ void ldsm4(uint32_t addr, uint32_t* r) {
    asm volatile("ldmatrix.sync.aligned.m8n8.x4.shared.b16 {%0,%1,%2,%3}, [%4];"
                 : "=r"(r[0]), "=r"(r[1]), "=r"(r[2]), "=r"(r[3]) : "r"(addr));
}
__device__ __forceinline__ void ldsm4t(uint32_t addr, uint32_t* r) {
    asm volatile("ldmatrix.sync.aligned.m8n8.x4.trans.shared.b16 {%0,%1,%2,%3}, [%4];"
                 : "=r"(r[0]), "=r"(r[1]), "=r"(r[2]), "=r"(r[3]) : "r"(addr));
}
// fp32-accumulate MMA
__device__ __forceinline__ void mma16816(float* d, const uint32_t* a, uint32_t b0, uint32_t b1) {
    asm volatile("mma.sync.aligned.m16n8k16.row.col.f32.f16.f16.f32 "
                 "{%0,%1,%2,%3},{%4,%5,%6,%7},{%8,%9},{%0,%1,%2,%3};"
                 : "+f"(d[0]), "+f"(d[1]), "+f"(d[2]), "+f"(d[3])
                 : "r"(a[0]), "r"(a[1]), "r"(a[2]), "r"(a[3]), "r"(b0), "r"(b1));
}
// fp16-accumulate MMA (d/c are f16x2 pairs; d0 packs (r,c0),(r,c1); d1 packs (r+8,c0),(r+8,c1))
__device__ __forceinline__ void mma16816h(uint32_t* d, const uint32_t* a, uint32_t b0, uint32_t b1) {
    asm volatile("mma.sync.aligned.m16n8k16.row.col.f16.f16.f16.f16 "
                 "{%0,%1},{%2,%3,%4,%5},{%6,%7},{%0,%1};"
                 : "+r"(d[0]), "+r"(d[1])
                 : "r"(a[0]), "r"(a[1]), "r"(a[2]), "r"(a[3]), "r"(b0), "r"(b1));
}
__device__ __forceinline__ uint32_t packh2(__half a, __half b) {
    __half2 t; t.x = a; t.y = b;
    return *reinterpret_cast<uint32_t*>(&t);
}

// ---------------------------------------------------------------------------
// Split fp32 -> fp16 hi + lo*1024
// ---------------------------------------------------------------------------
__global__ void __launch_bounds__(256) split_kernel(
    const float* __restrict__ in, __half* __restrict__ hi,
    __half* __restrict__ lo, int n4)
{
    int i = blockIdx.x * 256 + threadIdx.x;
    if (i >= n4) return;
    float4 v = ((const float4*)in)[i];
    float vv[4] = {v.x, v.y, v.z, v.w};
    __half h[4], l[4];
    #pragma unroll
    for (int j = 0; j < 4; j++) {
        h[j] = __float2half(vv[j]);
        l[j] = __float2half((vv[j] - __half2float(h[j])) * LOSCALE);
    }
    ((uint32_t*)hi)[2*i]   = packh2(h[0], h[1]);
    ((uint32_t*)hi)[2*i+1] = packh2(h[2], h[3]);
    ((uint32_t*)lo)[2*i]   = packh2(l[0], l[1]);
    ((uint32_t*)lo)[2*i+1] = packh2(l[2], l[3]);
}

// ---------------------------------------------------------------------------
// Transpose weights: W (KxN fp32, row-major) -> Wt (NxK fp16)
// ---------------------------------------------------------------------------
__global__ void __launch_bounds__(256) tsplit_kernel(
    const float* __restrict__ W, __half* __restrict__ Th, int K, int N)
{
    __shared__ float t[32][33];
    int n0 = blockIdx.x * 32, k0 = blockIdx.y * 32;
    int tx = threadIdx.x, ty = threadIdx.y;
    #pragma unroll
    for (int i = 0; i < 32; i += 8)
        t[ty + i][tx] = W[(size_t)(k0 + ty + i) * N + n0 + tx];
    __syncthreads();
    #pragma unroll
    for (int i = 0; i < 32; i += 8)
        Th[(size_t)(n0 + ty + i) * K + k0 + tx] = __float2half(t[tx][ty + i]);
}

// ---------------------------------------------------------------------------
// mma.sync GEMM: C = (Ah + Al*2^-10) * B^T.
// hi-pass: fp32-acc MMA; lo-pass: fp16-acc MMA (half-rate-bypass experiment).
// Tile 128x128, 8 warps 2Mx4N (warp 64x32), BK=64 (SW128), double buffer.
// ---------------------------------------------------------------------------
#define TILE_B     (128 * 128)           // 16384 B
#define STAGE_B    (3 * TILE_B)          // 49152 B
#define MM_SMEM    (2 * STAGE_B)         // 98304 B

template<int MODE>
__global__ void __launch_bounds__(256, 1) mmasync_kernel(
    const __half* __restrict__ Ah, const __half* __restrict__ Al,
    const __half* __restrict__ Bh,
    float* __restrict__ C, int N, int K)
{
    extern __shared__ char smraw[];
    const uint32_t smb = smem_u32(smraw);

    const int tid  = threadIdx.x;
    const int wid  = tid >> 5, lane = tid & 31;
    const int wm   = wid & 1;
    const int wn   = wid >> 1;
    const int bm   = blockIdx.y * 128, bn = blockIdx.x * 128;
    const int l16  = lane & 15, lh = lane >> 4;

    float acc[4][4][4];
    uint32_t accl[4][4][2];
    #pragma unroll
    for (int i = 0; i < 4; i++)
        #pragma unroll
        for (int j = 0; j < 4; j++) {
            #pragma unroll
            for (int k = 0; k < 4; k++) acc[i][j][k] = 0.f;
            accl[i][j][0] = 0u; accl[i][j][1] = 0u;
        }

    const __half* srcs[3] = {Ah, Al, Bh};

    auto fill = [&](int s, int k0) {
        uint32_t sb = smb + (uint32_t)s * STAGE_B;
        #pragma unroll
        for (int t = 0; t < 3; t++) {
            const __half* src = srcs[t];
            const int rbase = (t < 2) ? bm : bn;
            uint32_t tb = sb + (uint32_t)t * TILE_B;
            #pragma unroll
            for (int i = 0; i < 4; i++) {
                int chunk = tid + i * 256;
                int row = chunk >> 3, c = chunk & 7;
                cpa16(tb + SWZ128((uint32_t)(row * 128 + c * 16)),
                      src + (size_t)(rbase + row) * K + k0 + c * 8);
            }
        }
    };

    const int nch = K >> 6;   // BK = 64
    fill(0, 0); CP_COMMIT();

    for (int i = 0; i < nch; i++) {
        if (i + 1 < nch) { fill((i + 1) & 1, (i + 1) << 6); CP_COMMIT(); CP_WAIT(1); }
        else             { CP_WAIT(0); }
        __syncthreads();

        uint32_t sb = smb + (uint32_t)(i & 1) * STAGE_B;
        uint32_t Abh = sb, Abl = sb + TILE_B, Bbh = sb + 2 * TILE_B;

        #pragma unroll
        for (int kh = 0; kh < 4; kh++) {
            const uint32_t koff = (uint32_t)(kh * 32 + lh * 16);
            uint32_t ah[4][4], al[4][4];
            #pragma unroll
            for (int mt = 0; mt < 4; mt++) {
                uint32_t ro = SWZ128((uint32_t)((wm * 64 + mt * 16 + l16) * 128) + koff);
                ldsm4(Abh + ro, ah[mt]);
                ldsm4(Abl + ro, al[mt]);
            }
            uint32_t bh[2][4];
            #pragma unroll
            for (int np = 0; np < 2; np++) {
                uint32_t ro = SWZ128((uint32_t)((wn * 32 + np * 16 + l16) * 128) + koff);
                ldsm4(Bbh + ro, bh[np]);
            }
            // hi pass: fp32-acc MMAs
            #pragma unroll
            for (int mt = 0; mt < 4; mt++)
                #pragma unroll
                for (int nt = 0; nt < 4; nt++) {
                    const int np = nt >> 1, o = nt & 1;
                    mma16816(acc[mt][nt], ah[mt], bh[np][o], bh[np][o + 2]);
                }
            // lo pass: fp16-acc MMAs (lo plane pre-scaled x1024)
            #pragma unroll
            for (int mt = 0; mt < 4; mt++)
                #pragma unroll
                for (int nt = 0; nt < 4; nt++) {
                    const int np = nt >> 1, o = nt & 1;
                    mma16816h(accl[mt][nt], al[mt], bh[np][o], bh[np][o + 2]);
                }
        }
        __syncthreads();
    }

    const int er = lane >> 2, ec = (lane & 3) * 2;
    #pragma unroll
    for (int mt = 0; mt < 4; mt++)
        #pragma unroll
        for (int nt = 0; nt < 4; nt++) {
            int r0 = bm + wm * 64 + mt * 16 + er;
            int c0 = bn + wn * 32 + nt * 8 + ec;
            __half2 p0 = *reinterpret_cast<__half2*>(&accl[mt][nt][0]);
            __half2 p1 = *reinterpret_cast<__half2*>(&accl[mt][nt][1]);
            float v[4];
            v[0] = acc[mt][nt][0] + __half2float(p0.x) * INVLOSCALE;
            v[1] = acc[mt][nt][1] + __half2float(p0.y) * INVLOSCALE;
            v[2] = acc[mt][nt][2] + __half2float(p1.x) * INVLOSCALE;
            v[3] = acc[mt][nt][3] + __half2float(p1.y) * INVLOSCALE;
            if (MODE == 0) {
                *(float2*)&C[(size_t)r0 * N + c0]       = make_float2(v[0], v[1]);
                *(float2*)&C[(size_t)(r0 + 8) * N + c0] = make_float2(v[2], v[3]);
            } else {
                int bb = r0 >> 11, t = r0 & 2047;
                int part = c0 >> 10, rem = c0 & 1023;
                int hh = rem >> 6, d = rem & 63;
                size_t o = ((((size_t)part * BATCH + bb) * NHEAD + hh) * TSEQ + t) * HDIM + d;
                #pragma unroll
                for (int rr = 0; rr < 2; rr++) {
                    float v0 = v[2 * rr + 0];
                    float v1 = v[2 * rr + 1];
                    size_t oo = o + (size_t)rr * 8 * HDIM;
                    if (part == 0) {
                        v0 *= QSCALE; v1 *= QSCALE;
                        __half h0 = __float2half(v0), h1 = __float2half(v1);
                        *(uint32_t*)&g_qkvh[oo] = packh2(h0, h1);
                        *(uint32_t*)&g_qkvl[oo] = packh2(                   // UNSCALED lo
                            __float2half(v0 - __half2float(h0)),
                            __float2half(v1 - __half2float(h1)));
                    } else {
                        *(uint32_t*)&g_qkvh[oo] = packh2(__float2half(v0), __float2half(v1));
                    }
                }
            }
        }
}

// ---------------------------------------------------------------------------
// Tensor-core flash attention (causal), fp16 2-term, Bq=128, Bk=64, D=64.
// (unchanged this round except g_yl written x1024 for the proj GEMM)
// ---------------------------------------------------------------------------
#define FL_SMEM (64 * 1024)

__global__ void __launch_bounds__(256, 2) flash_tc_kernel()
{
    extern __shared__ char smraw[];
    const uint32_t S = smem_u32(smraw);
    const int tid = threadIdx.x, w = tid >> 5, lane = tid & 31;
    const int l16 = lane & 15, lh = lane >> 4;
    const int b = blockIdx.z, h = blockIdx.y;
    const int qt = (int)(gridDim.x - 1 - blockIdx.x);   // heaviest first
    const int n_kt = 2 * qt + 2;

    const uint32_t Qh_s = S, Ql_s = S + 16384;
    const uint32_t stg0 = S + 32768;

    const size_t head = (((size_t)b) * NHEAD + h) * TSEQ * HDIM;
    const size_t HSZ  = (size_t)BATCH * NHEAD * TSEQ * HDIM;
    const __half* qh = g_qkvh + head;
    const __half* ql = g_qkvl + head;
    const __half* kh = g_qkvh + HSZ + head;
    const __half* vh = g_qkvh + 2 * HSZ + head;

    {
        #pragma unroll
        for (int i = 0; i < 8; i++) {
            int idx = tid + i * 256;
            int mtx = idx >> 10, row = (idx >> 3) & 127, c = idx & 7;
            const __half* src = (mtx ? ql : qh) + (size_t)(qt * 128 + row) * HDIM + c * 8;
            cpa16((mtx ? Ql_s : Qh_s) + SWZ128((uint32_t)(row * 128 + c * 16)), src);
        }
    }
    auto fillkv = [&](int s, int kt) {
        uint32_t sb = stg0 + (uint32_t)s * 16384u;
        const __half* bases[2] = {kh, vh};
        #pragma unroll
        for (int i = 0; i < 4; i++) {
            int idx = tid + i * 256;
            int mtx = idx >> 9, row = (idx >> 3) & 63, c = idx & 7;
            cpa16(sb + (uint32_t)mtx * 8192u + SWZ128((uint32_t)(row * 128 + c * 16)),
                  bases[mtx] + (size_t)(kt * 64 + row) * HDIM + c * 8);
        }
    };

    fillkv(0, 0); CP_COMMIT();
    if (n_kt > 1) { fillkv(1, 1); CP_COMMIT(); }

    float m0 = -1e30f, m1 = -1e30f, l0 = 0.f, l1 = 0.f;
    float o[8][4];
    #pragma unroll
    for (int j = 0; j < 8; j++)
        #pragma unroll
        for (int e = 0; e < 4; e++) o[j][e] = 0.f;

    for (int kt = 0; kt < n_kt; kt++) {
        if (kt + 1 < n_kt) { CP_WAIT(1); } else { CP_WAIT(0); }
        __syncthreads();

        const uint32_t sb   = stg0 + (uint32_t)(kt & 1) * 16384u;
        const uint32_t Kh_s = sb, Vh_s = sb + 8192;

        float s[8][4];
        #pragma unroll
        for (int j = 0; j < 8; j++)
            #pragma unroll
            for (int e = 0; e < 4; e++) s[j][e] = 0.f;

        #pragma unroll
        for (int kk = 0; kk < 4; kk++) {
            const uint32_t koff = (uint32_t)(kk * 32 + lh * 16);
            uint32_t qf[4], qlf[4];
            ldsm4(Qh_s + SWZ128((uint32_t)((w * 16 + l16) * 128) + koff), qf);
            ldsm4(Ql_s + SWZ128((uint32_t)((w * 16 + l16) * 128) + koff), qlf);
            #pragma unroll
            for (int gp = 0; gp < 2; gp++) {
                const int g0 = 2 * gp, g1 = 2 * gp + 1;
                uint32_t kf0[4], kf1[4];
                ldsm4(Kh_s + SWZ128((uint32_t)((g0 * 16 + l16) * 128) + koff), kf0);
                ldsm4(Kh_s + SWZ128((uint32_t)((g1 * 16 + l16) * 128) + koff), kf1);
                mma16816(s[2 * g0],     qf, kf0[0], kf0[2]);
                mma16816(s[2 * g0 + 1], qf, kf0[1], kf0[3]);
                mma16816(s[2 * g1],     qf, kf1[0], kf1[2]);
                mma16816(s[2 * g1 + 1], qf, kf1[1], kf1[3]);
                mma16816(s[2 * g0],     qlf, kf0[0], kf0[2]);
                mma16816(s[2 * g0 + 1], qlf, kf0[1], kf0[3]);
                mma16816(s[2 * g1],     qlf, kf1[0], kf1[2]);
                mma16816(s[2 * g1 + 1], qlf, kf1[1], kf1[3]);
            }
        }

        const int row0 = qt * 128 + w * 16 + (lane >> 2);
        if (kt * 64 + 63 > qt * 128 + w * 16) {
            #pragma unroll
            for (int j = 0; j < 8; j++) {
                int colb = kt * 64 + j * 8 + (lane & 3) * 2;
                if (colb + 0 > row0)     s[j][0] = -1e30f;
                if (colb + 1 > row0)     s[j][1] = -1e30f;
                if (colb + 0 > row0 + 8) s[j][2] = -1e30f;
                if (colb + 1 > row0 + 8) s[j][3] = -1e30f;
            }
        }

        float mx0 = -1e30f, mx1 = -1e30f;
        #pragma unroll
        for (int j = 0; j < 8; j++) {
            mx0 = fmaxf(mx0, fmaxf(s[j][0], s[j][1]));
            mx1 = fmaxf(mx1, fmaxf(s[j][2], s[j][3]));
        }
        mx0 = fmaxf(mx0, __shfl_xor_sync(0xffffffffu, mx0, 1));
        mx0 = fmaxf(mx0, __shfl_xor_sync(0xffffffffu, mx0, 2));
        mx1 = fmaxf(mx1, __shfl_xor_sync(0xffffffffu, mx1, 1));
        mx1 = fmaxf(mx1, __shfl_xor_sync(0xffffffffu, mx1, 2));
        float nm0 = fmaxf(m0, mx0), nm1 = fmaxf(m1, mx1);
        float c0 = exp2f(m0 - nm0), c1 = exp2f(m1 - nm1);
        m0 = nm0; m1 = nm1;
        float sum0 = 0.f, sum1 = 0.f;
        #pragma unroll
        for (int j = 0; j < 8; j++) {
            s[j][0] = exp2f(s[j][0] - m0);
            s[j][1] = exp2f(s[j][1] - m0);
            s[j][2] = exp2f(s[j][2] - m1);
            s[j][3] = exp2f(s[j][3] - m1);
            sum0 += s[j][0] + s[j][1];
            sum1 += s[j][2] + s[j][3];
        }
        sum0 += __shfl_xor_sync(0xffffffffu, sum0, 1);
        sum0 += __shfl_xor_sync(0xffffffffu, sum0, 2);
        sum1 += __shfl_xor_sync(0xffffffffu, sum1, 1);
        sum1 += __shfl_xor_sync(0xffffffffu, sum1, 2);
        l0 = l0 * c0 + sum0;
        l1 = l1 * c1 + sum1;
        #pragma unroll
        for (int j = 0; j < 8; j++) {
            o[j][0] *= c0; o[j][1] *= c0; o[j][2] *= c1; o[j][3] *= c1;
        }

        #pragma unroll
        for (int kk = 0; kk < 4; kk++) {
            uint32_t pa[4], pb[4];
            #pragma unroll
            for (int half = 0; half < 2; half++) {
                const int f = 2 * kk + half;
                __half h0 = __float2half(s[f][0]);
                __half h1 = __float2half(s[f][1]);
                __half h2 = __float2half(s[f][2]);
                __half h3 = __float2half(s[f][3]);
                pa[2 * half + 0] = packh2(h0, h1);
                pa[2 * half + 1] = packh2(h2, h3);
                pb[2 * half + 0] = packh2(
                    __float2half(s[f][0] - __half2float(h0)),
                    __float2half(s[f][1] - __half2float(h1)));
                pb[2 * half + 1] = packh2(
                    __float2half(s[f][2] - __half2float(h2)),
                    __float2half(s[f][3] - __half2float(h3)));
            }
            #pragma unroll
            for (int gp = 0; gp < 2; gp++) {
                const int g0 = 2 * gp, g1 = 2 * gp + 1;
                uint32_t vf0[4], vf1[4];
                uint32_t ro0 = SWZ128((uint32_t)((kk * 16 + l16) * 128 + g0 * 32) + (uint32_t)(lh * 16));
                uint32_t ro1 = SWZ128((uint32_t)((kk * 16 + l16) * 128 + g1 * 32) + (uint32_t)(lh * 16));
                ldsm4t(Vh_s + ro0, vf0);
                ldsm4t(Vh_s + ro1, vf1);
                mma16816(o[2 * g0],     pa, vf0[0], vf0[1]);
                mma16816(o[2 * g0 + 1], pa, vf0[2], vf0[3]);
                mma16816(o[2 * g1],     pa, vf1[0], vf1[1]);
                mma16816(o[2 * g1 + 1], pa, vf1[2], vf1[3]);
                mma16816(o[2 * g0],     pb, vf0[0], vf0[1]);
                mma16816(o[2 * g0 + 1], pb, vf0[2], vf0[3]);
                mma16816(o[2 * g1],     pb, vf1[0], vf1[1]);
                mma16816(o[2 * g1 + 1], pb, vf1[2], vf1[3]);
            }
        }

        __syncthreads();
        if (kt + 2 < n_kt) { fillkv(kt & 1, kt + 2); CP_COMMIT(); }
    }

    const float inv0 = 1.f / l0, inv1 = 1.f / l1;
    const int r0 = qt * 128 + w * 16 + (lane >> 2);
    const int t0 = r0, t1 = r0 + 8;
    #pragma unroll
    for (int j = 0; j < 8; j++) {
        int d = j * 8 + (lane & 3) * 2;
        size_t o0 = ((size_t)b * TSEQ + t0) * CDIM + h * HDIM + d;
        size_t o1 = ((size_t)b * TSEQ + t1) * CDIM + h * HDIM + d;
        float y0 = o[j][0] * inv0, y1 = o[j][1] * inv0;
        float y2 = o[j][2] * inv1, y3 = o[j][3] * inv1;
        __half h0 = __float2half(y0), h1 = __float2half(y1);
        __half h2 = __float2half(y2), h3 = __float2half(y3);
        *(uint32_t*)&g_yh[o0] = packh2(h0, h1);
        *(uint32_t*)&g_yh[o1] = packh2(h2, h3);
        *(uint32_t*)&g_yl[o0] = packh2(                          // scaled x1024
            __float2half((y0 - __half2float(h0)) * LOSCALE),
            __float2half((y1 - __half2float(h1)) * LOSCALE));
        *(uint32_t*)&g_yl[o1] = packh2(
            __float2half((y2 - __half2float(h2)) * LOSCALE),
            __float2half((y3 - __half2float(h3)) * LOSCALE));
    }
}

// ---------------------------------------------------------------------------
extern "C" void kernel_launch(void* const* d_in, const int* in_sizes, int n_in,
                              void* d_out, int out_size)
{
    const float* x      = (const float*)d_in[0];
    const float* w_qkv  = (const float*)d_in[1];
    const float* w_proj = (const float*)d_in[2];
    float* out = (float*)d_out;

    __half *xh, *xl, *yh, *yl, *wq, *wp;
    cudaGetSymbolAddress((void**)&xh, g_xh);
    cudaGetSymbolAddress((void**)&xl, g_xl);
    cudaGetSymbolAddress((void**)&yh, g_yh);
    cudaGetSymbolAddress((void**)&yl, g_yl);
    cudaGetSymbolAddress((void**)&wq, g_wq);
    cudaGetSymbolAddress((void**)&wp, g_wp);

    cudaFuncSetAttribute(mmasync_kernel<0>, cudaFuncAttributeMaxDynamicSharedMemorySize, MM_SMEM);
    cudaFuncSetAttribute(mmasync_kernel<1>, cudaFuncAttributeMaxDynamicSharedMemorySize, MM_SMEM);
    cudaFuncSetAttribute(flash_tc_kernel,   cudaFuncAttributeMaxDynamicSharedMemorySize, FL_SMEM);
    cudaFuncSetAttribute(mmasync_kernel<0>, cudaFuncAttributePreferredSharedMemoryCarveout, 100);
    cudaFuncSetAttribute(mmasync_kernel<1>, cudaFuncAttributePreferredSharedMemoryCarveout, 100);
    cudaFuncSetAttribute(flash_tc_kernel,   cudaFuncAttributePreferredSharedMemoryCarveout, 100);

    const int n4 = MTOT * CDIM / 4;

    split_kernel<<<(n4 + 255) / 256, 256>>>(x, xh, xl, n4);

    {
        dim3 g1(C3 / 32, CDIM / 32), blk(32, 8);
        tsplit_kernel<<<g1, blk>>>(w_qkv, wq, CDIM, C3);
        dim3 g2(CDIM / 32, CDIM / 32);
        tsplit_kernel<<<g2, blk>>>(w_proj, wp, CDIM, CDIM);
    }

    {
        dim3 grid(C3 / 128, MTOT / 128);
        mmasync_kernel<1><<<grid, 256, MM_SMEM>>>(xh, xl, wq, nullptr, C3, CDIM);
    }

    {
        dim3 grid(TSEQ / 128, NHEAD, BATCH);
        flash_tc_kernel<<<grid, 256, FL_SMEM>>>();
    }

    {
        dim3 grid(CDIM / 128, MTOT / 128);
        mmasync_kernel<0><<<grid, 256, MM_SMEM>>>(yh, yl, wp, out, CDIM, CDIM);
    }
    (void)in_sizes; (void)n_in; (void)out_size;
}

// round 10
// speedup vs baseline: 1.2483x; 1.2249x over previous
#include <cuda_runtime.h>
#include <cuda_fp16.h>
#include <cstdint>

// Problem constants
#define BATCH 4
#define TSEQ  2048
#define CDIM  1024
#define NHEAD 16
#define HDIM  64
#define C3    (3*CDIM)
#define MTOT  (BATCH*TSEQ)   // 8192

#define QSCALE 0.18033688011112042f   // 0.125 * log2(e)
#define LOSCALE 1024.0f               // lo-plane pre-scale (exact exponent shift)
#define INVLOSCALE 0.0009765625f      // 2^-10

// ---------------------------------------------------------------------------
// Device-global scratch (no allocation allowed)
// ---------------------------------------------------------------------------
__device__ __align__(256) __half g_qkvh[(size_t)3 * BATCH * NHEAD * TSEQ * HDIM];
__device__ __align__(256) __half g_qkvl[(size_t)3 * BATCH * NHEAD * TSEQ * HDIM]; // Q-lo, UNSCALED
__device__ __align__(256) __half g_yh[(size_t)MTOT * CDIM];
__device__ __align__(256) __half g_yl[(size_t)MTOT * CDIM];   // scaled x1024
__device__ __align__(256) __half g_xh[(size_t)MTOT * CDIM];
__device__ __align__(256) __half g_xl[(size_t)MTOT * CDIM];   // scaled x1024
__device__ __align__(256) __half g_wq[(size_t)C3 * CDIM];     // transposed N x K
__device__ __align__(256) __half g_wp[(size_t)CDIM * CDIM];   // transposed N x K

// ---------------------------------------------------------------------------
// Helpers (baseline PTX only)
// ---------------------------------------------------------------------------
__device__ __forceinline__ uint32_t smem_u32(const void* p) {
    uint32_t a;
    asm("{ .reg .u64 t; cvta.to.shared.u64 t, %1; cvt.u32.u64 %0, t; }" : "=r"(a) : "l"(p));
    return a;
}
__device__ __forceinline__ void cpa16(uint32_t dst, const void* src) {
    asm volatile("cp.async.cg.shared.global [%0], [%1], 16;\n" :: "r"(dst), "l"(src));
}
#define CP_COMMIT() asm volatile("cp.async.commit_group;\n" ::: "memory")
#define CP_WAIT(n)  asm volatile("cp.async.wait_group %0;\n" :: "n"(n) : "memory")
#define SWZ128(o) ((o) ^ (((o) >> 3) & 0x70))

__device__ __forceinline__ void ldsm4(uint32_t addr, uint32_t* r) {
    asm volatile("ldmatrix.sync.aligned.m8n8.x4.shared.b16 {%0,%1,%2,%3}, [%4];"
                 : "=r"(r[0]), "=r"(r[1]), "=r"(r[2]), "=r"(r[3]) : "r"(addr));
}
__device__ __forceinline__ void ldsm4t(uint32_t addr, uint32_t* r) {
    asm volatile("ldmatrix.sync.aligned.m8n8.x4.trans.shared.b16 {%0,%1,%2,%3}, [%4];"
                 : "=r"(r[0]), "=r"(r[1]), "=r"(r[2]), "=r"(r[3]) : "r"(addr));
}
// fp32-accumulate MMA
__device__ __forceinline__ void mma16816(float* d, const uint32_t* a, uint32_t b0, uint32_t b1) {
    asm volatile("mma.sync.aligned.m16n8k16.row.col.f32.f16.f16.f32 "
                 "{%0,%1,%2,%3},{%4,%5,%6,%7},{%8,%9},{%0,%1,%2,%3};"
                 : "+f"(d[0]), "+f"(d[1]), "+f"(d[2]), "+f"(d[3])
                 : "r"(a[0]), "r"(a[1]), "r"(a[2]), "r"(a[3]), "r"(b0), "r"(b1));
}
// fp16-accumulate MMA
__device__ __forceinline__ void mma16816h(uint32_t* d, const uint32_t* a, uint32_t b0, uint32_t b1) {
    asm volatile("mma.sync.aligned.m16n8k16.row.col.f16.f16.f16.f16 "
                 "{%0,%1},{%2,%3,%4,%5},{%6,%7},{%0,%1};"
                 : "+r"(d[0]), "+r"(d[1])
                 : "r"(a[0]), "r"(a[1]), "r"(a[2]), "r"(a[3]), "r"(b0), "r"(b1));
}
__device__ __forceinline__ uint32_t packh2(__half a, __half b) {
    __half2 t; t.x = a; t.y = b;
    return *reinterpret_cast<uint32_t*>(&t);
}

// ---------------------------------------------------------------------------
// Split fp32 -> fp16 hi + lo*1024
// ---------------------------------------------------------------------------
__global__ void __launch_bounds__(256) split_kernel(
    const float* __restrict__ in, __half* __restrict__ hi,
    __half* __restrict__ lo, int n4)
{
    int i = blockIdx.x * 256 + threadIdx.x;
    if (i >= n4) return;
    float4 v = ((const float4*)in)[i];
    float vv[4] = {v.x, v.y, v.z, v.w};
    __half h[4], l[4];
    #pragma unroll
    for (int j = 0; j < 4; j++) {
        h[j] = __float2half(vv[j]);
        l[j] = __float2half((vv[j] - __half2float(h[j])) * LOSCALE);
    }
    ((uint32_t*)hi)[2*i]   = packh2(h[0], h[1]);
    ((uint32_t*)hi)[2*i+1] = packh2(h[2], h[3]);
    ((uint32_t*)lo)[2*i]   = packh2(l[0], l[1]);
    ((uint32_t*)lo)[2*i+1] = packh2(l[2], l[3]);
}

// ---------------------------------------------------------------------------
// Transpose weights: W (KxN fp32, row-major) -> Wt (NxK fp16)
// ---------------------------------------------------------------------------
__global__ void __launch_bounds__(256) tsplit_kernel(
    const float* __restrict__ W, __half* __restrict__ Th, int K, int N)
{
    __shared__ float t[32][33];
    int n0 = blockIdx.x * 32, k0 = blockIdx.y * 32;
    int tx = threadIdx.x, ty = threadIdx.y;
    #pragma unroll
    for (int i = 0; i < 32; i += 8)
        t[ty + i][tx] = W[(size_t)(k0 + ty + i) * N + n0 + tx];
    __syncthreads();
    #pragma unroll
    for (int i = 0; i < 32; i += 8)
        Th[(size_t)(n0 + ty + i) * K + k0 + tx] = __float2half(t[tx][ty + i]);
}

// ---------------------------------------------------------------------------
// mma.sync GEMM, tile 128x128, BK=64 (SW128), double buffer.
// MODE 0: proj, 2-term, fp32 C out.
// MODE 1: Q-GEMM (N=1024), 2-term, epilogue scale+split to g_qkvh/g_qkvl.
// MODE 2: KV-GEMM (N=2048, B = wq+1024 rows), 1-term, epilogue hi only.
// ---------------------------------------------------------------------------
#define TILE_B     (128 * 128)           // 16384 B
#define STAGE_B    (3 * TILE_B)          // 49152 B
#define MM_SMEM    (2 * STAGE_B)         // 98304 B

template<int MODE>
__global__ void __launch_bounds__(256, 1) mmasync_kernel(
    const __half* __restrict__ Ah, const __half* __restrict__ Al,
    const __half* __restrict__ Bh,
    float* __restrict__ C, int N, int K)
{
    constexpr bool TWO = (MODE != 2);   // 2-term (hi+lo) vs 1-term
    extern __shared__ char smraw[];
    const uint32_t smb = smem_u32(smraw);

    const int tid  = threadIdx.x;
    const int wid  = tid >> 5, lane = tid & 31;
    const int wm   = wid & 1;
    const int wn   = wid >> 1;
    const int bm   = blockIdx.y * 128, bn = blockIdx.x * 128;
    const int l16  = lane & 15, lh = lane >> 4;

    float acc[4][4][4];
    uint32_t accl[4][4][2];
    #pragma unroll
    for (int i = 0; i < 4; i++)
        #pragma unroll
        for (int j = 0; j < 4; j++) {
            #pragma unroll
            for (int k = 0; k < 4; k++) acc[i][j][k] = 0.f;
            accl[i][j][0] = 0u; accl[i][j][1] = 0u;
        }

    auto fill = [&](int s, int k0) {
        uint32_t sb = smb + (uint32_t)s * STAGE_B;
        // A hi
        #pragma unroll
        for (int i = 0; i < 4; i++) {
            int chunk = tid + i * 256;
            int row = chunk >> 3, c = chunk & 7;
            cpa16(sb + SWZ128((uint32_t)(row * 128 + c * 16)),
                  Ah + (size_t)(bm + row) * K + k0 + c * 8);
        }
        // A lo (2-term only)
        if (TWO) {
            #pragma unroll
            for (int i = 0; i < 4; i++) {
                int chunk = tid + i * 256;
                int row = chunk >> 3, c = chunk & 7;
                cpa16(sb + TILE_B + SWZ128((uint32_t)(row * 128 + c * 16)),
                      Al + (size_t)(bm + row) * K + k0 + c * 8);
            }
        }
        // B
        #pragma unroll
        for (int i = 0; i < 4; i++) {
            int chunk = tid + i * 256;
            int row = chunk >> 3, c = chunk & 7;
            cpa16(sb + 2 * TILE_B + SWZ128((uint32_t)(row * 128 + c * 16)),
                  Bh + (size_t)(bn + row) * K + k0 + c * 8);
        }
    };

    const int nch = K >> 6;   // BK = 64
    fill(0, 0); CP_COMMIT();

    for (int i = 0; i < nch; i++) {
        if (i + 1 < nch) { fill((i + 1) & 1, (i + 1) << 6); CP_COMMIT(); CP_WAIT(1); }
        else             { CP_WAIT(0); }
        __syncthreads();

        uint32_t sb = smb + (uint32_t)(i & 1) * STAGE_B;
        uint32_t Abh = sb, Abl = sb + TILE_B, Bbh = sb + 2 * TILE_B;

        #pragma unroll
        for (int kh = 0; kh < 4; kh++) {
            const uint32_t koff = (uint32_t)(kh * 32 + lh * 16);
            uint32_t ah[4][4], al[4][4];
            #pragma unroll
            for (int mt = 0; mt < 4; mt++) {
                uint32_t ro = SWZ128((uint32_t)((wm * 64 + mt * 16 + l16) * 128) + koff);
                ldsm4(Abh + ro, ah[mt]);
                if (TWO) ldsm4(Abl + ro, al[mt]);
            }
            uint32_t bh[2][4];
            #pragma unroll
            for (int np = 0; np < 2; np++) {
                uint32_t ro = SWZ128((uint32_t)((wn * 32 + np * 16 + l16) * 128) + koff);
                ldsm4(Bbh + ro, bh[np]);
            }
            // hi pass: fp32-acc
            #pragma unroll
            for (int mt = 0; mt < 4; mt++)
                #pragma unroll
                for (int nt = 0; nt < 4; nt++) {
                    const int np = nt >> 1, o = nt & 1;
                    mma16816(acc[mt][nt], ah[mt], bh[np][o], bh[np][o + 2]);
                }
            // lo pass: fp16-acc (lo plane pre-scaled x1024)
            if (TWO) {
                #pragma unroll
                for (int mt = 0; mt < 4; mt++)
                    #pragma unroll
                    for (int nt = 0; nt < 4; nt++) {
                        const int np = nt >> 1, o = nt & 1;
                        mma16816h(accl[mt][nt], al[mt], bh[np][o], bh[np][o + 2]);
                    }
            }
        }
        __syncthreads();
    }

    const int er = lane >> 2, ec = (lane & 3) * 2;
    #pragma unroll
    for (int mt = 0; mt < 4; mt++)
        #pragma unroll
        for (int nt = 0; nt < 4; nt++) {
            int r0 = bm + wm * 64 + mt * 16 + er;
            int c0 = bn + wn * 32 + nt * 8 + ec;
            float v[4];
            if (TWO) {
                __half2 p0 = *reinterpret_cast<__half2*>(&accl[mt][nt][0]);
                __half2 p1 = *reinterpret_cast<__half2*>(&accl[mt][nt][1]);
                v[0] = acc[mt][nt][0] + __half2float(p0.x) * INVLOSCALE;
                v[1] = acc[mt][nt][1] + __half2float(p0.y) * INVLOSCALE;
                v[2] = acc[mt][nt][2] + __half2float(p1.x) * INVLOSCALE;
                v[3] = acc[mt][nt][3] + __half2float(p1.y) * INVLOSCALE;
            } else {
                v[0] = acc[mt][nt][0]; v[1] = acc[mt][nt][1];
                v[2] = acc[mt][nt][2]; v[3] = acc[mt][nt][3];
            }
            if (MODE == 0) {
                *(float2*)&C[(size_t)r0 * N + c0]       = make_float2(v[0], v[1]);
                *(float2*)&C[(size_t)(r0 + 8) * N + c0] = make_float2(v[2], v[3]);
            } else if (MODE == 1) {
                // Q part: c0 in [0,1024)
                int bb = r0 >> 11, t = r0 & 2047;
                int hh = c0 >> 6, d = c0 & 63;
                size_t o = (((size_t)bb * NHEAD + hh) * TSEQ + t) * HDIM + d;
                #pragma unroll
                for (int rr = 0; rr < 2; rr++) {
                    float v0 = v[2 * rr + 0] * QSCALE;
                    float v1 = v[2 * rr + 1] * QSCALE;
                    size_t oo = o + (size_t)rr * 8 * HDIM;
                    __half h0 = __float2half(v0), h1 = __float2half(v1);
                    *(uint32_t*)&g_qkvh[oo] = packh2(h0, h1);
                    *(uint32_t*)&g_qkvl[oo] = packh2(
                        __float2half(v0 - __half2float(h0)),
                        __float2half(v1 - __half2float(h1)));
                }
            } else {
                // K/V part: c0 in [0,2048); part = 1 + (c0>>10)
                int bb = r0 >> 11, t = r0 & 2047;
                int part = 1 + (c0 >> 10), rem = c0 & 1023;
                int hh = rem >> 6, d = rem & 63;
                size_t o = ((((size_t)part * BATCH + bb) * NHEAD + hh) * TSEQ + t) * HDIM + d;
                #pragma unroll
                for (int rr = 0; rr < 2; rr++) {
                    size_t oo = o + (size_t)rr * 8 * HDIM;
                    *(uint32_t*)&g_qkvh[oo] =
                        packh2(__float2half(v[2 * rr]), __float2half(v[2 * rr + 1]));
                }
            }
        }
}

// ---------------------------------------------------------------------------
// Tensor-core flash attention (causal), Bq=128, Bk=64, D=64.
// S: 2-term (Qh+Ql)·K.  PV: 1-term Ph·V (P-lo dropped).
// ---------------------------------------------------------------------------
#define FL_SMEM (64 * 1024)

__global__ void __launch_bounds__(256, 2) flash_tc_kernel()
{
    extern __shared__ char smraw[];
    const uint32_t S = smem_u32(smraw);
    const int tid = threadIdx.x, w = tid >> 5, lane = tid & 31;
    const int l16 = lane & 15, lh = lane >> 4;
    const int b = blockIdx.z, h = blockIdx.y;
    const int qt = (int)(gridDim.x - 1 - blockIdx.x);   // heaviest first
    const int n_kt = 2 * qt + 2;

    const uint32_t Qh_s = S, Ql_s = S + 16384;
    const uint32_t stg0 = S + 32768;

    const size_t head = (((size_t)b) * NHEAD + h) * TSEQ * HDIM;
    const size_t HSZ  = (size_t)BATCH * NHEAD * TSEQ * HDIM;
    const __half* qh = g_qkvh + head;
    const __half* ql = g_qkvl + head;
    const __half* kh = g_qkvh + HSZ + head;
    const __half* vh = g_qkvh + 2 * HSZ + head;

    {
        #pragma unroll
        for (int i = 0; i < 8; i++) {
            int idx = tid + i * 256;
            int mtx = idx >> 10, row = (idx >> 3) & 127, c = idx & 7;
            const __half* src = (mtx ? ql : qh) + (size_t)(qt * 128 + row) * HDIM + c * 8;
            cpa16((mtx ? Ql_s : Qh_s) + SWZ128((uint32_t)(row * 128 + c * 16)), src);
        }
    }
    auto fillkv = [&](int s, int kt) {
        uint32_t sb = stg0 + (uint32_t)s * 16384u;
        const __half* bases[2] = {kh, vh};
        #pragma unroll
        for (int i = 0; i < 4; i++) {
            int idx = tid + i * 256;
            int mtx = idx >> 9, row = (idx >> 3) & 63, c = idx & 7;
            cpa16(sb + (uint32_t)mtx * 8192u + SWZ128((uint32_t)(row * 128 + c * 16)),
                  bases[mtx] + (size_t)(kt * 64 + row) * HDIM + c * 8);
        }
    };

    fillkv(0, 0); CP_COMMIT();
    if (n_kt > 1) { fillkv(1, 1); CP_COMMIT(); }

    float m0 = -1e30f, m1 = -1e30f, l0 = 0.f, l1 = 0.f;
    float o[8][4];
    #pragma unroll
    for (int j = 0; j < 8; j++)
        #pragma unroll
        for (int e = 0; e < 4; e++) o[j][e] = 0.f;

    for (int kt = 0; kt < n_kt; kt++) {
        if (kt + 1 < n_kt) { CP_WAIT(1); } else { CP_WAIT(0); }
        __syncthreads();

        const uint32_t sb   = stg0 + (uint32_t)(kt & 1) * 16384u;
        const uint32_t Kh_s = sb, Vh_s = sb + 8192;

        float s[8][4];
        #pragma unroll
        for (int j = 0; j < 8; j++)
            #pragma unroll
            for (int e = 0; e < 4; e++) s[j][e] = 0.f;

        #pragma unroll
        for (int kk = 0; kk < 4; kk++) {
            const uint32_t koff = (uint32_t)(kk * 32 + lh * 16);
            uint32_t qf[4], qlf[4];
            ldsm4(Qh_s + SWZ128((uint32_t)((w * 16 + l16) * 128) + koff), qf);
            ldsm4(Ql_s + SWZ128((uint32_t)((w * 16 + l16) * 128) + koff), qlf);
            #pragma unroll
            for (int gp = 0; gp < 2; gp++) {
                const int g0 = 2 * gp, g1 = 2 * gp + 1;
                uint32_t kf0[4], kf1[4];
                ldsm4(Kh_s + SWZ128((uint32_t)((g0 * 16 + l16) * 128) + koff), kf0);
                ldsm4(Kh_s + SWZ128((uint32_t)((g1 * 16 + l16) * 128) + koff), kf1);
                mma16816(s[2 * g0],     qf, kf0[0], kf0[2]);
                mma16816(s[2 * g0 + 1], qf, kf0[1], kf0[3]);
                mma16816(s[2 * g1],     qf, kf1[0], kf1[2]);
                mma16816(s[2 * g1 + 1], qf, kf1[1], kf1[3]);
                mma16816(s[2 * g0],     qlf, kf0[0], kf0[2]);
                mma16816(s[2 * g0 + 1], qlf, kf0[1], kf0[3]);
                mma16816(s[2 * g1],     qlf, kf1[0], kf1[2]);
                mma16816(s[2 * g1 + 1], qlf, kf1[1], kf1[3]);
            }
        }

        const int row0 = qt * 128 + w * 16 + (lane >> 2);
        if (kt * 64 + 63 > qt * 128 + w * 16) {
            #pragma unroll
            for (int j = 0; j < 8; j++) {
                int colb = kt * 64 + j * 8 + (lane & 3) * 2;
                if (colb + 0 > row0)     s[j][0] = -1e30f;
                if (colb + 1 > row0)     s[j][1] = -1e30f;
                if (colb + 0 > row0 + 8) s[j][2] = -1e30f;
                if (colb + 1 > row0 + 8) s[j][3] = -1e30f;
            }
        }

        float mx0 = -1e30f, mx1 = -1e30f;
        #pragma unroll
        for (int j = 0; j < 8; j++) {
            mx0 = fmaxf(mx0, fmaxf(s[j][0], s[j][1]));
            mx1 = fmaxf(mx1, fmaxf(s[j][2], s[j][3]));
        }
        mx0 = fmaxf(mx0, __shfl_xor_sync(0xffffffffu, mx0, 1));
        mx0 = fmaxf(mx0, __shfl_xor_sync(0xffffffffu, mx0, 2));
        mx1 = fmaxf(mx1, __shfl_xor_sync(0xffffffffu, mx1, 1));
        mx1 = fmaxf(mx1, __shfl_xor_sync(0xffffffffu, mx1, 2));
        float nm0 = fmaxf(m0, mx0), nm1 = fmaxf(m1, mx1);
        float c0 = exp2f(m0 - nm0), c1 = exp2f(m1 - nm1);
        m0 = nm0; m1 = nm1;
        float sum0 = 0.f, sum1 = 0.f;
        #pragma unroll
        for (int j = 0; j < 8; j++) {
            s[j][0] = exp2f(s[j][0] - m0);
            s[j][1] = exp2f(s[j][1] - m0);
            s[j][2] = exp2f(s[j][2] - m1);
            s[j][3] = exp2f(s[j][3] - m1);
            sum0 += s[j][0] + s[j][1];
            sum1 += s[j][2] + s[j][3];
        }
        sum0 += __shfl_xor_sync(0xffffffffu, sum0, 1);
        sum0 += __shfl_xor_sync(0xffffffffu, sum0, 2);
        sum1 += __shfl_xor_sync(0xffffffffu, sum1, 1);
        sum1 += __shfl_xor_sync(0xffffffffu, sum1, 2);
        l0 = l0 * c0 + sum0;
        l1 = l1 * c1 + sum1;
        #pragma unroll
        for (int j = 0; j < 8; j++) {
            o[j][0] *= c0; o[j][1] *= c0; o[j][2] *= c1; o[j][3] *= c1;
        }

        // ---- O += P V (1-term: Ph·Vh) ----
        #pragma unroll
        for (int kk = 0; kk < 4; kk++) {
            uint32_t pa[4];
            #pragma unroll
            for (int half = 0; half < 2; half++) {
                const int f = 2 * kk + half;
                pa[2 * half + 0] = packh2(__float2half(s[f][0]), __float2half(s[f][1]));
                pa[2 * half + 1] = packh2(__float2half(s[f][2]), __float2half(s[f][3]));
            }
            #pragma unroll
            for (int gp = 0; gp < 2; gp++) {
                const int g0 = 2 * gp, g1 = 2 * gp + 1;
                uint32_t vf0[4], vf1[4];
                uint32_t ro0 = SWZ128((uint32_t)((kk * 16 + l16) * 128 + g0 * 32) + (uint32_t)(lh * 16));
                uint32_t ro1 = SWZ128((uint32_t)((kk * 16 + l16) * 128 + g1 * 32) + (uint32_t)(lh * 16));
                ldsm4t(Vh_s + ro0, vf0);
                ldsm4t(Vh_s + ro1, vf1);
                mma16816(o[2 * g0],     pa, vf0[0], vf0[1]);
                mma16816(o[2 * g0 + 1], pa, vf0[2], vf0[3]);
                mma16816(o[2 * g1],     pa, vf1[0], vf1[1]);
                mma16816(o[2 * g1 + 1], pa, vf1[2], vf1[3]);
            }
        }

        __syncthreads();
        if (kt + 2 < n_kt) { fillkv(kt & 1, kt + 2); CP_COMMIT(); }
    }

    const float inv0 = 1.f / l0, inv1 = 1.f / l1;
    const int r0 = qt * 128 + w * 16 + (lane >> 2);
    const int t0 = r0, t1 = r0 + 8;
    #pragma unroll
    for (int j = 0; j < 8; j++) {
        int d = j * 8 + (lane & 3) * 2;
        size_t o0 = ((size_t)b * TSEQ + t0) * CDIM + h * HDIM + d;
        size_t o1 = ((size_t)b * TSEQ + t1) * CDIM + h * HDIM + d;
        float y0 = o[j][0] * inv0, y1 = o[j][1] * inv0;
        float y2 = o[j][2] * inv1, y3 = o[j][3] * inv1;
        __half h0 = __float2half(y0), h1 = __float2half(y1);
        __half h2 = __float2half(y2), h3 = __float2half(y3);
        *(uint32_t*)&g_yh[o0] = packh2(h0, h1);
        *(uint32_t*)&g_yh[o1] = packh2(h2, h3);
        *(uint32_t*)&g_yl[o0] = packh2(                          // scaled x1024
            __float2half((y0 - __half2float(h0)) * LOSCALE),
            __float2half((y1 - __half2float(h1)) * LOSCALE));
        *(uint32_t*)&g_yl[o1] = packh2(
            __float2half((y2 - __half2float(h2)) * LOSCALE),
            __float2half((y3 - __half2float(h3)) * LOSCALE));
    }
}

// ---------------------------------------------------------------------------
extern "C" void kernel_launch(void* const* d_in, const int* in_sizes, int n_in,
                              void* d_out, int out_size)
{
    const float* x      = (const float*)d_in[0];
    const float* w_qkv  = (const float*)d_in[1];
    const float* w_proj = (const float*)d_in[2];
    float* out = (float*)d_out;

    __half *xh, *xl, *yh, *yl, *wq, *wp;
    cudaGetSymbolAddress((void**)&xh, g_xh);
    cudaGetSymbolAddress((void**)&xl, g_xl);
    cudaGetSymbolAddress((void**)&yh, g_yh);
    cudaGetSymbolAddress((void**)&yl, g_yl);
    cudaGetSymbolAddress((void**)&wq, g_wq);
    cudaGetSymbolAddress((void**)&wp, g_wp);

    cudaFuncSetAttribute(mmasync_kernel<0>, cudaFuncAttributeMaxDynamicSharedMemorySize, MM_SMEM);
    cudaFuncSetAttribute(mmasync_kernel<1>, cudaFuncAttributeMaxDynamicSharedMemorySize, MM_SMEM);
    cudaFuncSetAttribute(mmasync_kernel<2>, cudaFuncAttributeMaxDynamicSharedMemorySize, MM_SMEM);
    cudaFuncSetAttribute(flash_tc_kernel,   cudaFuncAttributeMaxDynamicSharedMemorySize, FL_SMEM);
    cudaFuncSetAttribute(mmasync_kernel<0>, cudaFuncAttributePreferredSharedMemoryCarveout, 100);
    cudaFuncSetAttribute(mmasync_kernel<1>, cudaFuncAttributePreferredSharedMemoryCarveout, 100);
    cudaFuncSetAttribute(mmasync_kernel<2>, cudaFuncAttributePreferredSharedMemoryCarveout, 100);
    cudaFuncSetAttribute(flash_tc_kernel,   cudaFuncAttributePreferredSharedMemoryCarveout, 100);

    const int n4 = MTOT * CDIM / 4;

    split_kernel<<<(n4 + 255) / 256, 256>>>(x, xh, xl, n4);

    {
        dim3 g1(C3 / 32, CDIM / 32), blk(32, 8);
        tsplit_kernel<<<g1, blk>>>(w_qkv, wq, CDIM, C3);
        dim3 g2(CDIM / 32, CDIM / 32);
        tsplit_kernel<<<g2, blk>>>(w_proj, wp, CDIM, CDIM);
    }

    // Q-GEMM: N=1024, 2-term
    {
        dim3 grid(CDIM / 128, MTOT / 128);
        mmasync_kernel<1><<<grid, 256, MM_SMEM>>>(xh, xl, wq, nullptr, CDIM, CDIM);
    }
    // KV-GEMM: N=2048, 1-term (B = wq rows 1024..3071)
    {
        dim3 grid((2 * CDIM) / 128, MTOT / 128);
        mmasync_kernel<2><<<grid, 256, MM_SMEM>>>(xh, xl, wq + (size_t)CDIM * CDIM,
                                                  nullptr, 2 * CDIM, CDIM);
    }

    {
        dim3 grid(TSEQ / 128, NHEAD, BATCH);
        flash_tc_kernel<<<grid, 256, FL_SMEM>>>();
    }

    {
        dim3 grid(CDIM / 128, MTOT / 128);
        mmasync_kernel<0><<<grid, 256, MM_SMEM>>>(yh, yl, wp, out, CDIM, CDIM);
    }
    (void)in_sizes; (void)n_in; (void)out_size;
}

// round 11
// speedup vs baseline: 1.2521x; 1.0031x over previous
#include <cuda_runtime.h>
#include <cuda_fp16.h>
#include <cstdint>

// Problem constants
#define BATCH 4
#define TSEQ  2048
#define CDIM  1024
#define NHEAD 16
#define HDIM  64
#define C3    (3*CDIM)
#define MTOT  (BATCH*TSEQ)   // 8192

#define QSCALE 0.18033688011112042f   // 0.125 * log2(e)

// ---------------------------------------------------------------------------
// Device-global scratch (no allocation allowed)
// ---------------------------------------------------------------------------
__device__ __align__(256) __half g_qkvh[(size_t)3 * BATCH * NHEAD * TSEQ * HDIM];
__device__ __align__(256) __half g_qkvl[(size_t)3 * BATCH * NHEAD * TSEQ * HDIM]; // Q-lo
__device__ __align__(256) __half g_yh[(size_t)MTOT * CDIM];
__device__ __align__(256) __half g_yl[(size_t)MTOT * CDIM];
__device__ __align__(256) __half g_xh[(size_t)MTOT * CDIM];
__device__ __align__(256) __half g_xl[(size_t)MTOT * CDIM];
__device__ __align__(256) __half g_wq[(size_t)C3 * CDIM];     // transposed N x K
__device__ __align__(256) __half g_wp[(size_t)CDIM * CDIM];   // transposed N x K

// ---------------------------------------------------------------------------
// Helpers (baseline PTX only)
// ---------------------------------------------------------------------------
__device__ __forceinline__ uint32_t smem_u32(const void* p) {
    uint32_t a;
    asm("{ .reg .u64 t; cvta.to.shared.u64 t, %1; cvt.u32.u64 %0, t; }" : "=r"(a) : "l"(p));
    return a;
}
__device__ __forceinline__ void cpa16(uint32_t dst, const void* src) {
    asm volatile("cp.async.cg.shared.global [%0], [%1], 16;\n" :: "r"(dst), "l"(src));
}
#define CP_COMMIT() asm volatile("cp.async.commit_group;\n" ::: "memory")
#define CP_WAIT(n)  asm volatile("cp.async.wait_group %0;\n" :: "n"(n) : "memory")
#define SWZ128(o) ((o) ^ (((o) >> 3) & 0x70))

__device__ __forceinline__ void ldsm4(uint32_t addr, uint32_t* r) {
    asm volatile("ldmatrix.sync.aligned.m8n8.x4.shared.b16 {%0,%1,%2,%3}, [%4];"
                 : "=r"(r[0]), "=r"(r[1]), "=r"(r[2]), "=r"(r[3]) : "r"(addr));
}
__device__ __forceinline__ void ldsm4t(uint32_t addr, uint32_t* r) {
    asm volatile("ldmatrix.sync.aligned.m8n8.x4.trans.shared.b16 {%0,%1,%2,%3}, [%4];"
                 : "=r"(r[0]), "=r"(r[1]), "=r"(r[2]), "=r"(r[3]) : "r"(addr));
}
__device__ __forceinline__ void mma16816(float* d, const uint32_t* a, uint32_t b0, uint32_t b1) {
    asm volatile("mma.sync.aligned.m16n8k16.row.col.f32.f16.f16.f32 "
                 "{%0,%1,%2,%3},{%4,%5,%6,%7},{%8,%9},{%0,%1,%2,%3};"
                 : "+f"(d[0]), "+f"(d[1]), "+f"(d[2]), "+f"(d[3])
                 : "r"(a[0]), "r"(a[1]), "r"(a[2]), "r"(a[3]), "r"(b0), "r"(b1));
}
__device__ __forceinline__ uint32_t packh2(__half a, __half b) {
    __half2 t; t.x = a; t.y = b;
    return *reinterpret_cast<uint32_t*>(&t);
}

// ---------------------------------------------------------------------------
// Split fp32 -> fp16 hi/lo (unscaled)
// ---------------------------------------------------------------------------
__global__ void __launch_bounds__(256) split_kernel(
    const float* __restrict__ in, __half* __restrict__ hi,
    __half* __restrict__ lo, int n4)
{
    int i = blockIdx.x * 256 + threadIdx.x;
    if (i >= n4) return;
    float4 v = ((const float4*)in)[i];
    float vv[4] = {v.x, v.y, v.z, v.w};
    __half h[4], l[4];
    #pragma unroll
    for (int j = 0; j < 4; j++) {
        h[j] = __float2half(vv[j]);
        l[j] = __float2half(vv[j] - __half2float(h[j]));
    }
    ((uint32_t*)hi)[2*i]   = packh2(h[0], h[1]);
    ((uint32_t*)hi)[2*i+1] = packh2(h[2], h[3]);
    ((uint32_t*)lo)[2*i]   = packh2(l[0], l[1]);
    ((uint32_t*)lo)[2*i+1] = packh2(l[2], l[3]);
}

// ---------------------------------------------------------------------------
// Transpose weights: W (KxN fp32, row-major) -> Wt (NxK fp16)
// ---------------------------------------------------------------------------
__global__ void __launch_bounds__(256) tsplit_kernel(
    const float* __restrict__ W, __half* __restrict__ Th, int K, int N)
{
    __shared__ float t[32][33];
    int n0 = blockIdx.x * 32, k0 = blockIdx.y * 32;
    int tx = threadIdx.x, ty = threadIdx.y;
    #pragma unroll
    for (int i = 0; i < 32; i += 8)
        t[ty + i][tx] = W[(size_t)(k0 + ty + i) * N + n0 + tx];
    __syncthreads();
    #pragma unroll
    for (int i = 0; i < 32; i += 8)
        Th[(size_t)(n0 + ty + i) * K + k0 + tx] = __float2half(t[tx][ty + i]);
}

// ---------------------------------------------------------------------------
// mma.sync GEMM, tile 128x128, BK=64 (SW128), double buffer, 2 CTAs/SM.
// hi and lo passes both accumulate into the SAME fp32 acc (64 regs).
// MODE 0: proj, 2-term, fp32 C out.
// MODE 1: Q-GEMM (N=1024), 2-term, epilogue scale+split to g_qkvh/g_qkvl.
// MODE 2: KV-GEMM (N=2048), 1-term, epilogue hi only.
// ---------------------------------------------------------------------------
#define TILE_B     (128 * 128)           // 16384 B
#define STAGE_B    (3 * TILE_B)          // 49152 B
#define MM_SMEM    (2 * STAGE_B)         // 98304 B

template<int MODE>
__global__ void __launch_bounds__(256, 2) mmasync_kernel(
    const __half* __restrict__ Ah, const __half* __restrict__ Al,
    const __half* __restrict__ Bh,
    float* __restrict__ C, int N, int K)
{
    constexpr bool TWO = (MODE != 2);   // 2-term (hi+lo) vs 1-term
    extern __shared__ char smraw[];
    const uint32_t smb = smem_u32(smraw);

    const int tid  = threadIdx.x;
    const int wid  = tid >> 5, lane = tid & 31;
    const int wm   = wid & 1;
    const int wn   = wid >> 1;
    const int bm   = blockIdx.y * 128, bn = blockIdx.x * 128;
    const int l16  = lane & 15, lh = lane >> 4;

    float acc[4][4][4];
    #pragma unroll
    for (int i = 0; i < 4; i++)
        #pragma unroll
        for (int j = 0; j < 4; j++)
            #pragma unroll
            for (int k = 0; k < 4; k++) acc[i][j][k] = 0.f;

    auto fill = [&](int s, int k0) {
        uint32_t sb = smb + (uint32_t)s * STAGE_B;
        #pragma unroll
        for (int i = 0; i < 4; i++) {
            int chunk = tid + i * 256;
            int row = chunk >> 3, c = chunk & 7;
            cpa16(sb + SWZ128((uint32_t)(row * 128 + c * 16)),
                  Ah + (size_t)(bm + row) * K + k0 + c * 8);
        }
        if (TWO) {
            #pragma unroll
            for (int i = 0; i < 4; i++) {
                int chunk = tid + i * 256;
                int row = chunk >> 3, c = chunk & 7;
                cpa16(sb + TILE_B + SWZ128((uint32_t)(row * 128 + c * 16)),
                      Al + (size_t)(bm + row) * K + k0 + c * 8);
            }
        }
        #pragma unroll
        for (int i = 0; i < 4; i++) {
            int chunk = tid + i * 256;
            int row = chunk >> 3, c = chunk & 7;
            cpa16(sb + 2 * TILE_B + SWZ128((uint32_t)(row * 128 + c * 16)),
                  Bh + (size_t)(bn + row) * K + k0 + c * 8);
        }
    };

    const int nch = K >> 6;   // BK = 64
    fill(0, 0); CP_COMMIT();

    for (int i = 0; i < nch; i++) {
        if (i + 1 < nch) { fill((i + 1) & 1, (i + 1) << 6); CP_COMMIT(); CP_WAIT(1); }
        else             { CP_WAIT(0); }
        __syncthreads();

        uint32_t sb = smb + (uint32_t)(i & 1) * STAGE_B;
        uint32_t Abh = sb, Abl = sb + TILE_B, Bbh = sb + 2 * TILE_B;

        #pragma unroll
        for (int kh = 0; kh < 4; kh++) {
            const uint32_t koff = (uint32_t)(kh * 32 + lh * 16);
            uint32_t ah[4][4], al[4][4];
            #pragma unroll
            for (int mt = 0; mt < 4; mt++) {
                uint32_t ro = SWZ128((uint32_t)((wm * 64 + mt * 16 + l16) * 128) + koff);
                ldsm4(Abh + ro, ah[mt]);
                if (TWO) ldsm4(Abl + ro, al[mt]);
            }
            uint32_t bh[2][4];
            #pragma unroll
            for (int np = 0; np < 2; np++) {
                uint32_t ro = SWZ128((uint32_t)((wn * 32 + np * 16 + l16) * 128) + koff);
                ldsm4(Bbh + ro, bh[np]);
            }
            // hi pass
            #pragma unroll
            for (int mt = 0; mt < 4; mt++)
                #pragma unroll
                for (int nt = 0; nt < 4; nt++) {
                    const int np = nt >> 1, o = nt & 1;
                    mma16816(acc[mt][nt], ah[mt], bh[np][o], bh[np][o + 2]);
                }
            // lo pass (same fp32 accumulators)
            if (TWO) {
                #pragma unroll
                for (int mt = 0; mt < 4; mt++)
                    #pragma unroll
                    for (int nt = 0; nt < 4; nt++) {
                        const int np = nt >> 1, o = nt & 1;
                        mma16816(acc[mt][nt], al[mt], bh[np][o], bh[np][o + 2]);
                    }
            }
        }
        __syncthreads();
    }

    const int er = lane >> 2, ec = (lane & 3) * 2;
    #pragma unroll
    for (int mt = 0; mt < 4; mt++)
        #pragma unroll
        for (int nt = 0; nt < 4; nt++) {
            int r0 = bm + wm * 64 + mt * 16 + er;
            int c0 = bn + wn * 32 + nt * 8 + ec;
            float* v = acc[mt][nt];
            if (MODE == 0) {
                *(float2*)&C[(size_t)r0 * N + c0]       = make_float2(v[0], v[1]);
                *(float2*)&C[(size_t)(r0 + 8) * N + c0] = make_float2(v[2], v[3]);
            } else if (MODE == 1) {
                int bb = r0 >> 11, t = r0 & 2047;
                int hh = c0 >> 6, d = c0 & 63;
                size_t o = (((size_t)bb * NHEAD + hh) * TSEQ + t) * HDIM + d;
                #pragma unroll
                for (int rr = 0; rr < 2; rr++) {
                    float v0 = v[2 * rr + 0] * QSCALE;
                    float v1 = v[2 * rr + 1] * QSCALE;
                    size_t oo = o + (size_t)rr * 8 * HDIM;
                    __half h0 = __float2half(v0), h1 = __float2half(v1);
                    *(uint32_t*)&g_qkvh[oo] = packh2(h0, h1);
                    *(uint32_t*)&g_qkvl[oo] = packh2(
                        __float2half(v0 - __half2float(h0)),
                        __float2half(v1 - __half2float(h1)));
                }
            } else {
                int bb = r0 >> 11, t = r0 & 2047;
                int part = 1 + (c0 >> 10), rem = c0 & 1023;
                int hh = rem >> 6, d = rem & 63;
                size_t o = ((((size_t)part * BATCH + bb) * NHEAD + hh) * TSEQ + t) * HDIM + d;
                #pragma unroll
                for (int rr = 0; rr < 2; rr++) {
                    size_t oo = o + (size_t)rr * 8 * HDIM;
                    *(uint32_t*)&g_qkvh[oo] =
                        packh2(__float2half(v[2 * rr]), __float2half(v[2 * rr + 1]));
                }
            }
        }
}

// ---------------------------------------------------------------------------
// Tensor-core flash attention (causal), Bq=128, Bk=64, D=64.
// S: 2-term (Qh+Ql)·K.  PV: 1-term Ph·V.
// ---------------------------------------------------------------------------
#define FL_SMEM (64 * 1024)

__global__ void __launch_bounds__(256, 2) flash_tc_kernel()
{
    extern __shared__ char smraw[];
    const uint32_t S = smem_u32(smraw);
    const int tid = threadIdx.x, w = tid >> 5, lane = tid & 31;
    const int l16 = lane & 15, lh = lane >> 4;
    const int b = blockIdx.z, h = blockIdx.y;
    const int qt = (int)(gridDim.x - 1 - blockIdx.x);   // heaviest first
    const int n_kt = 2 * qt + 2;

    const uint32_t Qh_s = S, Ql_s = S + 16384;
    const uint32_t stg0 = S + 32768;

    const size_t head = (((size_t)b) * NHEAD + h) * TSEQ * HDIM;
    const size_t HSZ  = (size_t)BATCH * NHEAD * TSEQ * HDIM;
    const __half* qh = g_qkvh + head;
    const __half* ql = g_qkvl + head;
    const __half* kh = g_qkvh + HSZ + head;
    const __half* vh = g_qkvh + 2 * HSZ + head;

    {
        #pragma unroll
        for (int i = 0; i < 8; i++) {
            int idx = tid + i * 256;
            int mtx = idx >> 10, row = (idx >> 3) & 127, c = idx & 7;
            const __half* src = (mtx ? ql : qh) + (size_t)(qt * 128 + row) * HDIM + c * 8;
            cpa16((mtx ? Ql_s : Qh_s) + SWZ128((uint32_t)(row * 128 + c * 16)), src);
        }
    }
    auto fillkv = [&](int s, int kt) {
        uint32_t sb = stg0 + (uint32_t)s * 16384u;
        const __half* bases[2] = {kh, vh};
        #pragma unroll
        for (int i = 0; i < 4; i++) {
            int idx = tid + i * 256;
            int mtx = idx >> 9, row = (idx >> 3) & 63, c = idx & 7;
            cpa16(sb + (uint32_t)mtx * 8192u + SWZ128((uint32_t)(row * 128 + c * 16)),
                  bases[mtx] + (size_t)(kt * 64 + row) * HDIM + c * 8);
        }
    };

    fillkv(0, 0); CP_COMMIT();
    if (n_kt > 1) { fillkv(1, 1); CP_COMMIT(); }

    float m0 = -1e30f, m1 = -1e30f, l0 = 0.f, l1 = 0.f;
    float o[8][4];
    #pragma unroll
    for (int j = 0; j < 8; j++)
        #pragma unroll
        for (int e = 0; e < 4; e++) o[j][e] = 0.f;

    for (int kt = 0; kt < n_kt; kt++) {
        if (kt + 1 < n_kt) { CP_WAIT(1); } else { CP_WAIT(0); }
        __syncthreads();

        const uint32_t sb   = stg0 + (uint32_t)(kt & 1) * 16384u;
        const uint32_t Kh_s = sb, Vh_s = sb + 8192;

        float s[8][4];
        #pragma unroll
        for (int j = 0; j < 8; j++)
            #pragma unroll
            for (int e = 0; e < 4; e++) s[j][e] = 0.f;

        #pragma unroll
        for (int kk = 0; kk < 4; kk++) {
            const uint32_t koff = (uint32_t)(kk * 32 + lh * 16);
            uint32_t qf[4], qlf[4];
            ldsm4(Qh_s + SWZ128((uint32_t)((w * 16 + l16) * 128) + koff), qf);
            ldsm4(Ql_s + SWZ128((uint32_t)((w * 16 + l16) * 128) + koff), qlf);
            #pragma unroll
            for (int gp = 0; gp < 2; gp++) {
                const int g0 = 2 * gp, g1 = 2 * gp + 1;
                uint32_t kf0[4], kf1[4];
                ldsm4(Kh_s + SWZ128((uint32_t)((g0 * 16 + l16) * 128) + koff), kf0);
                ldsm4(Kh_s + SWZ128((uint32_t)((g1 * 16 + l16) * 128) + koff), kf1);
                mma16816(s[2 * g0],     qf, kf0[0], kf0[2]);
                mma16816(s[2 * g0 + 1], qf, kf0[1], kf0[3]);
                mma16816(s[2 * g1],     qf, kf1[0], kf1[2]);
                mma16816(s[2 * g1 + 1], qf, kf1[1], kf1[3]);
                mma16816(s[2 * g0],     qlf, kf0[0], kf0[2]);
                mma16816(s[2 * g0 + 1], qlf, kf0[1], kf0[3]);
                mma16816(s[2 * g1],     qlf, kf1[0], kf1[2]);
                mma16816(s[2 * g1 + 1], qlf, kf1[1], kf1[3]);
            }
        }

        const int row0 = qt * 128 + w * 16 + (lane >> 2);
        if (kt * 64 + 63 > qt * 128 + w * 16) {
            #pragma unroll
            for (int j = 0; j < 8; j++) {
                int colb = kt * 64 + j * 8 + (lane & 3) * 2;
                if (colb + 0 > row0)     s[j][0] = -1e30f;
                if (colb + 1 > row0)     s[j][1] = -1e30f;
                if (colb + 0 > row0 + 8) s[j][2] = -1e30f;
                if (colb + 1 > row0 + 8) s[j][3] = -1e30f;
            }
        }

        float mx0 = -1e30f, mx1 = -1e30f;
        #pragma unroll
        for (int j = 0; j < 8; j++) {
            mx0 = fmaxf(mx0, fmaxf(s[j][0], s[j][1]));
            mx1 = fmaxf(mx1, fmaxf(s[j][2], s[j][3]));
        }
        mx0 = fmaxf(mx0, __shfl_xor_sync(0xffffffffu, mx0, 1));
        mx0 = fmaxf(mx0, __shfl_xor_sync(0xffffffffu, mx0, 2));
        mx1 = fmaxf(mx1, __shfl_xor_sync(0xffffffffu, mx1, 1));
        mx1 = fmaxf(mx1, __shfl_xor_sync(0xffffffffu, mx1, 2));
        float nm0 = fmaxf(m0, mx0), nm1 = fmaxf(m1, mx1);
        float c0 = exp2f(m0 - nm0), c1 = exp2f(m1 - nm1);
        m0 = nm0; m1 = nm1;
        float sum0 = 0.f, sum1 = 0.f;
        #pragma unroll
        for (int j = 0; j < 8; j++) {
            s[j][0] = exp2f(s[j][0] - m0);
            s[j][1] = exp2f(s[j][1] - m0);
            s[j][2] = exp2f(s[j][2] - m1);
            s[j][3] = exp2f(s[j][3] - m1);
            sum0 += s[j][0] + s[j][1];
            sum1 += s[j][2] + s[j][3];
        }
        sum0 += __shfl_xor_sync(0xffffffffu, sum0, 1);
        sum0 += __shfl_xor_sync(0xffffffffu, sum0, 2);
        sum1 += __shfl_xor_sync(0xffffffffu, sum1, 1);
        sum1 += __shfl_xor_sync(0xffffffffu, sum1, 2);
        l0 = l0 * c0 + sum0;
        l1 = l1 * c1 + sum1;
        #pragma unroll
        for (int j = 0; j < 8; j++) {
            o[j][0] *= c0; o[j][1] *= c0; o[j][2] *= c1; o[j][3] *= c1;
        }

        // ---- O += P V (1-term) ----
        #pragma unroll
        for (int kk = 0; kk < 4; kk++) {
            uint32_t pa[4];
            #pragma unroll
            for (int half = 0; half < 2; half++) {
                const int f = 2 * kk + half;
                pa[2 * half + 0] = packh2(__float2half(s[f][0]), __float2half(s[f][1]));
                pa[2 * half + 1] = packh2(__float2half(s[f][2]), __float2half(s[f][3]));
            }
            #pragma unroll
            for (int gp = 0; gp < 2; gp++) {
                const int g0 = 2 * gp, g1 = 2 * gp + 1;
                uint32_t vf0[4], vf1[4];
                uint32_t ro0 = SWZ128((uint32_t)((kk * 16 + l16) * 128 + g0 * 32) + (uint32_t)(lh * 16));
                uint32_t ro1 = SWZ128((uint32_t)((kk * 16 + l16) * 128 + g1 * 32) + (uint32_t)(lh * 16));
                ldsm4t(Vh_s + ro0, vf0);
                ldsm4t(Vh_s + ro1, vf1);
                mma16816(o[2 * g0],     pa, vf0[0], vf0[1]);
                mma16816(o[2 * g0 + 1], pa, vf0[2], vf0[3]);
                mma16816(o[2 * g1],     pa, vf1[0], vf1[1]);
                mma16816(o[2 * g1 + 1], pa, vf1[2], vf1[3]);
            }
        }

        __syncthreads();
        if (kt + 2 < n_kt) { fillkv(kt & 1, kt + 2); CP_COMMIT(); }
    }

    const float inv0 = 1.f / l0, inv1 = 1.f / l1;
    const int r0 = qt * 128 + w * 16 + (lane >> 2);
    const int t0 = r0, t1 = r0 + 8;
    #pragma unroll
    for (int j = 0; j < 8; j++) {
        int d = j * 8 + (lane & 3) * 2;
        size_t o0 = ((size_t)b * TSEQ + t0) * CDIM + h * HDIM + d;
        size_t o1 = ((size_t)b * TSEQ + t1) * CDIM + h * HDIM + d;
        float y0 = o[j][0] * inv0, y1 = o[j][1] * inv0;
        float y2 = o[j][2] * inv1, y3 = o[j][3] * inv1;
        __half h0 = __float2half(y0), h1 = __float2half(y1);
        __half h2 = __float2half(y2), h3 = __float2half(y3);
        *(uint32_t*)&g_yh[o0] = packh2(h0, h1);
        *(uint32_t*)&g_yh[o1] = packh2(h2, h3);
        *(uint32_t*)&g_yl[o0] = packh2(
            __float2half(y0 - __half2float(h0)),
            __float2half(y1 - __half2float(h1)));
        *(uint32_t*)&g_yl[o1] = packh2(
            __float2half(y2 - __half2float(h2)),
            __float2half(y3 - __half2float(h3)));
    }
}

// ---------------------------------------------------------------------------
extern "C" void kernel_launch(void* const* d_in, const int* in_sizes, int n_in,
                              void* d_out, int out_size)
{
    const float* x      = (const float*)d_in[0];
    const float* w_qkv  = (const float*)d_in[1];
    const float* w_proj = (const float*)d_in[2];
    float* out = (float*)d_out;

    __half *xh, *xl, *yh, *yl, *wq, *wp;
    cudaGetSymbolAddress((void**)&xh, g_xh);
    cudaGetSymbolAddress((void**)&xl, g_xl);
    cudaGetSymbolAddress((void**)&yh, g_yh);
    cudaGetSymbolAddress((void**)&yl, g_yl);
    cudaGetSymbolAddress((void**)&wq, g_wq);
    cudaGetSymbolAddress((void**)&wp, g_wp);

    cudaFuncSetAttribute(mmasync_kernel<0>, cudaFuncAttributeMaxDynamicSharedMemorySize, MM_SMEM);
    cudaFuncSetAttribute(mmasync_kernel<1>, cudaFuncAttributeMaxDynamicSharedMemorySize, MM_SMEM);
    cudaFuncSetAttribute(mmasync_kernel<2>, cudaFuncAttributeMaxDynamicSharedMemorySize, MM_SMEM);
    cudaFuncSetAttribute(flash_tc_kernel,   cudaFuncAttributeMaxDynamicSharedMemorySize, FL_SMEM);
    cudaFuncSetAttribute(mmasync_kernel<0>, cudaFuncAttributePreferredSharedMemoryCarveout, 100);
    cudaFuncSetAttribute(mmasync_kernel<1>, cudaFuncAttributePreferredSharedMemoryCarveout, 100);
    cudaFuncSetAttribute(mmasync_kernel<2>, cudaFuncAttributePreferredSharedMemoryCarveout, 100);
    cudaFuncSetAttribute(flash_tc_kernel,   cudaFuncAttributePreferredSharedMemoryCarveout, 100);

    const int n4 = MTOT * CDIM / 4;

    split_kernel<<<(n4 + 255) / 256, 256>>>(x, xh, xl, n4);

    {
        dim3 g1(C3 / 32, CDIM / 32), blk(32, 8);
        tsplit_kernel<<<g1, blk>>>(w_qkv, wq, CDIM, C3);
        dim3 g2(CDIM / 32, CDIM / 32);
        tsplit_kernel<<<g2, blk>>>(w_proj, wp, CDIM, CDIM);
    }

    // Q-GEMM: N=1024, 2-term
    {
        dim3 grid(CDIM / 128, MTOT / 128);
        mmasync_kernel<1><<<grid, 256, MM_SMEM>>>(xh, xl, wq, nullptr, CDIM, CDIM);
    }
    // KV-GEMM: N=2048, 1-term (B = wq rows 1024..3071)
    {
        dim3 grid((2 * CDIM) / 128, MTOT / 128);
        mmasync_kernel<2><<<grid, 256, MM_SMEM>>>(xh, xl, wq + (size_t)CDIM * CDIM,
                                                  nullptr, 2 * CDIM, CDIM);
    }

    {
        dim3 grid(TSEQ / 128, NHEAD, BATCH);
        flash_tc_kernel<<<grid, 256, FL_SMEM>>>();
    }

    {
        dim3 grid(CDIM / 128, MTOT / 128);
        mmasync_kernel<0><<<grid, 256, MM_SMEM>>>(yh, yl, wp, out, CDIM, CDIM);
    }
    (void)in_sizes; (void)n_in; (void)out_size;
}

// round 12
// speedup vs baseline: 1.4384x; 1.1488x over previous
#include <cuda_runtime.h>
#include <cuda_fp16.h>
#include <cstdint>

// Problem constants
#define BATCH 4
#define TSEQ  2048
#define CDIM  1024
#define NHEAD 16
#define HDIM  64
#define C3    (3*CDIM)
#define MTOT  (BATCH*TSEQ)   // 8192

#define QSCALE 0.18033688011112042f   // 0.125 * log2(e)

// ---------------------------------------------------------------------------
// Device-global scratch (no allocation allowed)
// ---------------------------------------------------------------------------
__device__ __align__(256) __half g_qkvh[(size_t)3 * BATCH * NHEAD * TSEQ * HDIM];
__device__ __align__(256) __half g_qkvl[(size_t)3 * BATCH * NHEAD * TSEQ * HDIM]; // Q-lo
__device__ __align__(256) __half g_yh[(size_t)MTOT * CDIM];
__device__ __align__(256) __half g_xh[(size_t)MTOT * CDIM];
__device__ __align__(256) __half g_xl[(size_t)MTOT * CDIM];
__device__ __align__(256) __half g_wq[(size_t)C3 * CDIM];     // transposed N x K
__device__ __align__(256) __half g_wp[(size_t)CDIM * CDIM];   // transposed N x K

// ---------------------------------------------------------------------------
// Helpers (baseline PTX only)
// ---------------------------------------------------------------------------
__device__ __forceinline__ uint32_t smem_u32(const void* p) {
    uint32_t a;
    asm("{ .reg .u64 t; cvta.to.shared.u64 t, %1; cvt.u32.u64 %0, t; }" : "=r"(a) : "l"(p));
    return a;
}
__device__ __forceinline__ void cpa16(uint32_t dst, const void* src) {
    asm volatile("cp.async.cg.shared.global [%0], [%1], 16;\n" :: "r"(dst), "l"(src));
}
#define CP_COMMIT() asm volatile("cp.async.commit_group;\n" ::: "memory")
#define CP_WAIT(n)  asm volatile("cp.async.wait_group %0;\n" :: "n"(n) : "memory")
#define SWZ128(o) ((o) ^ (((o) >> 3) & 0x70))

__device__ __forceinline__ void ldsm4(uint32_t addr, uint32_t* r) {
    asm volatile("ldmatrix.sync.aligned.m8n8.x4.shared.b16 {%0,%1,%2,%3}, [%4];"
                 : "=r"(r[0]), "=r"(r[1]), "=r"(r[2]), "=r"(r[3]) : "r"(addr));
}
__device__ __forceinline__ void ldsm4t(uint32_t addr, uint32_t* r) {
    asm volatile("ldmatrix.sync.aligned.m8n8.x4.trans.shared.b16 {%0,%1,%2,%3}, [%4];"
                 : "=r"(r[0]), "=r"(r[1]), "=r"(r[2]), "=r"(r[3]) : "r"(addr));
}
__device__ __forceinline__ void mma16816(float* d, const uint32_t* a, uint32_t b0, uint32_t b1) {
    asm volatile("mma.sync.aligned.m16n8k16.row.col.f32.f16.f16.f32 "
                 "{%0,%1,%2,%3},{%4,%5,%6,%7},{%8,%9},{%0,%1,%2,%3};"
                 : "+f"(d[0]), "+f"(d[1]), "+f"(d[2]), "+f"(d[3])
                 : "r"(a[0]), "r"(a[1]), "r"(a[2]), "r"(a[3]), "r"(b0), "r"(b1));
}
__device__ __forceinline__ uint32_t packh2(__half a, __half b) {
    __half2 t; t.x = a; t.y = b;
    return *reinterpret_cast<uint32_t*>(&t);
}

// ---------------------------------------------------------------------------
// Split fp32 -> fp16 hi/lo
// ---------------------------------------------------------------------------
__global__ void __launch_bounds__(256) split_kernel(
    const float* __restrict__ in, __half* __restrict__ hi,
    __half* __restrict__ lo, int n4)
{
    int i = blockIdx.x * 256 + threadIdx.x;
    if (i >= n4) return;
    float4 v = ((const float4*)in)[i];
    float vv[4] = {v.x, v.y, v.z, v.w};
    __half h[4], l[4];
    #pragma unroll
    for (int j = 0; j < 4; j++) {
        h[j] = __float2half(vv[j]);
        l[j] = __float2half(vv[j] - __half2float(h[j]));
    }
    ((uint32_t*)hi)[2*i]   = packh2(h[0], h[1]);
    ((uint32_t*)hi)[2*i+1] = packh2(h[2], h[3]);
    ((uint32_t*)lo)[2*i]   = packh2(l[0], l[1]);
    ((uint32_t*)lo)[2*i+1] = packh2(l[2], l[3]);
}

// ---------------------------------------------------------------------------
// Transpose weights: W (KxN fp32, row-major) -> Wt (NxK fp16)
// ---------------------------------------------------------------------------
__global__ void __launch_bounds__(256) tsplit_kernel(
    const float* __restrict__ W, __half* __restrict__ Th, int K, int N)
{
    __shared__ float t[32][33];
    int n0 = blockIdx.x * 32, k0 = blockIdx.y * 32;
    int tx = threadIdx.x, ty = threadIdx.y;
    #pragma unroll
    for (int i = 0; i < 32; i += 8)
        t[ty + i][tx] = W[(size_t)(k0 + ty + i) * N + n0 + tx];
    __syncthreads();
    #pragma unroll
    for (int i = 0; i < 32; i += 8)
        Th[(size_t)(n0 + ty + i) * K + k0 + tx] = __float2half(t[tx][ty + i]);
}

// ---------------------------------------------------------------------------
// mma.sync GEMM, tile 128x128, BK=64 (SW128), double buffer, 2 CTAs/SM.
// MODE 0: proj, 1-term (A=yh only), fp32 C out.
// MODE 1: merged QKV GEMM (N=3072): CTAs with bn<1024 compute Q (2-term,
//         scale+split epilogue); bn>=1024 compute K/V (1-term, hi-only).
// ---------------------------------------------------------------------------
#define TILE_B     (128 * 128)           // 16384 B
#define STAGE_B    (3 * TILE_B)          // 49152 B
#define MM_SMEM    (2 * STAGE_B)         // 98304 B

template<int MODE>
__global__ void __launch_bounds__(256, 2) mmasync_kernel(
    const __half* __restrict__ Ah, const __half* __restrict__ Al,
    const __half* __restrict__ Bh,
    float* __restrict__ C, int N, int K)
{
    extern __shared__ char smraw[];
    const uint32_t smb = smem_u32(smraw);

    const int tid  = threadIdx.x;
    const int wid  = tid >> 5, lane = tid & 31;
    const int wm   = wid & 1;
    const int wn   = wid >> 1;
    const int bm   = blockIdx.y * 128, bn = blockIdx.x * 128;
    const int l16  = lane & 15, lh = lane >> 4;
    const bool two = (MODE == 1) && (bn < CDIM);   // 2-term only for Q columns

    float acc[4][4][4];
    #pragma unroll
    for (int i = 0; i < 4; i++)
        #pragma unroll
        for (int j = 0; j < 4; j++)
            #pragma unroll
            for (int k = 0; k < 4; k++) acc[i][j][k] = 0.f;

    auto fill = [&](int s, int k0) {
        uint32_t sb = smb + (uint32_t)s * STAGE_B;
        #pragma unroll
        for (int i = 0; i < 4; i++) {
            int chunk = tid + i * 256;
            int row = chunk >> 3, c = chunk & 7;
            cpa16(sb + SWZ128((uint32_t)(row * 128 + c * 16)),
                  Ah + (size_t)(bm + row) * K + k0 + c * 8);
        }
        if (two) {
            #pragma unroll
            for (int i = 0; i < 4; i++) {
                int chunk = tid + i * 256;
                int row = chunk >> 3, c = chunk & 7;
                cpa16(sb + TILE_B + SWZ128((uint32_t)(row * 128 + c * 16)),
                      Al + (size_t)(bm + row) * K + k0 + c * 8);
            }
        }
        #pragma unroll
        for (int i = 0; i < 4; i++) {
            int chunk = tid + i * 256;
            int row = chunk >> 3, c = chunk & 7;
            cpa16(sb + 2 * TILE_B + SWZ128((uint32_t)(row * 128 + c * 16)),
                  Bh + (size_t)(bn + row) * K + k0 + c * 8);
        }
    };

    const int nch = K >> 6;   // BK = 64
    fill(0, 0); CP_COMMIT();

    for (int i = 0; i < nch; i++) {
        if (i + 1 < nch) { fill((i + 1) & 1, (i + 1) << 6); CP_COMMIT(); CP_WAIT(1); }
        else             { CP_WAIT(0); }
        __syncthreads();

        uint32_t sb = smb + (uint32_t)(i & 1) * STAGE_B;
        uint32_t Abh = sb, Abl = sb + TILE_B, Bbh = sb + 2 * TILE_B;

        #pragma unroll
        for (int kh = 0; kh < 4; kh++) {
            const uint32_t koff = (uint32_t)(kh * 32 + lh * 16);
            uint32_t ah[4][4], al[4][4];
            #pragma unroll
            for (int mt = 0; mt < 4; mt++) {
                uint32_t ro = SWZ128((uint32_t)((wm * 64 + mt * 16 + l16) * 128) + koff);
                ldsm4(Abh + ro, ah[mt]);
                if (two) ldsm4(Abl + ro, al[mt]);
            }
            uint32_t bh[2][4];
            #pragma unroll
            for (int np = 0; np < 2; np++) {
                uint32_t ro = SWZ128((uint32_t)((wn * 32 + np * 16 + l16) * 128) + koff);
                ldsm4(Bbh + ro, bh[np]);
            }
            // hi pass
            #pragma unroll
            for (int mt = 0; mt < 4; mt++)
                #pragma unroll
                for (int nt = 0; nt < 4; nt++) {
                    const int np = nt >> 1, o = nt & 1;
                    mma16816(acc[mt][nt], ah[mt], bh[np][o], bh[np][o + 2]);
                }
            // lo pass (Q columns only)
            if (two) {
                #pragma unroll
                for (int mt = 0; mt < 4; mt++)
                    #pragma unroll
                    for (int nt = 0; nt < 4; nt++) {
                        const int np = nt >> 1, o = nt & 1;
                        mma16816(acc[mt][nt], al[mt], bh[np][o], bh[np][o + 2]);
                    }
            }
        }
        __syncthreads();
    }

    const int er = lane >> 2, ec = (lane & 3) * 2;
    #pragma unroll
    for (int mt = 0; mt < 4; mt++)
        #pragma unroll
        for (int nt = 0; nt < 4; nt++) {
            int r0 = bm + wm * 64 + mt * 16 + er;
            int c0 = bn + wn * 32 + nt * 8 + ec;
            float* v = acc[mt][nt];
            if (MODE == 0) {
                *(float2*)&C[(size_t)r0 * N + c0]       = make_float2(v[0], v[1]);
                *(float2*)&C[(size_t)(r0 + 8) * N + c0] = make_float2(v[2], v[3]);
            } else {
                int bb = r0 >> 11, t = r0 & 2047;
                int part = c0 >> 10, rem = c0 & 1023;
                int hh = rem >> 6, d = rem & 63;
                size_t o = ((((size_t)part * BATCH + bb) * NHEAD + hh) * TSEQ + t) * HDIM + d;
                if (part == 0) {
                    #pragma unroll
                    for (int rr = 0; rr < 2; rr++) {
                        float v0 = v[2 * rr + 0] * QSCALE;
                        float v1 = v[2 * rr + 1] * QSCALE;
                        size_t oo = o + (size_t)rr * 8 * HDIM;
                        __half h0 = __float2half(v0), h1 = __float2half(v1);
                        *(uint32_t*)&g_qkvh[oo] = packh2(h0, h1);
                        *(uint32_t*)&g_qkvl[oo] = packh2(
                            __float2half(v0 - __half2float(h0)),
                            __float2half(v1 - __half2float(h1)));
                    }
                } else {
                    #pragma unroll
                    for (int rr = 0; rr < 2; rr++) {
                        size_t oo = o + (size_t)rr * 8 * HDIM;
                        *(uint32_t*)&g_qkvh[oo] =
                            packh2(__float2half(v[2 * rr]), __float2half(v[2 * rr + 1]));
                    }
                }
            }
        }
}

// ---------------------------------------------------------------------------
// Tensor-core flash attention (causal), Bq=128, Bk=64, D=64.
// S: 2-term (Qh+Ql)·K.  PV: 1-term Ph·V.  Epilogue writes Y hi only.
// ---------------------------------------------------------------------------
#define FL_SMEM (64 * 1024)

__global__ void __launch_bounds__(256, 2) flash_tc_kernel()
{
    extern __shared__ char smraw[];
    const uint32_t S = smem_u32(smraw);
    const int tid = threadIdx.x, w = tid >> 5, lane = tid & 31;
    const int l16 = lane & 15, lh = lane >> 4;
    const int b = blockIdx.z, h = blockIdx.y;
    const int qt = (int)(gridDim.x - 1 - blockIdx.x);   // heaviest first
    const int n_kt = 2 * qt + 2;

    const uint32_t Qh_s = S, Ql_s = S + 16384;
    const uint32_t stg0 = S + 32768;

    const size_t head = (((size_t)b) * NHEAD + h) * TSEQ * HDIM;
    const size_t HSZ  = (size_t)BATCH * NHEAD * TSEQ * HDIM;
    const __half* qh = g_qkvh + head;
    const __half* ql = g_qkvl + head;
    const __half* kh = g_qkvh + HSZ + head;
    const __half* vh = g_qkvh + 2 * HSZ + head;

    {
        #pragma unroll
        for (int i = 0; i < 8; i++) {
            int idx = tid + i * 256;
            int mtx = idx >> 10, row = (idx >> 3) & 127, c = idx & 7;
            const __half* src = (mtx ? ql : qh) + (size_t)(qt * 128 + row) * HDIM + c * 8;
            cpa16((mtx ? Ql_s : Qh_s) + SWZ128((uint32_t)(row * 128 + c * 16)), src);
        }
    }
    auto fillkv = [&](int s, int kt) {
        uint32_t sb = stg0 + (uint32_t)s * 16384u;
        const __half* bases[2] = {kh, vh};
        #pragma unroll
        for (int i = 0; i < 4; i++) {
            int idx = tid + i * 256;
            int mtx = idx >> 9, row = (idx >> 3) & 63, c = idx & 7;
            cpa16(sb + (uint32_t)mtx * 8192u + SWZ128((uint32_t)(row * 128 + c * 16)),
                  bases[mtx] + (size_t)(kt * 64 + row) * HDIM + c * 8);
        }
    };

    fillkv(0, 0); CP_COMMIT();
    if (n_kt > 1) { fillkv(1, 1); CP_COMMIT(); }

    float m0 = -1e30f, m1 = -1e30f, l0 = 0.f, l1 = 0.f;
    float o[8][4];
    #pragma unroll
    for (int j = 0; j < 8; j++)
        #pragma unroll
        for (int e = 0; e < 4; e++) o[j][e] = 0.f;

    for (int kt = 0; kt < n_kt; kt++) {
        if (kt + 1 < n_kt) { CP_WAIT(1); } else { CP_WAIT(0); }
        __syncthreads();

        const uint32_t sb   = stg0 + (uint32_t)(kt & 1) * 16384u;
        const uint32_t Kh_s = sb, Vh_s = sb + 8192;

        float s[8][4];
        #pragma unroll
        for (int j = 0; j < 8; j++)
            #pragma unroll
            for (int e = 0; e < 4; e++) s[j][e] = 0.f;

        #pragma unroll
        for (int kk = 0; kk < 4; kk++) {
            const uint32_t koff = (uint32_t)(kk * 32 + lh * 16);
            uint32_t qf[4], qlf[4];
            ldsm4(Qh_s + SWZ128((uint32_t)((w * 16 + l16) * 128) + koff), qf);
            ldsm4(Ql_s + SWZ128((uint32_t)((w * 16 + l16) * 128) + koff), qlf);
            #pragma unroll
            for (int gp = 0; gp < 2; gp++) {
                const int g0 = 2 * gp, g1 = 2 * gp + 1;
                uint32_t kf0[4], kf1[4];
                ldsm4(Kh_s + SWZ128((uint32_t)((g0 * 16 + l16) * 128) + koff), kf0);
                ldsm4(Kh_s + SWZ128((uint32_t)((g1 * 16 + l16) * 128) + koff), kf1);
                mma16816(s[2 * g0],     qf, kf0[0], kf0[2]);
                mma16816(s[2 * g0 + 1], qf, kf0[1], kf0[3]);
                mma16816(s[2 * g1],     qf, kf1[0], kf1[2]);
                mma16816(s[2 * g1 + 1], qf, kf1[1], kf1[3]);
                mma16816(s[2 * g0],     qlf, kf0[0], kf0[2]);
                mma16816(s[2 * g0 + 1], qlf, kf0[1], kf0[3]);
                mma16816(s[2 * g1],     qlf, kf1[0], kf1[2]);
                mma16816(s[2 * g1 + 1], qlf, kf1[1], kf1[3]);
            }
        }

        const int row0 = qt * 128 + w * 16 + (lane >> 2);
        if (kt * 64 + 63 > qt * 128 + w * 16) {
            #pragma unroll
            for (int j = 0; j < 8; j++) {
                int colb = kt * 64 + j * 8 + (lane & 3) * 2;
                if (colb + 0 > row0)     s[j][0] = -1e30f;
                if (colb + 1 > row0)     s[j][1] = -1e30f;
                if (colb + 0 > row0 + 8) s[j][2] = -1e30f;
                if (colb + 1 > row0 + 8) s[j][3] = -1e30f;
            }
        }

        float mx0 = -1e30f, mx1 = -1e30f;
        #pragma unroll
        for (int j = 0; j < 8; j++) {
            mx0 = fmaxf(mx0, fmaxf(s[j][0], s[j][1]));
            mx1 = fmaxf(mx1, fmaxf(s[j][2], s[j][3]));
        }
        mx0 = fmaxf(mx0, __shfl_xor_sync(0xffffffffu, mx0, 1));
        mx0 = fmaxf(mx0, __shfl_xor_sync(0xffffffffu, mx0, 2));
        mx1 = fmaxf(mx1, __shfl_xor_sync(0xffffffffu, mx1, 1));
        mx1 = fmaxf(mx1, __shfl_xor_sync(0xffffffffu, mx1, 2));
        float nm0 = fmaxf(m0, mx0), nm1 = fmaxf(m1, mx1);
        float c0 = exp2f(m0 - nm0), c1 = exp2f(m1 - nm1);
        m0 = nm0; m1 = nm1;
        float sum0 = 0.f, sum1 = 0.f;
        #pragma unroll
        for (int j = 0; j < 8; j++) {
            s[j][0] = exp2f(s[j][0] - m0);
            s[j][1] = exp2f(s[j][1] - m0);
            s[j][2] = exp2f(s[j][2] - m1);
            s[j][3] = exp2f(s[j][3] - m1);
            sum0 += s[j][0] + s[j][1];
            sum1 += s[j][2] + s[j][3];
        }
        sum0 += __shfl_xor_sync(0xffffffffu, sum0, 1);
        sum0 += __shfl_xor_sync(0xffffffffu, sum0, 2);
        sum1 += __shfl_xor_sync(0xffffffffu, sum1, 1);
        sum1 += __shfl_xor_sync(0xffffffffu, sum1, 2);
        l0 = l0 * c0 + sum0;
        l1 = l1 * c1 + sum1;
        #pragma unroll
        for (int j = 0; j < 8; j++) {
            o[j][0] *= c0; o[j][1] *= c0; o[j][2] *= c1; o[j][3] *= c1;
        }

        // ---- O += P V (1-term) ----
        #pragma unroll
        for (int kk = 0; kk < 4; kk++) {
            uint32_t pa[4];
            #pragma unroll
            for (int half = 0; half < 2; half++) {
                const int f = 2 * kk + half;
                pa[2 * half + 0] = packh2(__float2half(s[f][0]), __float2half(s[f][1]));
                pa[2 * half + 1] = packh2(__float2half(s[f][2]), __float2half(s[f][3]));
            }
            #pragma unroll
            for (int gp = 0; gp < 2; gp++) {
                const int g0 = 2 * gp, g1 = 2 * gp + 1;
                uint32_t vf0[4], vf1[4];
                uint32_t ro0 = SWZ128((uint32_t)((kk * 16 + l16) * 128 + g0 * 32) + (uint32_t)(lh * 16));
                uint32_t ro1 = SWZ128((uint32_t)((kk * 16 + l16) * 128 + g1 * 32) + (uint32_t)(lh * 16));
                ldsm4t(Vh_s + ro0, vf0);
                ldsm4t(Vh_s + ro1, vf1);
                mma16816(o[2 * g0],     pa, vf0[0], vf0[1]);
                mma16816(o[2 * g0 + 1], pa, vf0[2], vf0[3]);
                mma16816(o[2 * g1],     pa, vf1[0], vf1[1]);
                mma16816(o[2 * g1 + 1], pa, vf1[2], vf1[3]);
            }
        }

        __syncthreads();
        if (kt + 2 < n_kt) { fillkv(kt & 1, kt + 2); CP_COMMIT(); }
    }

    const float inv0 = 1.f / l0, inv1 = 1.f / l1;
    const int r0 = qt * 128 + w * 16 + (lane >> 2);
    const int t0 = r0, t1 = r0 + 8;
    #pragma unroll
    for (int j = 0; j < 8; j++) {
        int d = j * 8 + (lane & 3) * 2;
        size_t o0 = ((size_t)b * TSEQ + t0) * CDIM + h * HDIM + d;
        size_t o1 = ((size_t)b * TSEQ + t1) * CDIM + h * HDIM + d;
        *(uint32_t*)&g_yh[o0] = packh2(__float2half(o[j][0] * inv0),
                                       __float2half(o[j][1] * inv0));
        *(uint32_t*)&g_yh[o1] = packh2(__float2half(o[j][2] * inv1),
                                       __float2half(o[j][3] * inv1));
    }
}

// ---------------------------------------------------------------------------
extern "C" void kernel_launch(void* const* d_in, const int* in_sizes, int n_in,
                              void* d_out, int out_size)
{
    const float* x      = (const float*)d_in[0];
    const float* w_qkv  = (const float*)d_in[1];
    const float* w_proj = (const float*)d_in[2];
    float* out = (float*)d_out;

    __half *xh, *xl, *yh, *wq, *wp;
    cudaGetSymbolAddress((void**)&xh, g_xh);
    cudaGetSymbolAddress((void**)&xl, g_xl);
    cudaGetSymbolAddress((void**)&yh, g_yh);
    cudaGetSymbolAddress((void**)&wq, g_wq);
    cudaGetSymbolAddress((void**)&wp, g_wp);

    cudaFuncSetAttribute(mmasync_kernel<0>, cudaFuncAttributeMaxDynamicSharedMemorySize, MM_SMEM);
    cudaFuncSetAttribute(mmasync_kernel<1>, cudaFuncAttributeMaxDynamicSharedMemorySize, MM_SMEM);
    cudaFuncSetAttribute(flash_tc_kernel,   cudaFuncAttributeMaxDynamicSharedMemorySize, FL_SMEM);
    cudaFuncSetAttribute(mmasync_kernel<0>, cudaFuncAttributePreferredSharedMemoryCarveout, 100);
    cudaFuncSetAttribute(mmasync_kernel<1>, cudaFuncAttributePreferredSharedMemoryCarveout, 100);
    cudaFuncSetAttribute(flash_tc_kernel,   cudaFuncAttributePreferredSharedMemoryCarveout, 100);

    const int n4 = MTOT * CDIM / 4;

    split_kernel<<<(n4 + 255) / 256, 256>>>(x, xh, xl, n4);

    {
        dim3 g1(C3 / 32, CDIM / 32), blk(32, 8);
        tsplit_kernel<<<g1, blk>>>(w_qkv, wq, CDIM, C3);
        dim3 g2(CDIM / 32, CDIM / 32);
        tsplit_kernel<<<g2, blk>>>(w_proj, wp, CDIM, CDIM);
    }

    // merged QKV GEMM: N=3072 (Q 2-term / KV 1-term per-CTA)
    {
        dim3 grid(C3 / 128, MTOT / 128);
        mmasync_kernel<1><<<grid, 256, MM_SMEM>>>(xh, xl, wq, nullptr, C3, CDIM);
    }

    {
        dim3 grid(TSEQ / 128, NHEAD, BATCH);
        flash_tc_kernel<<<grid, 256, FL_SMEM>>>();
    }

    // proj GEMM: 1-term (Y hi only)
    {
        dim3 grid(CDIM / 128, MTOT / 128);
        mmasync_kernel<0><<<grid, 256, MM_SMEM>>>(yh, nullptr, wp, out, CDIM, CDIM);
    }
    (void)in_sizes; (void)n_in; (void)out_size;
}

// round 13
// speedup vs baseline: 1.8290x; 1.2715x over previous
#include <cuda_runtime.h>
#include <cuda_fp16.h>
#include <cstdint>

// Problem constants
#define BATCH 4
#define TSEQ  2048
#define CDIM  1024
#define NHEAD 16
#define HDIM  64
#define C3    (3*CDIM)
#define MTOT  (BATCH*TSEQ)   // 8192

#define QSCALE 0.18033688011112042f   // 0.125 * log2(e)

// ---------------------------------------------------------------------------
// Device-global scratch (no allocation allowed)
// ---------------------------------------------------------------------------
__device__ __align__(256) __half g_qkv[(size_t)3 * BATCH * NHEAD * TSEQ * HDIM];
__device__ __align__(256) __half g_y[(size_t)MTOT * CDIM];
__device__ __align__(256) __half g_x[(size_t)MTOT * CDIM];
__device__ __align__(256) __half g_wq[(size_t)C3 * CDIM];     // transposed N x K
__device__ __align__(256) __half g_wp[(size_t)CDIM * CDIM];   // transposed N x K

// ---------------------------------------------------------------------------
// Helpers (baseline PTX only)
// ---------------------------------------------------------------------------
__device__ __forceinline__ uint32_t smem_u32(const void* p) {
    uint32_t a;
    asm("{ .reg .u64 t; cvta.to.shared.u64 t, %1; cvt.u32.u64 %0, t; }" : "=r"(a) : "l"(p));
    return a;
}
__device__ __forceinline__ void cpa16(uint32_t dst, const void* src) {
    asm volatile("cp.async.cg.shared.global [%0], [%1], 16;\n" :: "r"(dst), "l"(src));
}
#define CP_COMMIT() asm volatile("cp.async.commit_group;\n" ::: "memory")
#define CP_WAIT(n)  asm volatile("cp.async.wait_group %0;\n" :: "n"(n) : "memory")
#define SWZ128(o) ((o) ^ (((o) >> 3) & 0x70))

__device__ __forceinline__ void ldsm4(uint32_t addr, uint32_t* r) {
    asm volatile("ldmatrix.sync.aligned.m8n8.x4.shared.b16 {%0,%1,%2,%3}, [%4];"
                 : "=r"(r[0]), "=r"(r[1]), "=r"(r[2]), "=r"(r[3]) : "r"(addr));
}
__device__ __forceinline__ void ldsm4t(uint32_t addr, uint32_t* r) {
    asm volatile("ldmatrix.sync.aligned.m8n8.x4.trans.shared.b16 {%0,%1,%2,%3}, [%4];"
                 : "=r"(r[0]), "=r"(r[1]), "=r"(r[2]), "=r"(r[3]) : "r"(addr));
}
__device__ __forceinline__ void mma16816(float* d, const uint32_t* a, uint32_t b0, uint32_t b1) {
    asm volatile("mma.sync.aligned.m16n8k16.row.col.f32.f16.f16.f32 "
                 "{%0,%1,%2,%3},{%4,%5,%6,%7},{%8,%9},{%0,%1,%2,%3};"
                 : "+f"(d[0]), "+f"(d[1]), "+f"(d[2]), "+f"(d[3])
                 : "r"(a[0]), "r"(a[1]), "r"(a[2]), "r"(a[3]), "r"(b0), "r"(b1));
}
__device__ __forceinline__ uint32_t packh2(__half a, __half b) {
    __half2 t; t.x = a; t.y = b;
    return *reinterpret_cast<uint32_t*>(&t);
}

// ---------------------------------------------------------------------------
// Convert fp32 -> fp16
// ---------------------------------------------------------------------------
__global__ void __launch_bounds__(256) cvt_kernel(
    const float* __restrict__ in, __half* __restrict__ out, int n4)
{
    int i = blockIdx.x * 256 + threadIdx.x;
    if (i >= n4) return;
    float4 v = ((const float4*)in)[i];
    ((uint32_t*)out)[2*i]   = packh2(__float2half(v.x), __float2half(v.y));
    ((uint32_t*)out)[2*i+1] = packh2(__float2half(v.z), __float2half(v.w));
}

// ---------------------------------------------------------------------------
// Transpose weights: W (KxN fp32, row-major) -> Wt (NxK fp16)
// ---------------------------------------------------------------------------
__global__ void __launch_bounds__(256) tsplit_kernel(
    const float* __restrict__ W, __half* __restrict__ Th, int K, int N)
{
    __shared__ float t[32][33];
    int n0 = blockIdx.x * 32, k0 = blockIdx.y * 32;
    int tx = threadIdx.x, ty = threadIdx.y;
    #pragma unroll
    for (int i = 0; i < 32; i += 8)
        t[ty + i][tx] = W[(size_t)(k0 + ty + i) * N + n0 + tx];
    __syncthreads();
    #pragma unroll
    for (int i = 0; i < 32; i += 8)
        Th[(size_t)(n0 + ty + i) * K + k0 + tx] = __float2half(t[tx][ty + i]);
}

// ---------------------------------------------------------------------------
// mma.sync fp16 GEMM (1-term), tile 128x128, BK=64 (SW128), double buffer.
// MODE 0: proj -> fp32 C.   MODE 1: QKV -> head-major fp16 (Q pre-scaled).
// smem: 2 stages x (A 16KB + B 16KB) = 64KB -> 2 CTAs/SM.
// ---------------------------------------------------------------------------
#define TILE_B     (128 * 128)           // 16384 B
#define STAGE_B    (2 * TILE_B)          // 32768 B
#define MM_SMEM    (2 * STAGE_B)         // 65536 B

template<int MODE>
__global__ void __launch_bounds__(256, 2) mmasync_kernel(
    const __half* __restrict__ Ah, const __half* __restrict__ Bh,
    float* __restrict__ C, int N, int K)
{
    extern __shared__ char smraw[];
    const uint32_t smb = smem_u32(smraw);

    const int tid  = threadIdx.x;
    const int wid  = tid >> 5, lane = tid & 31;
    const int wm   = wid & 1;
    const int wn   = wid >> 1;
    const int bm   = blockIdx.y * 128, bn = blockIdx.x * 128;
    const int l16  = lane & 15, lh = lane >> 4;

    float acc[4][4][4];
    #pragma unroll
    for (int i = 0; i < 4; i++)
        #pragma unroll
        for (int j = 0; j < 4; j++)
            #pragma unroll
            for (int k = 0; k < 4; k++) acc[i][j][k] = 0.f;

    auto fill = [&](int s, int k0) {
        uint32_t sb = smb + (uint32_t)s * STAGE_B;
        #pragma unroll
        for (int i = 0; i < 4; i++) {
            int chunk = tid + i * 256;
            int row = chunk >> 3, c = chunk & 7;
            cpa16(sb + SWZ128((uint32_t)(row * 128 + c * 16)),
                  Ah + (size_t)(bm + row) * K + k0 + c * 8);
        }
        #pragma unroll
        for (int i = 0; i < 4; i++) {
            int chunk = tid + i * 256;
            int row = chunk >> 3, c = chunk & 7;
            cpa16(sb + TILE_B + SWZ128((uint32_t)(row * 128 + c * 16)),
                  Bh + (size_t)(bn + row) * K + k0 + c * 8);
        }
    };

    const int nch = K >> 6;   // BK = 64
    fill(0, 0); CP_COMMIT();

    for (int i = 0; i < nch; i++) {
        if (i + 1 < nch) { fill((i + 1) & 1, (i + 1) << 6); CP_COMMIT(); CP_WAIT(1); }
        else             { CP_WAIT(0); }
        __syncthreads();

        uint32_t sb = smb + (uint32_t)(i & 1) * STAGE_B;
        uint32_t Ab = sb, Bb = sb + TILE_B;

        #pragma unroll
        for (int kh = 0; kh < 4; kh++) {
            const uint32_t koff = (uint32_t)(kh * 32 + lh * 16);
            uint32_t ah[4][4];
            #pragma unroll
            for (int mt = 0; mt < 4; mt++) {
                uint32_t ro = SWZ128((uint32_t)((wm * 64 + mt * 16 + l16) * 128) + koff);
                ldsm4(Ab + ro, ah[mt]);
            }
            uint32_t bh[2][4];
            #pragma unroll
            for (int np = 0; np < 2; np++) {
                uint32_t ro = SWZ128((uint32_t)((wn * 32 + np * 16 + l16) * 128) + koff);
                ldsm4(Bb + ro, bh[np]);
            }
            #pragma unroll
            for (int mt = 0; mt < 4; mt++)
                #pragma unroll
                for (int nt = 0; nt < 4; nt++) {
                    const int np = nt >> 1, o = nt & 1;
                    mma16816(acc[mt][nt], ah[mt], bh[np][o], bh[np][o + 2]);
                }
        }
        __syncthreads();
    }

    const int er = lane >> 2, ec = (lane & 3) * 2;
    #pragma unroll
    for (int mt = 0; mt < 4; mt++)
        #pragma unroll
        for (int nt = 0; nt < 4; nt++) {
            int r0 = bm + wm * 64 + mt * 16 + er;
            int c0 = bn + wn * 32 + nt * 8 + ec;
            float* v = acc[mt][nt];
            if (MODE == 0) {
                *(float2*)&C[(size_t)r0 * N + c0]       = make_float2(v[0], v[1]);
                *(float2*)&C[(size_t)(r0 + 8) * N + c0] = make_float2(v[2], v[3]);
            } else {
                int bb = r0 >> 11, t = r0 & 2047;
                int part = c0 >> 10, rem = c0 & 1023;
                int hh = rem >> 6, d = rem & 63;
                float sc = (part == 0) ? QSCALE : 1.f;
                size_t o = ((((size_t)part * BATCH + bb) * NHEAD + hh) * TSEQ + t) * HDIM + d;
                #pragma unroll
                for (int rr = 0; rr < 2; rr++) {
                    size_t oo = o + (size_t)rr * 8 * HDIM;
                    *(uint32_t*)&g_qkv[oo] = packh2(__float2half(v[2 * rr] * sc),
                                                    __float2half(v[2 * rr + 1] * sc));
                }
            }
        }
}

// ---------------------------------------------------------------------------
// Tensor-core flash attention (causal), fp16 1-term, Bq=128, Bk=64, D=64.
// smem: Q(16K) + 2 stages x {K,V}(8K each) = 48KB -> 2 CTAs/SM easily.
// ---------------------------------------------------------------------------
#define FL_SMEM (48 * 1024)

__global__ void __launch_bounds__(256, 2) flash_tc_kernel()
{
    extern __shared__ char smraw[];
    const uint32_t S = smem_u32(smraw);
    const int tid = threadIdx.x, w = tid >> 5, lane = tid & 31;
    const int l16 = lane & 15, lh = lane >> 4;
    const int b = blockIdx.z, h = blockIdx.y;
    const int qt = (int)(gridDim.x - 1 - blockIdx.x);   // heaviest first
    const int n_kt = 2 * qt + 2;

    const uint32_t Q_s  = S;
    const uint32_t stg0 = S + 16384;

    const size_t head = (((size_t)b) * NHEAD + h) * TSEQ * HDIM;
    const size_t HSZ  = (size_t)BATCH * NHEAD * TSEQ * HDIM;
    const __half* qp = g_qkv + head;
    const __half* kp = g_qkv + HSZ + head;
    const __half* vp = g_qkv + 2 * HSZ + head;

    {
        #pragma unroll
        for (int i = 0; i < 4; i++) {
            int idx = tid + i * 256;                // 0..1023
            int row = idx >> 3, c = idx & 7;
            cpa16(Q_s + SWZ128((uint32_t)(row * 128 + c * 16)),
                  qp + (size_t)(qt * 128 + row) * HDIM + c * 8);
        }
    }
    auto fillkv = [&](int s, int kt) {
        uint32_t sb = stg0 + (uint32_t)s * 16384u;
        const __half* bases[2] = {kp, vp};
        #pragma unroll
        for (int i = 0; i < 4; i++) {
            int idx = tid + i * 256;
            int mtx = idx >> 9, row = (idx >> 3) & 63, c = idx & 7;
            cpa16(sb + (uint32_t)mtx * 8192u + SWZ128((uint32_t)(row * 128 + c * 16)),
                  bases[mtx] + (size_t)(kt * 64 + row) * HDIM + c * 8);
        }
    };

    fillkv(0, 0); CP_COMMIT();
    if (n_kt > 1) { fillkv(1, 1); CP_COMMIT(); }

    float m0 = -1e30f, m1 = -1e30f, l0 = 0.f, l1 = 0.f;
    float o[8][4];
    #pragma unroll
    for (int j = 0; j < 8; j++)
        #pragma unroll
        for (int e = 0; e < 4; e++) o[j][e] = 0.f;

    for (int kt = 0; kt < n_kt; kt++) {
        if (kt + 1 < n_kt) { CP_WAIT(1); } else { CP_WAIT(0); }
        __syncthreads();

        const uint32_t sb  = stg0 + (uint32_t)(kt & 1) * 16384u;
        const uint32_t K_s = sb, V_s = sb + 8192;

        // ---- S = Q K^T (1-term) ----
        float s[8][4];
        #pragma unroll
        for (int j = 0; j < 8; j++)
            #pragma unroll
            for (int e = 0; e < 4; e++) s[j][e] = 0.f;

        #pragma unroll
        for (int kk = 0; kk < 4; kk++) {
            const uint32_t koff = (uint32_t)(kk * 32 + lh * 16);
            uint32_t qf[4];
            ldsm4(Q_s + SWZ128((uint32_t)((w * 16 + l16) * 128) + koff), qf);
            #pragma unroll
            for (int gp = 0; gp < 2; gp++) {
                const int g0 = 2 * gp, g1 = 2 * gp + 1;
                uint32_t kf0[4], kf1[4];
                ldsm4(K_s + SWZ128((uint32_t)((g0 * 16 + l16) * 128) + koff), kf0);
                ldsm4(K_s + SWZ128((uint32_t)((g1 * 16 + l16) * 128) + koff), kf1);
                mma16816(s[2 * g0],     qf, kf0[0], kf0[2]);
                mma16816(s[2 * g0 + 1], qf, kf0[1], kf0[3]);
                mma16816(s[2 * g1],     qf, kf1[0], kf1[2]);
                mma16816(s[2 * g1 + 1], qf, kf1[1], kf1[3]);
            }
        }

        const int row0 = qt * 128 + w * 16 + (lane >> 2);
        if (kt * 64 + 63 > qt * 128 + w * 16) {
            #pragma unroll
            for (int j = 0; j < 8; j++) {
                int colb = kt * 64 + j * 8 + (lane & 3) * 2;
                if (colb + 0 > row0)     s[j][0] = -1e30f;
                if (colb + 1 > row0)     s[j][1] = -1e30f;
                if (colb + 0 > row0 + 8) s[j][2] = -1e30f;
                if (colb + 1 > row0 + 8) s[j][3] = -1e30f;
            }
        }

        float mx0 = -1e30f, mx1 = -1e30f;
        #pragma unroll
        for (int j = 0; j < 8; j++) {
            mx0 = fmaxf(mx0, fmaxf(s[j][0], s[j][1]));
            mx1 = fmaxf(mx1, fmaxf(s[j][2], s[j][3]));
        }
        mx0 = fmaxf(mx0, __shfl_xor_sync(0xffffffffu, mx0, 1));
        mx0 = fmaxf(mx0, __shfl_xor_sync(0xffffffffu, mx0, 2));
        mx1 = fmaxf(mx1, __shfl_xor_sync(0xffffffffu, mx1, 1));
        mx1 = fmaxf(mx1, __shfl_xor_sync(0xffffffffu, mx1, 2));
        float nm0 = fmaxf(m0, mx0), nm1 = fmaxf(m1, mx1);
        float c0 = exp2f(m0 - nm0), c1 = exp2f(m1 - nm1);
        m0 = nm0; m1 = nm1;
        float sum0 = 0.f, sum1 = 0.f;
        #pragma unroll
        for (int j = 0; j < 8; j++) {
            s[j][0] = exp2f(s[j][0] - m0);
            s[j][1] = exp2f(s[j][1] - m0);
            s[j][2] = exp2f(s[j][2] - m1);
            s[j][3] = exp2f(s[j][3] - m1);
            sum0 += s[j][0] + s[j][1];
            sum1 += s[j][2] + s[j][3];
        }
        sum0 += __shfl_xor_sync(0xffffffffu, sum0, 1);
        sum0 += __shfl_xor_sync(0xffffffffu, sum0, 2);
        sum1 += __shfl_xor_sync(0xffffffffu, sum1, 1);
        sum1 += __shfl_xor_sync(0xffffffffu, sum1, 2);
        l0 = l0 * c0 + sum0;
        l1 = l1 * c1 + sum1;
        #pragma unroll
        for (int j = 0; j < 8; j++) {
            o[j][0] *= c0; o[j][1] *= c0; o[j][2] *= c1; o[j][3] *= c1;
        }

        // ---- O += P V (1-term) ----
        #pragma unroll
        for (int kk = 0; kk < 4; kk++) {
            uint32_t pa[4];
            #pragma unroll
            for (int half = 0; half < 2; half++) {
                const int f = 2 * kk + half;
                pa[2 * half + 0] = packh2(__float2half(s[f][0]), __float2half(s[f][1]));
                pa[2 * half + 1] = packh2(__float2half(s[f][2]), __float2half(s[f][3]));
            }
            #pragma unroll
            for (int gp = 0; gp < 2; gp++) {
                const int g0 = 2 * gp, g1 = 2 * gp + 1;
                uint32_t vf0[4], vf1[4];
                uint32_t ro0 = SWZ128((uint32_t)((kk * 16 + l16) * 128 + g0 * 32) + (uint32_t)(lh * 16));
                uint32_t ro1 = SWZ128((uint32_t)((kk * 16 + l16) * 128 + g1 * 32) + (uint32_t)(lh * 16));
                ldsm4t(V_s + ro0, vf0);
                ldsm4t(V_s + ro1, vf1);
                mma16816(o[2 * g0],     pa, vf0[0], vf0[1]);
                mma16816(o[2 * g0 + 1], pa, vf0[2], vf0[3]);
                mma16816(o[2 * g1],     pa, vf1[0], vf1[1]);
                mma16816(o[2 * g1 + 1], pa, vf1[2], vf1[3]);
            }
        }

        __syncthreads();
        if (kt + 2 < n_kt) { fillkv(kt & 1, kt + 2); CP_COMMIT(); }
    }

    const float inv0 = 1.f / l0, inv1 = 1.f / l1;
    const int r0 = qt * 128 + w * 16 + (lane >> 2);
    const int t0 = r0, t1 = r0 + 8;
    #pragma unroll
    for (int j = 0; j < 8; j++) {
        int d = j * 8 + (lane & 3) * 2;
        size_t o0 = ((size_t)b * TSEQ + t0) * CDIM + h * HDIM + d;
        size_t o1 = ((size_t)b * TSEQ + t1) * CDIM + h * HDIM + d;
        *(uint32_t*)&g_y[o0] = packh2(__float2half(o[j][0] * inv0),
                                      __float2half(o[j][1] * inv0));
        *(uint32_t*)&g_y[o1] = packh2(__float2half(o[j][2] * inv1),
                                      __float2half(o[j][3] * inv1));
    }
}

// ---------------------------------------------------------------------------
extern "C" void kernel_launch(void* const* d_in, const int* in_sizes, int n_in,
                              void* d_out, int out_size)
{
    const float* x      = (const float*)d_in[0];
    const float* w_qkv  = (const float*)d_in[1];
    const float* w_proj = (const float*)d_in[2];
    float* out = (float*)d_out;

    __half *xh, *yh, *wq, *wp;
    cudaGetSymbolAddress((void**)&xh, g_x);
    cudaGetSymbolAddress((void**)&yh, g_y);
    cudaGetSymbolAddress((void**)&wq, g_wq);
    cudaGetSymbolAddress((void**)&wp, g_wp);

    cudaFuncSetAttribute(mmasync_kernel<0>, cudaFuncAttributeMaxDynamicSharedMemorySize, MM_SMEM);
    cudaFuncSetAttribute(mmasync_kernel<1>, cudaFuncAttributeMaxDynamicSharedMemorySize, MM_SMEM);
    cudaFuncSetAttribute(flash_tc_kernel,   cudaFuncAttributeMaxDynamicSharedMemorySize, FL_SMEM);
    cudaFuncSetAttribute(mmasync_kernel<0>, cudaFuncAttributePreferredSharedMemoryCarveout, 100);
    cudaFuncSetAttribute(mmasync_kernel<1>, cudaFuncAttributePreferredSharedMemoryCarveout, 100);
    cudaFuncSetAttribute(flash_tc_kernel,   cudaFuncAttributePreferredSharedMemoryCarveout, 100);

    const int n4 = MTOT * CDIM / 4;

    // 1) X -> fp16
    cvt_kernel<<<(n4 + 255) / 256, 256>>>(x, xh, n4);

    // 2) transpose weights -> fp16
    {
        dim3 g1(C3 / 32, CDIM / 32), blk(32, 8);
        tsplit_kernel<<<g1, blk>>>(w_qkv, wq, CDIM, C3);
        dim3 g2(CDIM / 32, CDIM / 32);
        tsplit_kernel<<<g2, blk>>>(w_proj, wp, CDIM, CDIM);
    }

    // 3) QKV GEMM (N=3072, 1-term) with head-major epilogue (Q pre-scaled)
    {
        dim3 grid(C3 / 128, MTOT / 128);
        mmasync_kernel<1><<<grid, 256, MM_SMEM>>>(xh, wq, nullptr, C3, CDIM);
    }

    // 4) flash attention -> g_y (fp16)
    {
        dim3 grid(TSEQ / 128, NHEAD, BATCH);
        flash_tc_kernel<<<grid, 256, FL_SMEM>>>();
    }

    // 5) proj GEMM (1-term) -> fp32 out
    {
        dim3 grid(CDIM / 128, MTOT / 128);
        mmasync_kernel<0><<<grid, 256, MM_SMEM>>>(yh, wp, out, CDIM, CDIM);
    }
    (void)in_sizes; (void)n_in; (void)out_size;
}

// round 14
// speedup vs baseline: 1.8759x; 1.0256x over previous
#include <cuda_runtime.h>
#include <cuda_fp16.h>
#include <cstdint>

// Problem constants
#define BATCH 4
#define TSEQ  2048
#define CDIM  1024
#define NHEAD 16
#define HDIM  64
#define C3    (3*CDIM)
#define MTOT  (BATCH*TSEQ)   // 8192

#define QSCALE 0.18033688011112042f   // 0.125 * log2(e)

// ---------------------------------------------------------------------------
// Device-global scratch (no allocation allowed)
// ---------------------------------------------------------------------------
__device__ __align__(256) __half g_qkv[(size_t)3 * BATCH * NHEAD * TSEQ * HDIM];
__device__ __align__(256) __half g_y[(size_t)MTOT * CDIM];
__device__ __align__(256) __half g_x[(size_t)MTOT * CDIM];
__device__ __align__(256) __half g_wq[(size_t)C3 * CDIM];     // transposed N x K
__device__ __align__(256) __half g_wp[(size_t)CDIM * CDIM];   // transposed N x K

// ---------------------------------------------------------------------------
// Helpers (baseline PTX only)
// ---------------------------------------------------------------------------
__device__ __forceinline__ uint32_t smem_u32(const void* p) {
    uint32_t a;
    asm("{ .reg .u64 t; cvta.to.shared.u64 t, %1; cvt.u32.u64 %0, t; }" : "=r"(a) : "l"(p));
    return a;
}
__device__ __forceinline__ void cpa16(uint32_t dst, const void* src) {
    asm volatile("cp.async.cg.shared.global [%0], [%1], 16;\n" :: "r"(dst), "l"(src));
}
#define CP_COMMIT() asm volatile("cp.async.commit_group;\n" ::: "memory")
#define CP_WAIT(n)  asm volatile("cp.async.wait_group %0;\n" :: "n"(n) : "memory")
#define SWZ128(o) ((o) ^ (((o) >> 3) & 0x70))

__device__ __forceinline__ void ldsm4(uint32_t addr, uint32_t* r) {
    asm volatile("ldmatrix.sync.aligned.m8n8.x4.shared.b16 {%0,%1,%2,%3}, [%4];"
                 : "=r"(r[0]), "=r"(r[1]), "=r"(r[2]), "=r"(r[3]) : "r"(addr));
}
__device__ __forceinline__ void ldsm4t(uint32_t addr, uint32_t* r) {
    asm volatile("ldmatrix.sync.aligned.m8n8.x4.trans.shared.b16 {%0,%1,%2,%3}, [%4];"
                 : "=r"(r[0]), "=r"(r[1]), "=r"(r[2]), "=r"(r[3]) : "r"(addr));
}
__device__ __forceinline__ void mma16816(float* d, const uint32_t* a, uint32_t b0, uint32_t b1) {
    asm volatile("mma.sync.aligned.m16n8k16.row.col.f32.f16.f16.f32 "
                 "{%0,%1,%2,%3},{%4,%5,%6,%7},{%8,%9},{%0,%1,%2,%3};"
                 : "+f"(d[0]), "+f"(d[1]), "+f"(d[2]), "+f"(d[3])
                 : "r"(a[0]), "r"(a[1]), "r"(a[2]), "r"(a[3]), "r"(b0), "r"(b1));
}
__device__ __forceinline__ uint32_t packh2(__half a, __half b) {
    __half2 t; t.x = a; t.y = b;
    return *reinterpret_cast<uint32_t*>(&t);
}

// ---------------------------------------------------------------------------
// Fused prep: X fp32->fp16 convert + both weight transposes, one launch.
// Block ranges: [0, NB_CVT) cvt; [NB_CVT, NB_CVT+NB_WQ) w_qkv T; rest w_proj T.
// ---------------------------------------------------------------------------
#define N4_X     (MTOT * CDIM / 4)          // 2M float4
#define NB_CVT   (N4_X / 256)               // 8192 blocks
#define NB_WQ    ((C3 / 32) * (CDIM / 32))  // 3072 blocks
#define NB_WP    ((CDIM / 32) * (CDIM / 32))// 1024 blocks
#define NB_PREP  (NB_CVT + NB_WQ + NB_WP)

__global__ void __launch_bounds__(256) prep_kernel(
    const float* __restrict__ x, const float* __restrict__ w_qkv,
    const float* __restrict__ w_proj)
{
    const int bid = blockIdx.x, tid = threadIdx.x;
    if (bid < NB_CVT) {
        int i = bid * 256 + tid;
        float4 v = ((const float4*)x)[i];
        ((uint32_t*)g_x)[2*i]   = packh2(__float2half(v.x), __float2half(v.y));
        ((uint32_t*)g_x)[2*i+1] = packh2(__float2half(v.z), __float2half(v.w));
        return;
    }
    __shared__ float t[32][33];
    const int tx = tid & 31, ty = tid >> 5;   // 32 x 8
    const float* W; __half* Th; int K, N, idx;
    if (bid < NB_CVT + NB_WQ) {
        idx = bid - NB_CVT; W = w_qkv; Th = g_wq; K = CDIM; N = C3;
    } else {
        idx = bid - NB_CVT - NB_WQ; W = w_proj; Th = g_wp; K = CDIM; N = CDIM;
    }
    const int nblk = N / 32;
    const int n0 = (idx % nblk) * 32, k0 = (idx / nblk) * 32;
    #pragma unroll
    for (int i = 0; i < 32; i += 8)
        t[ty + i][tx] = W[(size_t)(k0 + ty + i) * N + n0 + tx];
    __syncthreads();
    #pragma unroll
    for (int i = 0; i < 32; i += 8)
        Th[(size_t)(n0 + ty + i) * K + k0 + tx] = __float2half(t[tx][ty + i]);
}

// ---------------------------------------------------------------------------
// mma.sync fp16 GEMM (1-term), tile 128x128, BK=64 (SW128), double buffer.
// MODE 0: proj -> fp32 C.   MODE 1: QKV -> head-major fp16 (Q pre-scaled).
// ---------------------------------------------------------------------------
#define TILE_B     (128 * 128)           // 16384 B
#define STAGE_B    (2 * TILE_B)          // 32768 B
#define MM_SMEM    (2 * STAGE_B)         // 65536 B

template<int MODE>
__global__ void __launch_bounds__(256, 2) mmasync_kernel(
    const __half* __restrict__ Ah, const __half* __restrict__ Bh,
    float* __restrict__ C, int N, int K)
{
    extern __shared__ char smraw[];
    const uint32_t smb = smem_u32(smraw);

    const int tid  = threadIdx.x;
    const int wid  = tid >> 5, lane = tid & 31;
    const int wm   = wid & 1;
    const int wn   = wid >> 1;
    const int bm   = blockIdx.y * 128, bn = blockIdx.x * 128;
    const int l16  = lane & 15, lh = lane >> 4;

    float acc[4][4][4];
    #pragma unroll
    for (int i = 0; i < 4; i++)
        #pragma unroll
        for (int j = 0; j < 4; j++)
            #pragma unroll
            for (int k = 0; k < 4; k++) acc[i][j][k] = 0.f;

    auto fill = [&](int s, int k0) {
        uint32_t sb = smb + (uint32_t)s * STAGE_B;
        #pragma unroll
        for (int i = 0; i < 4; i++) {
            int chunk = tid + i * 256;
            int row = chunk >> 3, c = chunk & 7;
            cpa16(sb + SWZ128((uint32_t)(row * 128 + c * 16)),
                  Ah + (size_t)(bm + row) * K + k0 + c * 8);
        }
        #pragma unroll
        for (int i = 0; i < 4; i++) {
            int chunk = tid + i * 256;
            int row = chunk >> 3, c = chunk & 7;
            cpa16(sb + TILE_B + SWZ128((uint32_t)(row * 128 + c * 16)),
                  Bh + (size_t)(bn + row) * K + k0 + c * 8);
        }
    };

    const int nch = K >> 6;   // BK = 64
    fill(0, 0); CP_COMMIT();

    for (int i = 0; i < nch; i++) {
        if (i + 1 < nch) { fill((i + 1) & 1, (i + 1) << 6); CP_COMMIT(); CP_WAIT(1); }
        else             { CP_WAIT(0); }
        __syncthreads();

        uint32_t sb = smb + (uint32_t)(i & 1) * STAGE_B;
        uint32_t Ab = sb, Bb = sb + TILE_B;

        #pragma unroll
        for (int kh = 0; kh < 4; kh++) {
            const uint32_t koff = (uint32_t)(kh * 32 + lh * 16);
            uint32_t ah[4][4];
            #pragma unroll
            for (int mt = 0; mt < 4; mt++) {
                uint32_t ro = SWZ128((uint32_t)((wm * 64 + mt * 16 + l16) * 128) + koff);
                ldsm4(Ab + ro, ah[mt]);
            }
            uint32_t bh[2][4];
            #pragma unroll
            for (int np = 0; np < 2; np++) {
                uint32_t ro = SWZ128((uint32_t)((wn * 32 + np * 16 + l16) * 128) + koff);
                ldsm4(Bb + ro, bh[np]);
            }
            #pragma unroll
            for (int mt = 0; mt < 4; mt++)
                #pragma unroll
                for (int nt = 0; nt < 4; nt++) {
                    const int np = nt >> 1, o = nt & 1;
                    mma16816(acc[mt][nt], ah[mt], bh[np][o], bh[np][o + 2]);
                }
        }
        __syncthreads();
    }

    const int er = lane >> 2, ec = (lane & 3) * 2;
    #pragma unroll
    for (int mt = 0; mt < 4; mt++)
        #pragma unroll
        for (int nt = 0; nt < 4; nt++) {
            int r0 = bm + wm * 64 + mt * 16 + er;
            int c0 = bn + wn * 32 + nt * 8 + ec;
            float* v = acc[mt][nt];
            if (MODE == 0) {
                *(float2*)&C[(size_t)r0 * N + c0]       = make_float2(v[0], v[1]);
                *(float2*)&C[(size_t)(r0 + 8) * N + c0] = make_float2(v[2], v[3]);
            } else {
                int bb = r0 >> 11, t = r0 & 2047;
                int part = c0 >> 10, rem = c0 & 1023;
                int hh = rem >> 6, d = rem & 63;
                float sc = (part == 0) ? QSCALE : 1.f;
                size_t o = ((((size_t)part * BATCH + bb) * NHEAD + hh) * TSEQ + t) * HDIM + d;
                #pragma unroll
                for (int rr = 0; rr < 2; rr++) {
                    size_t oo = o + (size_t)rr * 8 * HDIM;
                    *(uint32_t*)&g_qkv[oo] = packh2(__float2half(v[2 * rr] * sc),
                                                    __float2half(v[2 * rr + 1] * sc));
                }
            }
        }
}

// ---------------------------------------------------------------------------
// Tensor-core flash attention (causal), fp16 1-term, Bq=128, Bk=64, D=64.
// 3-stage K/V pipeline; warps 0-3 skip the fully-masked final diagonal block.
// smem: Q(16K) + 3 stages x {K,V}(8K each) = 64KB -> 2 CTAs/SM.
// ---------------------------------------------------------------------------
#define FL_SMEM (64 * 1024)

__global__ void __launch_bounds__(256, 2) flash_tc_kernel()
{
    extern __shared__ char smraw[];
    const uint32_t S = smem_u32(smraw);
    const int tid = threadIdx.x, w = tid >> 5, lane = tid & 31;
    const int l16 = lane & 15, lh = lane >> 4;
    const int b = blockIdx.z, h = blockIdx.y;
    const int qt = (int)(gridDim.x - 1 - blockIdx.x);   // heaviest first
    const int n_kt = 2 * qt + 2;

    const uint32_t Q_s  = S;
    const uint32_t stg0 = S + 16384;

    const size_t head = (((size_t)b) * NHEAD + h) * TSEQ * HDIM;
    const size_t HSZ  = (size_t)BATCH * NHEAD * TSEQ * HDIM;
    const __half* qp = g_qkv + head;
    const __half* kp = g_qkv + HSZ + head;
    const __half* vp = g_qkv + 2 * HSZ + head;

    {
        #pragma unroll
        for (int i = 0; i < 4; i++) {
            int idx = tid + i * 256;
            int row = idx >> 3, c = idx & 7;
            cpa16(Q_s + SWZ128((uint32_t)(row * 128 + c * 16)),
                  qp + (size_t)(qt * 128 + row) * HDIM + c * 8);
        }
    }
    auto fillkv = [&](int s, int kt) {
        uint32_t sb = stg0 + (uint32_t)s * 16384u;
        const __half* bases[2] = {kp, vp};
        #pragma unroll
        for (int i = 0; i < 4; i++) {
            int idx = tid + i * 256;
            int mtx = idx >> 9, row = (idx >> 3) & 63, c = idx & 7;
            cpa16(sb + (uint32_t)mtx * 8192u + SWZ128((uint32_t)(row * 128 + c * 16)),
                  bases[mtx] + (size_t)(kt * 64 + row) * HDIM + c * 8);
        }
    };

    // prefill 3 stages
    fillkv(0, 0); CP_COMMIT();
    if (n_kt > 1) { fillkv(1, 1); CP_COMMIT(); }
    if (n_kt > 2) { fillkv(2, 2); CP_COMMIT(); }

    float m0 = -1e30f, m1 = -1e30f, l0 = 0.f, l1 = 0.f;
    float o[8][4];
    #pragma unroll
    for (int j = 0; j < 8; j++)
        #pragma unroll
        for (int e = 0; e < 4; e++) o[j][e] = 0.f;

    for (int kt = 0; kt < n_kt; kt++) {
        // stages in flight after prefill/fills: up to 3; wait until current ready
        if      (kt + 2 < n_kt) { CP_WAIT(2); }
        else if (kt + 1 < n_kt) { CP_WAIT(1); }
        else                    { CP_WAIT(0); }
        __syncthreads();

        // warps 0-3 contribute exactly zero on the final diagonal block
        const bool skip = (kt == n_kt - 1) && (w < 4);

        const int st = kt % 3;
        const uint32_t sb  = stg0 + (uint32_t)st * 16384u;
        const uint32_t K_s = sb, V_s = sb + 8192;

        if (!skip) {
            // ---- S = Q K^T ----
            float s[8][4];
            #pragma unroll
            for (int j = 0; j < 8; j++)
                #pragma unroll
                for (int e = 0; e < 4; e++) s[j][e] = 0.f;

            #pragma unroll
            for (int kk = 0; kk < 4; kk++) {
                const uint32_t koff = (uint32_t)(kk * 32 + lh * 16);
                uint32_t qf[4];
                ldsm4(Q_s + SWZ128((uint32_t)((w * 16 + l16) * 128) + koff), qf);
                #pragma unroll
                for (int gp = 0; gp < 2; gp++) {
                    const int g0 = 2 * gp, g1 = 2 * gp + 1;
                    uint32_t kf0[4], kf1[4];
                    ldsm4(K_s + SWZ128((uint32_t)((g0 * 16 + l16) * 128) + koff), kf0);
                    ldsm4(K_s + SWZ128((uint32_t)((g1 * 16 + l16) * 128) + koff), kf1);
                    mma16816(s[2 * g0],     qf, kf0[0], kf0[2]);
                    mma16816(s[2 * g0 + 1], qf, kf0[1], kf0[3]);
                    mma16816(s[2 * g1],     qf, kf1[0], kf1[2]);
                    mma16816(s[2 * g1 + 1], qf, kf1[1], kf1[3]);
                }
            }

            const int row0 = qt * 128 + w * 16 + (lane >> 2);
            if (kt * 64 + 63 > qt * 128 + w * 16) {
                #pragma unroll
                for (int j = 0; j < 8; j++) {
                    int colb = kt * 64 + j * 8 + (lane & 3) * 2;
                    if (colb + 0 > row0)     s[j][0] = -1e30f;
                    if (colb + 1 > row0)     s[j][1] = -1e30f;
                    if (colb + 0 > row0 + 8) s[j][2] = -1e30f;
                    if (colb + 1 > row0 + 8) s[j][3] = -1e30f;
                }
            }

            float mx0 = -1e30f, mx1 = -1e30f;
            #pragma unroll
            for (int j = 0; j < 8; j++) {
                mx0 = fmaxf(mx0, fmaxf(s[j][0], s[j][1]));
                mx1 = fmaxf(mx1, fmaxf(s[j][2], s[j][3]));
            }
            mx0 = fmaxf(mx0, __shfl_xor_sync(0xffffffffu, mx0, 1));
            mx0 = fmaxf(mx0, __shfl_xor_sync(0xffffffffu, mx0, 2));
            mx1 = fmaxf(mx1, __shfl_xor_sync(0xffffffffu, mx1, 1));
            mx1 = fmaxf(mx1, __shfl_xor_sync(0xffffffffu, mx1, 2));
            float nm0 = fmaxf(m0, mx0), nm1 = fmaxf(m1, mx1);
            float c0 = exp2f(m0 - nm0), c1 = exp2f(m1 - nm1);
            m0 = nm0; m1 = nm1;
            float sum0 = 0.f, sum1 = 0.f;
            #pragma unroll
            for (int j = 0; j < 8; j++) {
                s[j][0] = exp2f(s[j][0] - m0);
                s[j][1] = exp2f(s[j][1] - m0);
                s[j][2] = exp2f(s[j][2] - m1);
                s[j][3] = exp2f(s[j][3] - m1);
                sum0 += s[j][0] + s[j][1];
                sum1 += s[j][2] + s[j][3];
            }
            sum0 += __shfl_xor_sync(0xffffffffu, sum0, 1);
            sum0 += __shfl_xor_sync(0xffffffffu, sum0, 2);
            sum1 += __shfl_xor_sync(0xffffffffu, sum1, 1);
            sum1 += __shfl_xor_sync(0xffffffffu, sum1, 2);
            l0 = l0 * c0 + sum0;
            l1 = l1 * c1 + sum1;
            #pragma unroll
            for (int j = 0; j < 8; j++) {
                o[j][0] *= c0; o[j][1] *= c0; o[j][2] *= c1; o[j][3] *= c1;
            }

            // ---- O += P V ----
            #pragma unroll
            for (int kk = 0; kk < 4; kk++) {
                uint32_t pa[4];
                #pragma unroll
                for (int half = 0; half < 2; half++) {
                    const int f = 2 * kk + half;
                    pa[2 * half + 0] = packh2(__float2half(s[f][0]), __float2half(s[f][1]));
                    pa[2 * half + 1] = packh2(__float2half(s[f][2]), __float2half(s[f][3]));
                }
                #pragma unroll
                for (int gp = 0; gp < 2; gp++) {
                    const int g0 = 2 * gp, g1 = 2 * gp + 1;
                    uint32_t vf0[4], vf1[4];
                    uint32_t ro0 = SWZ128((uint32_t)((kk * 16 + l16) * 128 + g0 * 32) + (uint32_t)(lh * 16));
                    uint32_t ro1 = SWZ128((uint32_t)((kk * 16 + l16) * 128 + g1 * 32) + (uint32_t)(lh * 16));
                    ldsm4t(V_s + ro0, vf0);
                    ldsm4t(V_s + ro1, vf1);
                    mma16816(o[2 * g0],     pa, vf0[0], vf0[1]);
                    mma16816(o[2 * g0 + 1], pa, vf0[2], vf0[3]);
                    mma16816(o[2 * g1],     pa, vf1[0], vf1[1]);
                    mma16816(o[2 * g1 + 1], pa, vf1[2], vf1[3]);
                }
            }
        }

        __syncthreads();
        if (kt + 3 < n_kt) { fillkv(st, kt + 3); CP_COMMIT(); }
    }

    const float inv0 = 1.f / l0, inv1 = 1.f / l1;
    const int r0 = qt * 128 + w * 16 + (lane >> 2);
    const int t0 = r0, t1 = r0 + 8;
    #pragma unroll
    for (int j = 0; j < 8; j++) {
        int d = j * 8 + (lane & 3) * 2;
        size_t o0 = ((size_t)b * TSEQ + t0) * CDIM + h * HDIM + d;
        size_t o1 = ((size_t)b * TSEQ + t1) * CDIM + h * HDIM + d;
        *(uint32_t*)&g_y[o0] = packh2(__float2half(o[j][0] * inv0),
                                      __float2half(o[j][1] * inv0));
        *(uint32_t*)&g_y[o1] = packh2(__float2half(o[j][2] * inv1),
                                      __float2half(o[j][3] * inv1));
    }
}

// ---------------------------------------------------------------------------
extern "C" void kernel_launch(void* const* d_in, const int* in_sizes, int n_in,
                              void* d_out, int out_size)
{
    const float* x      = (const float*)d_in[0];
    const float* w_qkv  = (const float*)d_in[1];
    const float* w_proj = (const float*)d_in[2];
    float* out = (float*)d_out;

    __half *xh, *yh, *wq, *wp;
    cudaGetSymbolAddress((void**)&xh, g_x);
    cudaGetSymbolAddress((void**)&yh, g_y);
    cudaGetSymbolAddress((void**)&wq, g_wq);
    cudaGetSymbolAddress((void**)&wp, g_wp);

    cudaFuncSetAttribute(mmasync_kernel<0>, cudaFuncAttributeMaxDynamicSharedMemorySize, MM_SMEM);
    cudaFuncSetAttribute(mmasync_kernel<1>, cudaFuncAttributeMaxDynamicSharedMemorySize, MM_SMEM);
    cudaFuncSetAttribute(flash_tc_kernel,   cudaFuncAttributeMaxDynamicSharedMemorySize, FL_SMEM);
    cudaFuncSetAttribute(mmasync_kernel<0>, cudaFuncAttributePreferredSharedMemoryCarveout, 100);
    cudaFuncSetAttribute(mmasync_kernel<1>, cudaFuncAttributePreferredSharedMemoryCarveout, 100);
    cudaFuncSetAttribute(flash_tc_kernel,   cudaFuncAttributePreferredSharedMemoryCarveout, 100);

    // 1) fused prep: X->fp16 + weight transposes
    prep_kernel<<<NB_PREP, 256>>>(x, w_qkv, w_proj);

    // 2) QKV GEMM (N=3072) with head-major epilogue (Q pre-scaled)
    {
        dim3 grid(C3 / 128, MTOT / 128);
        mmasync_kernel<1><<<grid, 256, MM_SMEM>>>(xh, wq, nullptr, C3, CDIM);
    }

    // 3) flash attention -> g_y (fp16)
    {
        dim3 grid(TSEQ / 128, NHEAD, BATCH);
        flash_tc_kernel<<<grid, 256, FL_SMEM>>>();
    }

    // 4) proj GEMM -> fp32 out
    {
        dim3 grid(CDIM / 128, MTOT / 128);
        mmasync_kernel<0><<<grid, 256, MM_SMEM>>>(yh, wp, out, CDIM, CDIM);
    }
    (void)in_sizes; (void)n_in; (void)out_size;
}

// round 15
// speedup vs baseline: 2.0567x; 1.0964x over previous
#include <cuda_runtime.h>
#include <cuda_fp16.h>
#include <cstdint>

// Problem constants
#define BATCH 4
#define TSEQ  2048
#define CDIM  1024
#define NHEAD 16
#define HDIM  64
#define C3    (3*CDIM)
#define MTOT  (BATCH*TSEQ)   // 8192

#define QSCALE 0.18033688011112042f   // 0.125 * log2(e)

// ---------------------------------------------------------------------------
// Device-global scratch (no allocation allowed)
// ---------------------------------------------------------------------------
__device__ __align__(256) __half g_qkv[(size_t)3 * BATCH * NHEAD * TSEQ * HDIM];
__device__ __align__(256) __half g_y[(size_t)MTOT * CDIM];
__device__ __align__(256) __half g_x[(size_t)MTOT * CDIM];
__device__ __align__(256) __half g_wq[(size_t)C3 * CDIM];     // transposed N x K
__device__ __align__(256) __half g_wp[(size_t)CDIM * CDIM];   // transposed N x K

// ---------------------------------------------------------------------------
// Helpers (baseline PTX only)
// ---------------------------------------------------------------------------
__device__ __forceinline__ uint32_t smem_u32(const void* p) {
    uint32_t a;
    asm("{ .reg .u64 t; cvta.to.shared.u64 t, %1; cvt.u32.u64 %0, t; }" : "=r"(a) : "l"(p));
    return a;
}
__device__ __forceinline__ void cpa16(uint32_t dst, const void* src) {
    asm volatile("cp.async.cg.shared.global [%0], [%1], 16;\n" :: "r"(dst), "l"(src));
}
#define CP_COMMIT() asm volatile("cp.async.commit_group;\n" ::: "memory")
#define CP_WAIT(n)  asm volatile("cp.async.wait_group %0;\n" :: "n"(n) : "memory")
#define SWZ128(o) ((o) ^ (((o) >> 3) & 0x70))

__device__ __forceinline__ void ldsm4(uint32_t addr, uint32_t* r) {
    asm volatile("ldmatrix.sync.aligned.m8n8.x4.shared.b16 {%0,%1,%2,%3}, [%4];"
                 : "=r"(r[0]), "=r"(r[1]), "=r"(r[2]), "=r"(r[3]) : "r"(addr));
}
__device__ __forceinline__ void ldsm4t(uint32_t addr, uint32_t* r) {
    asm volatile("ldmatrix.sync.aligned.m8n8.x4.trans.shared.b16 {%0,%1,%2,%3}, [%4];"
                 : "=r"(r[0]), "=r"(r[1]), "=r"(r[2]), "=r"(r[3]) : "r"(addr));
}
__device__ __forceinline__ void mma16816(float* d, const uint32_t* a, uint32_t b0, uint32_t b1) {
    asm volatile("mma.sync.aligned.m16n8k16.row.col.f32.f16.f16.f32 "
                 "{%0,%1,%2,%3},{%4,%5,%6,%7},{%8,%9},{%0,%1,%2,%3};"
                 : "+f"(d[0]), "+f"(d[1]), "+f"(d[2]), "+f"(d[3])
                 : "r"(a[0]), "r"(a[1]), "r"(a[2]), "r"(a[3]), "r"(b0), "r"(b1));
}
__device__ __forceinline__ uint32_t packh2(__half a, __half b) {
    __half2 t; t.x = a; t.y = b;
    return *reinterpret_cast<uint32_t*>(&t);
}

// ---------------------------------------------------------------------------
// Fused prep: X fp32->fp16 convert + both weight transposes, one launch.
// ---------------------------------------------------------------------------
#define N4_X     (MTOT * CDIM / 4)
#define NB_CVT   (N4_X / 256)
#define NB_WQ    ((C3 / 32) * (CDIM / 32))
#define NB_WP    ((CDIM / 32) * (CDIM / 32))
#define NB_PREP  (NB_CVT + NB_WQ + NB_WP)

__global__ void __launch_bounds__(256) prep_kernel(
    const float* __restrict__ x, const float* __restrict__ w_qkv,
    const float* __restrict__ w_proj)
{
    const int bid = blockIdx.x, tid = threadIdx.x;
    if (bid < NB_CVT) {
        int i = bid * 256 + tid;
        float4 v = ((const float4*)x)[i];
        ((uint32_t*)g_x)[2*i]   = packh2(__float2half(v.x), __float2half(v.y));
        ((uint32_t*)g_x)[2*i+1] = packh2(__float2half(v.z), __float2half(v.w));
        return;
    }
    __shared__ float t[32][33];
    const int tx = tid & 31, ty = tid >> 5;
    const float* W; __half* Th; int K, N, idx;
    if (bid < NB_CVT + NB_WQ) {
        idx = bid - NB_CVT; W = w_qkv; Th = g_wq; K = CDIM; N = C3;
    } else {
        idx = bid - NB_CVT - NB_WQ; W = w_proj; Th = g_wp; K = CDIM; N = CDIM;
    }
    const int nblk = N / 32;
    const int n0 = (idx % nblk) * 32, k0 = (idx / nblk) * 32;
    #pragma unroll
    for (int i = 0; i < 32; i += 8)
        t[ty + i][tx] = W[(size_t)(k0 + ty + i) * N + n0 + tx];
    __syncthreads();
    #pragma unroll
    for (int i = 0; i < 32; i += 8)
        Th[(size_t)(n0 + ty + i) * K + k0 + tx] = __float2half(t[tx][ty + i]);
}

// ---------------------------------------------------------------------------
// mma.sync fp16 GEMM, CTA tile 128 x NT (NT=128 or 64), BK=64 (SW128).
// 8 warps: wm = wid&1 (64 rows), wn = wid>>1 (NT/4 cols).
// MODE 0: proj -> fp32 C.   MODE 1: QKV -> head-major fp16 (Q pre-scaled).
// ---------------------------------------------------------------------------
#define ATILE_B    (128 * 128)           // 16384 B

template<int MODE, int NT>
__global__ void __launch_bounds__(256, 2) mmasync_kernel(
    const __half* __restrict__ Ah, const __half* __restrict__ Bh,
    float* __restrict__ C, int N, int K)
{
    constexpr int BTILE_B  = NT * 128;          // bytes per B tile
    constexpr int STAGE_B  = ATILE_B + BTILE_B;
    constexpr int NTW      = NT / 32;           // nt values per warp (4 or 2)
    constexpr int NP       = NT / 64;           // B ldsm frags per warp (2 or 1)

    extern __shared__ char smraw[];
    const uint32_t smb = smem_u32(smraw);

    const int tid  = threadIdx.x;
    const int wid  = tid >> 5, lane = tid & 31;
    const int wm   = wid & 1;
    const int wn   = wid >> 1;
    const int bm   = blockIdx.y * 128, bn = blockIdx.x * NT;
    const int l16  = lane & 15, lh = lane >> 4;

    float acc[4][NTW][4];
    #pragma unroll
    for (int i = 0; i < 4; i++)
        #pragma unroll
        for (int j = 0; j < NTW; j++)
            #pragma unroll
            for (int k = 0; k < 4; k++) acc[i][j][k] = 0.f;

    auto fill = [&](int s, int k0) {
        uint32_t sb = smb + (uint32_t)s * STAGE_B;
        #pragma unroll
        for (int i = 0; i < 4; i++) {
            int chunk = tid + i * 256;
            int row = chunk >> 3, c = chunk & 7;
            cpa16(sb + SWZ128((uint32_t)(row * 128 + c * 16)),
                  Ah + (size_t)(bm + row) * K + k0 + c * 8);
        }
        #pragma unroll
        for (int i = 0; i < NT / 32; i++) {
            int chunk = tid + i * 256;
            int row = chunk >> 3, c = chunk & 7;
            cpa16(sb + ATILE_B + SWZ128((uint32_t)(row * 128 + c * 16)),
                  Bh + (size_t)(bn + row) * K + k0 + c * 8);
        }
    };

    const int nch = K >> 6;   // BK = 64
    fill(0, 0); CP_COMMIT();

    for (int i = 0; i < nch; i++) {
        if (i + 1 < nch) { fill((i + 1) & 1, (i + 1) << 6); CP_COMMIT(); CP_WAIT(1); }
        else             { CP_WAIT(0); }
        __syncthreads();

        uint32_t sb = smb + (uint32_t)(i & 1) * STAGE_B;
        uint32_t Ab = sb, Bb = sb + ATILE_B;

        #pragma unroll
        for (int kh = 0; kh < 4; kh++) {
            const uint32_t koff = (uint32_t)(kh * 32 + lh * 16);
            uint32_t ah[4][4];
            #pragma unroll
            for (int mt = 0; mt < 4; mt++) {
                uint32_t ro = SWZ128((uint32_t)((wm * 64 + mt * 16 + l16) * 128) + koff);
                ldsm4(Ab + ro, ah[mt]);
            }
            uint32_t bh[NP][4];
            #pragma unroll
            for (int np = 0; np < NP; np++) {
                uint32_t ro = SWZ128((uint32_t)((wn * (NT/4) + np * 16 + l16) * 128) + koff);
                ldsm4(Bb + ro, bh[np]);
            }
            #pragma unroll
            for (int mt = 0; mt < 4; mt++)
                #pragma unroll
                for (int nt = 0; nt < NTW; nt++) {
                    const int np = nt >> 1, o = nt & 1;
                    mma16816(acc[mt][nt], ah[mt], bh[np][o], bh[np][o + 2]);
                }
        }
        __syncthreads();
    }

    const int er = lane >> 2, ec = (lane & 3) * 2;
    #pragma unroll
    for (int mt = 0; mt < 4; mt++)
        #pragma unroll
        for (int nt = 0; nt < NTW; nt++) {
            int r0 = bm + wm * 64 + mt * 16 + er;
            int c0 = bn + wn * (NT/4) + nt * 8 + ec;
            float* v = acc[mt][nt];
            if (MODE == 0) {
                *(float2*)&C[(size_t)r0 * N + c0]       = make_float2(v[0], v[1]);
                *(float2*)&C[(size_t)(r0 + 8) * N + c0] = make_float2(v[2], v[3]);
            } else {
                int bb = r0 >> 11, t = r0 & 2047;
                int part = c0 >> 10, rem = c0 & 1023;
                int hh = rem >> 6, d = rem & 63;
                float sc = (part == 0) ? QSCALE : 1.f;
                size_t o = ((((size_t)part * BATCH + bb) * NHEAD + hh) * TSEQ + t) * HDIM + d;
                #pragma unroll
                for (int rr = 0; rr < 2; rr++) {
                    size_t oo = o + (size_t)rr * 8 * HDIM;
                    *(uint32_t*)&g_qkv[oo] = packh2(__float2half(v[2 * rr] * sc),
                                                    __float2half(v[2 * rr + 1] * sc));
                }
            }
        }
}

#define MM_SMEM_128 (2 * (ATILE_B + 128 * 128))   // 65536
#define MM_SMEM_64  (2 * (ATILE_B + 64 * 128))    // 49152

// ---------------------------------------------------------------------------
// Tensor-core flash attention (causal), fp16 1-term, Bq=128, Bk=64, D=64.
// 1D grid with GLOBAL LPT ordering: qt = 15 - (bid>>6), bh = bid & 63.
// 3-stage K/V pipeline; warps 0-3 skip the fully-masked final diagonal block.
// ---------------------------------------------------------------------------
#define FL_SMEM (64 * 1024)
#define NQT     (TSEQ / 128)   // 16

__global__ void __launch_bounds__(256, 2) flash_tc_kernel()
{
    extern __shared__ char smraw[];
    const uint32_t S = smem_u32(smraw);
    const int tid = threadIdx.x, w = tid >> 5, lane = tid & 31;
    const int l16 = lane & 15, lh = lane >> 4;
    const int bid = (int)blockIdx.x;
    const int qt = NQT - 1 - (bid >> 6);     // global heaviest-first (LPT)
    const int bh = bid & 63;
    const int b = bh >> 4, h = bh & 15;
    const int n_kt = 2 * qt + 2;

    const uint32_t Q_s  = S;
    const uint32_t stg0 = S + 16384;

    const size_t head = (((size_t)b) * NHEAD + h) * TSEQ * HDIM;
    const size_t HSZ  = (size_t)BATCH * NHEAD * TSEQ * HDIM;
    const __half* qp = g_qkv + head;
    const __half* kp = g_qkv + HSZ + head;
    const __half* vp = g_qkv + 2 * HSZ + head;

    {
        #pragma unroll
        for (int i = 0; i < 4; i++) {
            int idx = tid + i * 256;
            int row = idx >> 3, c = idx & 7;
            cpa16(Q_s + SWZ128((uint32_t)(row * 128 + c * 16)),
                  qp + (size_t)(qt * 128 + row) * HDIM + c * 8);
        }
    }
    auto fillkv = [&](int s, int kt) {
        uint32_t sb = stg0 + (uint32_t)s * 16384u;
        const __half* bases[2] = {kp, vp};
        #pragma unroll
        for (int i = 0; i < 4; i++) {
            int idx = tid + i * 256;
            int mtx = idx >> 9, row = (idx >> 3) & 63, c = idx & 7;
            cpa16(sb + (uint32_t)mtx * 8192u + SWZ128((uint32_t)(row * 128 + c * 16)),
                  bases[mtx] + (size_t)(kt * 64 + row) * HDIM + c * 8);
        }
    };

    fillkv(0, 0); CP_COMMIT();
    if (n_kt > 1) { fillkv(1, 1); CP_COMMIT(); }
    if (n_kt > 2) { fillkv(2, 2); CP_COMMIT(); }

    float m0 = -1e30f, m1 = -1e30f, l0 = 0.f, l1 = 0.f;
    float o[8][4];
    #pragma unroll
    for (int j = 0; j < 8; j++)
        #pragma unroll
        for (int e = 0; e < 4; e++) o[j][e] = 0.f;

    for (int kt = 0; kt < n_kt; kt++) {
        if      (kt + 2 < n_kt) { CP_WAIT(2); }
        else if (kt + 1 < n_kt) { CP_WAIT(1); }
        else                    { CP_WAIT(0); }
        __syncthreads();

        const bool skip = (kt == n_kt - 1) && (w < 4);
        const int st = kt % 3;
        const uint32_t sb  = stg0 + (uint32_t)st * 16384u;
        const uint32_t K_s = sb, V_s = sb + 8192;

        if (!skip) {
            float s[8][4];
            #pragma unroll
            for (int j = 0; j < 8; j++)
                #pragma unroll
                for (int e = 0; e < 4; e++) s[j][e] = 0.f;

            #pragma unroll
            for (int kk = 0; kk < 4; kk++) {
                const uint32_t koff = (uint32_t)(kk * 32 + lh * 16);
                uint32_t qf[4];
                ldsm4(Q_s + SWZ128((uint32_t)((w * 16 + l16) * 128) + koff), qf);
                #pragma unroll
                for (int gp = 0; gp < 2; gp++) {
                    const int g0 = 2 * gp, g1 = 2 * gp + 1;
                    uint32_t kf0[4], kf1[4];
                    ldsm4(K_s + SWZ128((uint32_t)((g0 * 16 + l16) * 128) + koff), kf0);
                    ldsm4(K_s + SWZ128((uint32_t)((g1 * 16 + l16) * 128) + koff), kf1);
                    mma16816(s[2 * g0],     qf, kf0[0], kf0[2]);
                    mma16816(s[2 * g0 + 1], qf, kf0[1], kf0[3]);
                    mma16816(s[2 * g1],     qf, kf1[0], kf1[2]);
                    mma16816(s[2 * g1 + 1], qf, kf1[1], kf1[3]);
                }
            }

            const int row0 = qt * 128 + w * 16 + (lane >> 2);
            if (kt * 64 + 63 > qt * 128 + w * 16) {
                #pragma unroll
                for (int j = 0; j < 8; j++) {
                    int colb = kt * 64 + j * 8 + (lane & 3) * 2;
                    if (colb + 0 > row0)     s[j][0] = -1e30f;
                    if (colb + 1 > row0)     s[j][1] = -1e30f;
                    if (colb + 0 > row0 + 8) s[j][2] = -1e30f;
                    if (colb + 1 > row0 + 8) s[j][3] = -1e30f;
                }
            }

            float mx0 = -1e30f, mx1 = -1e30f;
            #pragma unroll
            for (int j = 0; j < 8; j++) {
                mx0 = fmaxf(mx0, fmaxf(s[j][0], s[j][1]));
                mx1 = fmaxf(mx1, fmaxf(s[j][2], s[j][3]));
            }
            mx0 = fmaxf(mx0, __shfl_xor_sync(0xffffffffu, mx0, 1));
            mx0 = fmaxf(mx0, __shfl_xor_sync(0xffffffffu, mx0, 2));
            mx1 = fmaxf(mx1, __shfl_xor_sync(0xffffffffu, mx1, 1));
            mx1 = fmaxf(mx1, __shfl_xor_sync(0xffffffffu, mx1, 2));
            float nm0 = fmaxf(m0, mx0), nm1 = fmaxf(m1, mx1);
            float c0 = exp2f(m0 - nm0), c1 = exp2f(m1 - nm1);
            m0 = nm0; m1 = nm1;
            float sum0 = 0.f, sum1 = 0.f;
            #pragma unroll
            for (int j = 0; j < 8; j++) {
                s[j][0] = exp2f(s[j][0] - m0);
                s[j][1] = exp2f(s[j][1] - m0);
                s[j][2] = exp2f(s[j][2] - m1);
                s[j][3] = exp2f(s[j][3] - m1);
                sum0 += s[j][0] + s[j][1];
                sum1 += s[j][2] + s[j][3];
            }
            sum0 += __shfl_xor_sync(0xffffffffu, sum0, 1);
            sum0 += __shfl_xor_sync(0xffffffffu, sum0, 2);
            sum1 += __shfl_xor_sync(0xffffffffu, sum1, 1);
            sum1 += __shfl_xor_sync(0xffffffffu, sum1, 2);
            l0 = l0 * c0 + sum0;
            l1 = l1 * c1 + sum1;
            #pragma unroll
            for (int j = 0; j < 8; j++) {
                o[j][0] *= c0; o[j][1] *= c0; o[j][2] *= c1; o[j][3] *= c1;
            }

            #pragma unroll
            for (int kk = 0; kk < 4; kk++) {
                uint32_t pa[4];
                #pragma unroll
                for (int half = 0; half < 2; half++) {
                    const int f = 2 * kk + half;
                    pa[2 * half + 0] = packh2(__float2half(s[f][0]), __float2half(s[f][1]));
                    pa[2 * half + 1] = packh2(__float2half(s[f][2]), __float2half(s[f][3]));
                }
                #pragma unroll
                for (int gp = 0; gp < 2; gp++) {
                    const int g0 = 2 * gp, g1 = 2 * gp + 1;
                    uint32_t vf0[4], vf1[4];
                    uint32_t ro0 = SWZ128((uint32_t)((kk * 16 + l16) * 128 + g0 * 32) + (uint32_t)(lh * 16));
                    uint32_t ro1 = SWZ128((uint32_t)((kk * 16 + l16) * 128 + g1 * 32) + (uint32_t)(lh * 16));
                    ldsm4t(V_s + ro0, vf0);
                    ldsm4t(V_s + ro1, vf1);
                    mma16816(o[2 * g0],     pa, vf0[0], vf0[1]);
                    mma16816(o[2 * g0 + 1], pa, vf0[2], vf0[3]);
                    mma16816(o[2 * g1],     pa, vf1[0], vf1[1]);
                    mma16816(o[2 * g1 + 1], pa, vf1[2], vf1[3]);
                }
            }
        }

        __syncthreads();
        if (kt + 3 < n_kt) { fillkv(st, kt + 3); CP_COMMIT(); }
    }

    const float inv0 = 1.f / l0, inv1 = 1.f / l1;
    const int r0 = qt * 128 + w * 16 + (lane >> 2);
    const int t0 = r0, t1 = r0 + 8;
    #pragma unroll
    for (int j = 0; j < 8; j++) {
        int d = j * 8 + (lane & 3) * 2;
        size_t o0 = ((size_t)b * TSEQ + t0) * CDIM + h * HDIM + d;
        size_t o1 = ((size_t)b * TSEQ + t1) * CDIM + h * HDIM + d;
        *(uint32_t*)&g_y[o0] = packh2(__float2half(o[j][0] * inv0),
                                      __float2half(o[j][1] * inv0));
        *(uint32_t*)&g_y[o1] = packh2(__float2half(o[j][2] * inv1),
                                      __float2half(o[j][3] * inv1));
    }
}

// ---------------------------------------------------------------------------
extern "C" void kernel_launch(void* const* d_in, const int* in_sizes, int n_in,
                              void* d_out, int out_size)
{
    const float* x      = (const float*)d_in[0];
    const float* w_qkv  = (const float*)d_in[1];
    const float* w_proj = (const float*)d_in[2];
    float* out = (float*)d_out;

    __half *xh, *yh, *wq, *wp;
    cudaGetSymbolAddress((void**)&xh, g_x);
    cudaGetSymbolAddress((void**)&yh, g_y);
    cudaGetSymbolAddress((void**)&wq, g_wq);
    cudaGetSymbolAddress((void**)&wp, g_wp);

    cudaFuncSetAttribute((const void*)mmasync_kernel<1,128>, cudaFuncAttributeMaxDynamicSharedMemorySize, MM_SMEM_128);
    cudaFuncSetAttribute((const void*)mmasync_kernel<0,64>,  cudaFuncAttributeMaxDynamicSharedMemorySize, MM_SMEM_64);
    cudaFuncSetAttribute((const void*)flash_tc_kernel,       cudaFuncAttributeMaxDynamicSharedMemorySize, FL_SMEM);
    cudaFuncSetAttribute((const void*)mmasync_kernel<1,128>, cudaFuncAttributePreferredSharedMemoryCarveout, 100);
    cudaFuncSetAttribute((const void*)mmasync_kernel<0,64>,  cudaFuncAttributePreferredSharedMemoryCarveout, 100);
    cudaFuncSetAttribute((const void*)flash_tc_kernel,       cudaFuncAttributePreferredSharedMemoryCarveout, 100);

    // 1) fused prep
    prep_kernel<<<NB_PREP, 256>>>(x, w_qkv, w_proj);

    // 2) QKV GEMM (N=3072, 128-wide tiles)
    {
        dim3 grid(C3 / 128, MTOT / 128);
        mmasync_kernel<1,128><<<grid, 256, MM_SMEM_128>>>(xh, wq, nullptr, C3, CDIM);
    }

    // 3) flash attention, 1D LPT grid
    flash_tc_kernel<<<NQT * NHEAD * BATCH, 256, FL_SMEM>>>();

    // 4) proj GEMM (64-wide tiles -> finer tail)
    {
        dim3 grid(CDIM / 64, MTOT / 128);
        mmasync_kernel<0,64><<<grid, 256, MM_SMEM_64>>>(yh, wp, out, CDIM, CDIM);
    }
    (void)in_sizes; (void)n_in; (void)out_size;
}